// round 2
// baseline (speedup 1.0000x reference)
#include <cuda_runtime.h>
#include <cuda_bf16.h>
#include <stdint.h>

// Problem constants (fixed by the reference)
#define NN   50000
#define EE   800000
#define FIN  512
#define HH   256
#define OUTF 2
#define BN_EPS 1e-5f

// -------- scratch (device globals; no runtime allocation allowed) --------
__device__ int   g_is64;
__device__ int   g_row[EE];
__device__ int   g_col[EE];
__device__ float g_deg[NN];
__device__ float g_dinv[NN];
__device__ float g_snorm[NN];
__device__ float g_norm[EE];
__device__ float g_bufA[(size_t)NN * HH];   // 51.2 MB
__device__ float g_bufB[(size_t)NN * HH];   // 51.2 MB
__device__ float g_h3[(size_t)NN * OUTF];

// ---------------- edge-index dtype detection + extraction ----------------
// If the buffer holds int64 little-endian values < 2^31, every odd 32-bit word
// is 0. If it holds int32 indices, odd words are random node ids (~0 chance all
// of the first 2048 are zero).
__global__ void k_detect(const unsigned int* __restrict__ w) {
    if (blockIdx.x == 0 && threadIdx.x == 0) {
        int is64 = 1;
        for (int i = 0; i < 2048; i++) {
            if (w[2 * i + 1] != 0u) { is64 = 0; break; }
        }
        g_is64 = is64;
    }
}

__global__ void k_extract(const unsigned int* __restrict__ w,
                          int* __restrict__ row, int* __restrict__ col, int E) {
    int e = blockIdx.x * blockDim.x + threadIdx.x;
    if (e >= E) return;
    if (g_is64) {
        row[e] = (int)w[2 * e];
        col[e] = (int)w[2 * (E + e)];
    } else {
        row[e] = (int)w[e];
        col[e] = (int)w[E + e];
    }
}

// ---------------- degree / norm precompute ----------------
__global__ void k_set_deg(float* deg, int n) {
    int i = blockIdx.x * blockDim.x + threadIdx.x;
    if (i < n) deg[i] = 1.0f;   // self-loop weight
}

__global__ void k_deg_acc(const int* __restrict__ col,
                          const float* __restrict__ w,
                          float* __restrict__ deg, int E) {
    int e = blockIdx.x * blockDim.x + threadIdx.x;
    if (e < E) atomicAdd(&deg[col[e]], w[e]);
}

__global__ void k_dinv(const float* __restrict__ deg,
                       float* __restrict__ dinv,
                       float* __restrict__ snorm, int n) {
    int i = blockIdx.x * blockDim.x + threadIdx.x;
    if (i < n) {
        float d = rsqrtf(deg[i]);
        dinv[i] = d;
        snorm[i] = d * d;
    }
}

__global__ void k_norm(const int* __restrict__ row,
                       const int* __restrict__ col,
                       const float* __restrict__ w,
                       const float* __restrict__ dinv,
                       float* __restrict__ norm, int E) {
    int e = blockIdx.x * blockDim.x + threadIdx.x;
    if (e < E) norm[e] = dinv[row[e]] * w[e] * dinv[col[e]];
}

// ---------------- SGEMM: C[Nr,M] = A[Nr,K] * B[K,M], M multiple of 128 ----------------
// 128x128 tile, BK=8, 256 threads, 8x8 micro-tile.
template <int K>
__global__ __launch_bounds__(256, 2)
void sgemm128(const float* __restrict__ A, const float* __restrict__ B,
              float* __restrict__ C, int Nr, int M) {
    __shared__ float As[8][128];
    __shared__ float Bs[8][128];

    int tid = threadIdx.x;
    int bm = blockIdx.x * 128;
    int bn = blockIdx.y * 128;
    int tx = tid & 15;       // 0..15
    int ty = tid >> 4;       // 0..15

    float acc[8][8];
#pragma unroll
    for (int i = 0; i < 8; i++)
#pragma unroll
        for (int j = 0; j < 8; j++) acc[i][j] = 0.0f;

    int a_row = tid >> 1;            // 0..127
    int a_col = (tid & 1) * 4;       // 0 or 4
    int b_row = tid >> 5;            // 0..7
    int b_col = (tid & 31) * 4;      // 0..124

    for (int kt = 0; kt < K; kt += 8) {
        // load A tile (transposed into As[k][m]); zero-fill OOB rows
        float4 av = make_float4(0.f, 0.f, 0.f, 0.f);
        int gr = bm + a_row;
        if (gr < Nr)
            av = *reinterpret_cast<const float4*>(A + (size_t)gr * K + kt + a_col);
        As[a_col + 0][a_row] = av.x;
        As[a_col + 1][a_row] = av.y;
        As[a_col + 2][a_row] = av.z;
        As[a_col + 3][a_row] = av.w;

        // load B tile
        *reinterpret_cast<float4*>(&Bs[b_row][b_col]) =
            *reinterpret_cast<const float4*>(B + (size_t)(kt + b_row) * M + bn + b_col);

        __syncthreads();

#pragma unroll
        for (int k = 0; k < 8; k++) {
            float ar[8], br[8];
#pragma unroll
            for (int i = 0; i < 4; i++) {
                ar[i]     = As[k][ty * 4 + i];
                ar[4 + i] = As[k][64 + ty * 4 + i];
            }
#pragma unroll
            for (int j = 0; j < 4; j++) {
                br[j]     = Bs[k][tx * 4 + j];
                br[4 + j] = Bs[k][64 + tx * 4 + j];
            }
#pragma unroll
            for (int i = 0; i < 8; i++)
#pragma unroll
                for (int j = 0; j < 8; j++)
                    acc[i][j] += ar[i] * br[j];
        }
        __syncthreads();
    }

#pragma unroll
    for (int i = 0; i < 8; i++) {
        int r = bm + ((i < 4) ? (ty * 4 + i) : (64 + ty * 4 + (i - 4)));
        if (r >= Nr) continue;
#pragma unroll
        for (int j = 0; j < 8; j++) {
            int c = bn + ((j < 4) ? (tx * 4 + j) : (64 + tx * 4 + (j - 4)));
            C[(size_t)r * M + c] = acc[i][j];
        }
    }
}

// ---------------- aggregation ----------------
// self-loop contribution also serves as the initializer of agg
__global__ void k_init_agg(const float* __restrict__ h,
                           const float* __restrict__ snorm,
                           float* __restrict__ agg, int n) {
    int idx = blockIdx.x * blockDim.x + threadIdx.x;   // over n*64 float4s
    if (idx >= n * (HH / 4)) return;
    int i = idx / (HH / 4);
    float4 v = reinterpret_cast<const float4*>(h)[idx];
    float s = snorm[i];
    v.x *= s; v.y *= s; v.z *= s; v.w *= s;
    reinterpret_cast<float4*>(agg)[idx] = v;
}

// one edge per 64 threads (H=256 = 64 float4)
__global__ void k_scatter_h(const float* __restrict__ h,
                            const float* __restrict__ norm,
                            const int* __restrict__ row,
                            const int* __restrict__ col,
                            float* __restrict__ agg, int E) {
    int e = blockIdx.x * (blockDim.x >> 6) + (threadIdx.x >> 6);
    int lane = threadIdx.x & 63;
    if (e >= E) return;
    int r = row[e];
    int c = col[e];
    float nv = norm[e];
    float4 v = *reinterpret_cast<const float4*>(h + (size_t)r * HH + lane * 4);
    float* dst = agg + (size_t)c * HH + lane * 4;
    atomicAdd(dst + 0, v.x * nv);
    atomicAdd(dst + 1, v.y * nv);
    atomicAdd(dst + 2, v.z * nv);
    atomicAdd(dst + 3, v.w * nv);
}

// out = relu(((agg + b) - m) * rsqrt(v+eps) * g + be)
__global__ void k_bn_relu(const float* __restrict__ agg, float* __restrict__ out,
                          const float* __restrict__ b, const float* __restrict__ g,
                          const float* __restrict__ be, const float* __restrict__ m,
                          const float* __restrict__ v, int n) {
    int idx = blockIdx.x * blockDim.x + threadIdx.x;   // n*64 float4s
    if (idx >= n * (HH / 4)) return;
    int j4 = (idx & (HH / 4 - 1)) * 4;
    float4 a  = reinterpret_cast<const float4*>(agg)[idx];
    float4 bb = *reinterpret_cast<const float4*>(b + j4);
    float4 gg = *reinterpret_cast<const float4*>(g + j4);
    float4 ee = *reinterpret_cast<const float4*>(be + j4);
    float4 mm = *reinterpret_cast<const float4*>(m + j4);
    float4 vv = *reinterpret_cast<const float4*>(v + j4);
    float4 o;
    o.x = fmaxf((a.x + bb.x - mm.x) * rsqrtf(vv.x + BN_EPS) * gg.x + ee.x, 0.0f);
    o.y = fmaxf((a.y + bb.y - mm.y) * rsqrtf(vv.y + BN_EPS) * gg.y + ee.y, 0.0f);
    o.z = fmaxf((a.z + bb.z - mm.z) * rsqrtf(vv.z + BN_EPS) * gg.z + ee.z, 0.0f);
    o.w = fmaxf((a.w + bb.w - mm.w) * rsqrtf(vv.w + BN_EPS) * gg.w + ee.w, 0.0f);
    reinterpret_cast<float4*>(out)[idx] = o;
}

// ---------------- layer 3 (OUT=2) ----------------
__global__ void k_gemm_out(const float* __restrict__ Hin,
                           const float* __restrict__ W3,
                           float* __restrict__ h3, int n) {
    int i = blockIdx.x * blockDim.x + threadIdx.x;
    if (i >= n) return;
    const float4* hr = reinterpret_cast<const float4*>(Hin + (size_t)i * HH);
    float s0 = 0.f, s1 = 0.f;
#pragma unroll 16
    for (int k4 = 0; k4 < HH / 4; k4++) {
        float4 hv = hr[k4];
        int k = k4 * 4;
        s0 += hv.x * W3[(k + 0) * 2]     + hv.y * W3[(k + 1) * 2]
            + hv.z * W3[(k + 2) * 2]     + hv.w * W3[(k + 3) * 2];
        s1 += hv.x * W3[(k + 0) * 2 + 1] + hv.y * W3[(k + 1) * 2 + 1]
            + hv.z * W3[(k + 2) * 2 + 1] + hv.w * W3[(k + 3) * 2 + 1];
    }
    h3[i * 2]     = s0;
    h3[i * 2 + 1] = s1;
}

__global__ void k_out_init(const float* __restrict__ h3,
                           const float* __restrict__ snorm,
                           const float* __restrict__ b3,
                           float* __restrict__ out, int n) {
    int i = blockIdx.x * blockDim.x + threadIdx.x;
    if (i >= n) return;
    float s = snorm[i];
    out[i * 2]     = s * h3[i * 2]     + b3[0];
    out[i * 2 + 1] = s * h3[i * 2 + 1] + b3[1];
}

__global__ void k_scatter_out(const float* __restrict__ h3,
                              const float* __restrict__ norm,
                              const int* __restrict__ row,
                              const int* __restrict__ col,
                              float* __restrict__ out, int E) {
    int e = blockIdx.x * blockDim.x + threadIdx.x;
    if (e >= E) return;
    int r = row[e];
    int c = col[e];
    float nv = norm[e];
    atomicAdd(&out[c * 2],     nv * h3[r * 2]);
    atomicAdd(&out[c * 2 + 1], nv * h3[r * 2 + 1]);
}

// ---------------- launch ----------------
extern "C" void kernel_launch(void* const* d_in, const int* in_sizes, int n_in,
                              void* d_out, int out_size) {
    const float*        x   = (const float*)d_in[0];
    const unsigned int* eiw = (const unsigned int*)d_in[1];
    const float*        w   = (const float*)d_in[2];
    const float*        W1  = (const float*)d_in[3];
    const float*        b1  = (const float*)d_in[4];
    const float*        g1  = (const float*)d_in[5];
    const float*        be1 = (const float*)d_in[6];
    const float*        m1  = (const float*)d_in[7];
    const float*        v1  = (const float*)d_in[8];
    const float*        W2  = (const float*)d_in[9];
    const float*        b2  = (const float*)d_in[10];
    const float*        g2  = (const float*)d_in[11];
    const float*        be2 = (const float*)d_in[12];
    const float*        m2  = (const float*)d_in[13];
    const float*        v2  = (const float*)d_in[14];
    const float*        W3  = (const float*)d_in[15];
    const float*        b3  = (const float*)d_in[16];
    float* out = (float*)d_out;

    int *row, *col;
    float *deg, *dinv, *snorm, *norm, *bufA, *bufB, *h3;
    cudaGetSymbolAddress((void**)&row,   g_row);
    cudaGetSymbolAddress((void**)&col,   g_col);
    cudaGetSymbolAddress((void**)&deg,   g_deg);
    cudaGetSymbolAddress((void**)&dinv,  g_dinv);
    cudaGetSymbolAddress((void**)&snorm, g_snorm);
    cudaGetSymbolAddress((void**)&norm,  g_norm);
    cudaGetSymbolAddress((void**)&bufA,  g_bufA);
    cudaGetSymbolAddress((void**)&bufB,  g_bufB);
    cudaGetSymbolAddress((void**)&h3,    g_h3);

    const int n = NN, E = EE;
    dim3 t256(256);
    int nb_n   = (n + 255) / 256;
    int nb_e   = (E + 255) / 256;
    int nb_nh  = (n * (HH / 4) + 255) / 256;
    int nb_es  = (E + 3) / 4;                 // 4 edges per 256-thread block

    // edge index dtype handling
    k_detect<<<1, 32>>>(eiw);
    k_extract<<<nb_e, t256>>>(eiw, row, col, E);

    // degree / norms (layer-invariant)
    k_set_deg<<<nb_n, t256>>>(deg, n);
    k_deg_acc<<<nb_e, t256>>>(col, w, deg, E);
    k_dinv<<<nb_n, t256>>>(deg, dinv, snorm, n);
    k_norm<<<nb_e, t256>>>(row, col, w, dinv, norm, E);

    dim3 gemm_grid1((n + 127) / 128, HH / 128);

    // ---- layer 1 ----
    sgemm128<FIN><<<gemm_grid1, t256>>>(x, W1, bufA, n, HH);
    k_init_agg<<<nb_nh, t256>>>(bufA, snorm, bufB, n);
    k_scatter_h<<<nb_es, t256>>>(bufA, norm, row, col, bufB, E);
    k_bn_relu<<<nb_nh, t256>>>(bufB, bufA, b1, g1, be1, m1, v1, n);

    // ---- layer 2 ----
    sgemm128<HH><<<gemm_grid1, t256>>>(bufA, W2, bufB, n, HH);
    k_init_agg<<<nb_nh, t256>>>(bufB, snorm, bufA, n);
    k_scatter_h<<<nb_es, t256>>>(bufB, norm, row, col, bufA, E);
    k_bn_relu<<<nb_nh, t256>>>(bufA, bufB, b2, g2, be2, m2, v2, n);

    // ---- layer 3 ----
    k_gemm_out<<<nb_n, t256>>>(bufB, W3, h3, n);
    k_out_init<<<nb_n, t256>>>(h3, snorm, b3, out, n);
    k_scatter_out<<<nb_e, t256>>>(h3, norm, row, col, out, E);
}

// round 4
// speedup vs baseline: 1.1487x; 1.1487x over previous
#include <cuda_runtime.h>
#include <cuda_bf16.h>
#include <stdint.h>

#define NN   50000
#define EE   800000
#define FIN  512
#define HH   256
#define OUTF 2
#define BN_EPS 1e-5f

// -------------------- scratch --------------------
__device__ int   g_is64;
__device__ int   g_row[EE];
__device__ int   g_col[EE];
__device__ float g_deg[NN];
__device__ float g_dinv[NN];
__device__ float g_snorm[NN];
__device__ float g_norm[EE];
__device__ float g_bufA[(size_t)NN * HH];
__device__ float g_bufB[(size_t)NN * HH];
__device__ float g_h3[(size_t)NN * OUTF];
__device__ __nv_bfloat16 g_hi[(size_t)NN * FIN];
__device__ __nv_bfloat16 g_lo[(size_t)NN * FIN];
__device__ __nv_bfloat16 g_Whi[(size_t)HH * FIN];
__device__ __nv_bfloat16 g_Wlo[(size_t)HH * FIN];

// -------------------- edge-index dtype --------------------
__global__ void k_detect(const unsigned int* __restrict__ w) {
    if (blockIdx.x == 0 && threadIdx.x == 0) {
        int is64 = 1;
        for (int i = 0; i < 2048; i++)
            if (w[2 * i + 1] != 0u) { is64 = 0; break; }
        g_is64 = is64;
    }
}
__global__ void k_extract(const unsigned int* __restrict__ w,
                          int* __restrict__ row, int* __restrict__ col, int E) {
    int e = blockIdx.x * blockDim.x + threadIdx.x;
    if (e >= E) return;
    if (g_is64) { row[e] = (int)w[2 * e]; col[e] = (int)w[2 * (E + e)]; }
    else        { row[e] = (int)w[e];     col[e] = (int)w[E + e]; }
}

// -------------------- degree / norm --------------------
__global__ void k_set_deg(float* deg, int n) {
    int i = blockIdx.x * blockDim.x + threadIdx.x;
    if (i < n) deg[i] = 1.0f;
}
__global__ void k_deg_acc(const int* __restrict__ col, const float* __restrict__ w,
                          float* __restrict__ deg, int E) {
    int e = blockIdx.x * blockDim.x + threadIdx.x;
    if (e < E) atomicAdd(&deg[col[e]], w[e]);
}
__global__ void k_dinv(const float* __restrict__ deg, float* __restrict__ dinv,
                       float* __restrict__ snorm, int n) {
    int i = blockIdx.x * blockDim.x + threadIdx.x;
    if (i < n) { float d = rsqrtf(deg[i]); dinv[i] = d; snorm[i] = d * d; }
}
__global__ void k_norm(const int* __restrict__ row, const int* __restrict__ col,
                       const float* __restrict__ w, const float* __restrict__ dinv,
                       float* __restrict__ norm, int E) {
    int e = blockIdx.x * blockDim.x + threadIdx.x;
    if (e < E) norm[e] = dinv[row[e]] * w[e] * dinv[col[e]];
}

// -------------------- fp32 -> bf16 hi/lo split --------------------
__device__ __forceinline__ void split4(float4 v, __nv_bfloat162* H, __nv_bfloat162* L, size_t i2) {
    __nv_bfloat16 h0 = __float2bfloat16_rn(v.x);
    __nv_bfloat16 h1 = __float2bfloat16_rn(v.y);
    __nv_bfloat16 h2 = __float2bfloat16_rn(v.z);
    __nv_bfloat16 h3 = __float2bfloat16_rn(v.w);
    __nv_bfloat16 l0 = __float2bfloat16_rn(v.x - __bfloat162float(h0));
    __nv_bfloat16 l1 = __float2bfloat16_rn(v.y - __bfloat162float(h1));
    __nv_bfloat16 l2 = __float2bfloat16_rn(v.z - __bfloat162float(h2));
    __nv_bfloat16 l3 = __float2bfloat16_rn(v.w - __bfloat162float(h3));
    H[i2]     = __nv_bfloat162(h0, h1);
    H[i2 + 1] = __nv_bfloat162(h2, h3);
    L[i2]     = __nv_bfloat162(l0, l1);
    L[i2 + 1] = __nv_bfloat162(l2, l3);
}

__global__ void k_split_x(const float* __restrict__ x,
                          __nv_bfloat16* __restrict__ hi, __nv_bfloat16* __restrict__ lo,
                          size_t n4) {
    size_t i = (size_t)blockIdx.x * blockDim.x + threadIdx.x;
    if (i >= n4) return;
    split4(reinterpret_cast<const float4*>(x)[i],
           reinterpret_cast<__nv_bfloat162*>(hi),
           reinterpret_cast<__nv_bfloat162*>(lo), 2 * i);
}

// W [K,256] fp32 -> B [256,K] bf16 hi/lo (transposed; n-major, k contiguous)
__global__ void k_splitW(const float* __restrict__ W,
                         __nv_bfloat16* __restrict__ bhi, __nv_bfloat16* __restrict__ blo,
                         int K) {
    int idx = blockIdx.x * blockDim.x + threadIdx.x;
    if (idx >= 256 * K) return;
    int n = idx / K, k = idx - n * K;
    float v = W[(size_t)k * 256 + n];
    __nv_bfloat16 h = __float2bfloat16_rn(v);
    bhi[idx] = h;
    blo[idx] = __float2bfloat16_rn(v - __bfloat162float(h));
}

// -------------------- mma.sync helpers --------------------
__device__ __forceinline__ void mma16816(float* d, const uint32_t* a, const uint32_t* b) {
    asm volatile(
        "mma.sync.aligned.m16n8k16.row.col.f32.bf16.bf16.f32 "
        "{%0,%1,%2,%3}, {%4,%5,%6,%7}, {%8,%9}, {%0,%1,%2,%3};"
        : "+f"(d[0]), "+f"(d[1]), "+f"(d[2]), "+f"(d[3])
        : "r"(a[0]), "r"(a[1]), "r"(a[2]), "r"(a[3]), "r"(b[0]), "r"(b[1]));
}
__device__ __forceinline__ void cp_async16(uint32_t saddr, const void* gaddr, int src_sz) {
    asm volatile("cp.async.cg.shared.global [%0], [%1], 16, %2;"
                 :: "r"(saddr), "l"(gaddr), "r"(src_sz));
}
__device__ __forceinline__ void cp_commit() { asm volatile("cp.async.commit_group;"); }
__device__ __forceinline__ void cp_wait1()  { asm volatile("cp.async.wait_group 1;"); }
__device__ __forceinline__ void cp_wait0()  { asm volatile("cp.async.wait_group 0;"); }

// -------------------- split-bf16 HMMA GEMM --------------------
// C[Nr,256] = A[Nr,K] * B[256,K]^T  (3 split terms), Agg = snorm * C fused.
// Tiles: BM=128, BN=128, BK=32. 256 thr = 8 warps (4 x 2), warp tile 32x64.
// Smem word layout (stride 20 words = 40 halves per row): conflict-free for
// both the uint4 stores and the fragment LDS pattern.
template <int K>
__global__ __launch_bounds__(256, 2)
void mma_gemm(const __nv_bfloat16* __restrict__ Ahi, const __nv_bfloat16* __restrict__ Alo,
              const __nv_bfloat16* __restrict__ Bhi, const __nv_bfloat16* __restrict__ Blo,
              const float* __restrict__ snorm,
              float* __restrict__ C, float* __restrict__ Agg, int Nr) {
    constexpr int NCH = K / 32;
    constexpr int NQ  = 3 * NCH;
    __shared__ uint32_t As[2][2560];   // 128 rows x 20 words
    __shared__ uint32_t Bs[2][2560];

    const int tid  = threadIdx.x;
    const int lane = tid & 31;
    const int wid  = tid >> 5;
    const int warp_m = wid & 3;        // 4 warps along M (32 rows each)
    const int warp_n = wid >> 2;       // 2 warps along N (64 cols each)
    const int bm = blockIdx.x * 128;
    const int bn = blockIdx.y * 128;

    const __nv_bfloat16* APtr[3] = {Ahi, Ahi, Alo};
    const __nv_bfloat16* BPtr[3] = {Bhi, Blo, Bhi};

    float acc[2][8][4];
#pragma unroll
    for (int mt = 0; mt < 2; mt++)
#pragma unroll
        for (int nt = 0; nt < 8; nt++)
#pragma unroll
            for (int q = 0; q < 4; q++) acc[mt][nt][q] = 0.0f;

    // per-thread load coords: u = tid + i*256 -> row u>>2, k-octet u&3
    auto load_stage = [&](int st, int q) {
        int t  = q / NCH;
        int kt = (q - t * NCH) * 32;
        const __nv_bfloat16* Ap = APtr[t];
        const __nv_bfloat16* Bp = BPtr[t];
#pragma unroll
        for (int i = 0; i < 2; i++) {
            int u = tid + i * 256;
            int r = u >> 2, k8 = u & 3;
            int woff = r * 20 + k8 * 4;
            // A (row-bounds checked, zero-filled)
            int gr = bm + r;
            int ok = (gr < Nr);
            const void* gA = Ap + (size_t)(ok ? gr : 0) * K + kt + k8 * 8;
            cp_async16((uint32_t)__cvta_generic_to_shared(&As[st][woff]), gA, ok ? 16 : 0);
            // B (always in bounds: bn + r < 256)
            const void* gB = Bp + (size_t)(bn + r) * K + kt + k8 * 8;
            cp_async16((uint32_t)__cvta_generic_to_shared(&Bs[st][woff]), gB, 16);
        }
        cp_commit();
    };

    auto compute_stage = [&](int st) {
        const int lr4 = lane >> 2, lk = lane & 3;
#pragma unroll
        for (int ks = 0; ks < 2; ks++) {
            const int kw = ks * 8;
            uint32_t a[2][4], b[8][2];
#pragma unroll
            for (int mt = 0; mt < 2; mt++) {
                int base = (warp_m * 32 + mt * 16 + lr4) * 20 + kw + lk;
                a[mt][0] = As[st][base];
                a[mt][1] = As[st][base + 160];
                a[mt][2] = As[st][base + 4];
                a[mt][3] = As[st][base + 164];
            }
#pragma unroll
            for (int nt = 0; nt < 8; nt++) {
                int base = (warp_n * 64 + nt * 8 + lr4) * 20 + kw + lk;
                b[nt][0] = Bs[st][base];
                b[nt][1] = Bs[st][base + 4];
            }
#pragma unroll
            for (int mt = 0; mt < 2; mt++)
#pragma unroll
                for (int nt = 0; nt < 8; nt++)
                    mma16816(acc[mt][nt], a[mt], b[nt]);
        }
    };

    load_stage(0, 0);
    for (int q = 0; q < NQ; q++) {
        if (q + 1 < NQ) {
            load_stage((q + 1) & 1, q + 1);
            cp_wait1();
        } else {
            cp_wait0();
        }
        __syncthreads();
        compute_stage(q & 1);
        __syncthreads();
    }

    // epilogue: write C and Agg = snorm * C
    const int lr4 = lane >> 2, lk = lane & 3;
#pragma unroll
    for (int mt = 0; mt < 2; mt++) {
#pragma unroll
        for (int half = 0; half < 2; half++) {
            int r = bm + warp_m * 32 + mt * 16 + half * 8 + lr4;
            if (r >= Nr) continue;
            float s = snorm[r];
#pragma unroll
            for (int nt = 0; nt < 8; nt++) {
                int c = bn + warp_n * 64 + nt * 8 + lk * 2;
                float v0 = acc[mt][nt][half * 2];
                float v1 = acc[mt][nt][half * 2 + 1];
                size_t off = (size_t)r * 256 + c;
                *reinterpret_cast<float2*>(C + off)   = make_float2(v0, v1);
                *reinterpret_cast<float2*>(Agg + off) = make_float2(v0 * s, v1 * s);
            }
        }
    }
}

// -------------------- scatter / bn --------------------
__global__ void k_scatter_h(const float* __restrict__ h, const float* __restrict__ norm,
                            const int* __restrict__ row, const int* __restrict__ col,
                            float* __restrict__ agg, int E) {
    int e = blockIdx.x * (blockDim.x >> 6) + (threadIdx.x >> 6);
    int lane = threadIdx.x & 63;
    if (e >= E) return;
    int r = row[e], c = col[e];
    float nv = norm[e];
    float4 v = *reinterpret_cast<const float4*>(h + (size_t)r * HH + lane * 4);
    float* dst = agg + (size_t)c * HH + lane * 4;
    atomicAdd(dst + 0, v.x * nv);
    atomicAdd(dst + 1, v.y * nv);
    atomicAdd(dst + 2, v.z * nv);
    atomicAdd(dst + 3, v.w * nv);
}

// bn+relu, plus bf16 split of the output (feeds next GEMM)
__global__ void k_bn_relu(const float* __restrict__ agg, float* __restrict__ out,
                          __nv_bfloat16* __restrict__ hi, __nv_bfloat16* __restrict__ lo,
                          const float* __restrict__ b, const float* __restrict__ g,
                          const float* __restrict__ be, const float* __restrict__ m,
                          const float* __restrict__ v, int n) {
    int idx = blockIdx.x * blockDim.x + threadIdx.x;
    if (idx >= n * (HH / 4)) return;
    int j4 = (idx & (HH / 4 - 1)) * 4;
    float4 a  = reinterpret_cast<const float4*>(agg)[idx];
    float4 bb = *reinterpret_cast<const float4*>(b + j4);
    float4 gg = *reinterpret_cast<const float4*>(g + j4);
    float4 ee = *reinterpret_cast<const float4*>(be + j4);
    float4 mm = *reinterpret_cast<const float4*>(m + j4);
    float4 vv = *reinterpret_cast<const float4*>(v + j4);
    float4 o;
    o.x = fmaxf((a.x + bb.x - mm.x) * rsqrtf(vv.x + BN_EPS) * gg.x + ee.x, 0.0f);
    o.y = fmaxf((a.y + bb.y - mm.y) * rsqrtf(vv.y + BN_EPS) * gg.y + ee.y, 0.0f);
    o.z = fmaxf((a.z + bb.z - mm.z) * rsqrtf(vv.z + BN_EPS) * gg.z + ee.z, 0.0f);
    o.w = fmaxf((a.w + bb.w - mm.w) * rsqrtf(vv.w + BN_EPS) * gg.w + ee.w, 0.0f);
    reinterpret_cast<float4*>(out)[idx] = o;
    split4(o, reinterpret_cast<__nv_bfloat162*>(hi),
              reinterpret_cast<__nv_bfloat162*>(lo), 2 * (size_t)idx);
}

// -------------------- layer 3 (OUT=2) --------------------
__global__ void k_gemm_out(const float* __restrict__ Hin, const float* __restrict__ W3,
                           float* __restrict__ h3, int n) {
    int i = blockIdx.x * blockDim.x + threadIdx.x;
    if (i >= n) return;
    const float4* hr = reinterpret_cast<const float4*>(Hin + (size_t)i * HH);
    float s0 = 0.f, s1 = 0.f;
#pragma unroll 16
    for (int k4 = 0; k4 < HH / 4; k4++) {
        float4 hv = hr[k4];
        int k = k4 * 4;
        s0 += hv.x * W3[(k + 0) * 2]     + hv.y * W3[(k + 1) * 2]
            + hv.z * W3[(k + 2) * 2]     + hv.w * W3[(k + 3) * 2];
        s1 += hv.x * W3[(k + 0) * 2 + 1] + hv.y * W3[(k + 1) * 2 + 1]
            + hv.z * W3[(k + 2) * 2 + 1] + hv.w * W3[(k + 3) * 2 + 1];
    }
    h3[i * 2] = s0;
    h3[i * 2 + 1] = s1;
}
__global__ void k_out_init(const float* __restrict__ h3, const float* __restrict__ snorm,
                           const float* __restrict__ b3, float* __restrict__ out, int n) {
    int i = blockIdx.x * blockDim.x + threadIdx.x;
    if (i >= n) return;
    float s = snorm[i];
    out[i * 2]     = s * h3[i * 2]     + b3[0];
    out[i * 2 + 1] = s * h3[i * 2 + 1] + b3[1];
}
__global__ void k_scatter_out(const float* __restrict__ h3, const float* __restrict__ norm,
                              const int* __restrict__ row, const int* __restrict__ col,
                              float* __restrict__ out, int E) {
    int e = blockIdx.x * blockDim.x + threadIdx.x;
    if (e >= E) return;
    int r = row[e], c = col[e];
    float nv = norm[e];
    atomicAdd(&out[c * 2],     nv * h3[r * 2]);
    atomicAdd(&out[c * 2 + 1], nv * h3[r * 2 + 1]);
}

// -------------------- launch --------------------
extern "C" void kernel_launch(void* const* d_in, const int* in_sizes, int n_in,
                              void* d_out, int out_size) {
    const float*        x   = (const float*)d_in[0];
    const unsigned int* eiw = (const unsigned int*)d_in[1];
    const float*        w   = (const float*)d_in[2];
    const float*        W1  = (const float*)d_in[3];
    const float*        b1  = (const float*)d_in[4];
    const float*        g1  = (const float*)d_in[5];
    const float*        be1 = (const float*)d_in[6];
    const float*        m1  = (const float*)d_in[7];
    const float*        v1  = (const float*)d_in[8];
    const float*        W2  = (const float*)d_in[9];
    const float*        b2  = (const float*)d_in[10];
    const float*        g2  = (const float*)d_in[11];
    const float*        be2 = (const float*)d_in[12];
    const float*        m2  = (const float*)d_in[13];
    const float*        v2  = (const float*)d_in[14];
    const float*        W3  = (const float*)d_in[15];
    const float*        b3  = (const float*)d_in[16];
    float* out = (float*)d_out;

    int *row, *col;
    float *deg, *dinv, *snorm, *norm, *bufA, *bufB, *h3;
    __nv_bfloat16 *hi, *lo, *Whi, *Wlo;
    cudaGetSymbolAddress((void**)&row,   g_row);
    cudaGetSymbolAddress((void**)&col,   g_col);
    cudaGetSymbolAddress((void**)&deg,   g_deg);
    cudaGetSymbolAddress((void**)&dinv,  g_dinv);
    cudaGetSymbolAddress((void**)&snorm, g_snorm);
    cudaGetSymbolAddress((void**)&norm,  g_norm);
    cudaGetSymbolAddress((void**)&bufA,  g_bufA);
    cudaGetSymbolAddress((void**)&bufB,  g_bufB);
    cudaGetSymbolAddress((void**)&h3,    g_h3);
    cudaGetSymbolAddress((void**)&hi,    g_hi);
    cudaGetSymbolAddress((void**)&lo,    g_lo);
    cudaGetSymbolAddress((void**)&Whi,   g_Whi);
    cudaGetSymbolAddress((void**)&Wlo,   g_Wlo);

    const int n = NN, E = EE;
    dim3 t256(256);
    int nb_n  = (n + 255) / 256;
    int nb_e  = (E + 255) / 256;
    int nb_nh = (n * (HH / 4) + 255) / 256;
    int nb_es = (E + 3) / 4;
    int nb_sx = (int)(((size_t)n * FIN / 4 + 255) / 256);
    dim3 gemm_grid((n + 127) / 128, 2);

    // edges
    k_detect<<<1, 32>>>(eiw);
    k_extract<<<nb_e, t256>>>(eiw, row, col, E);
    k_set_deg<<<nb_n, t256>>>(deg, n);
    k_deg_acc<<<nb_e, t256>>>(col, w, deg, E);
    k_dinv<<<nb_n, t256>>>(deg, dinv, snorm, n);
    k_norm<<<nb_e, t256>>>(row, col, w, dinv, norm, E);

    // ---- layer 1 ----
    k_split_x<<<nb_sx, t256>>>(x, hi, lo, (size_t)n * FIN / 4);
    k_splitW<<<(256 * FIN + 255) / 256, t256>>>(W1, Whi, Wlo, FIN);
    mma_gemm<FIN><<<gemm_grid, t256>>>(hi, lo, Whi, Wlo, snorm, bufA, bufB, n);
    k_scatter_h<<<nb_es, t256>>>(bufA, norm, row, col, bufB, E);
    k_bn_relu<<<nb_nh, t256>>>(bufB, bufA, hi, lo, b1, g1, be1, m1, v1, n);

    // ---- layer 2 ----
    k_splitW<<<(256 * HH + 255) / 256, t256>>>(W2, Whi, Wlo, HH);
    mma_gemm<HH><<<gemm_grid, t256>>>(hi, lo, Whi, Wlo, snorm, bufB, bufA, n);
    k_scatter_h<<<nb_es, t256>>>(bufB, norm, row, col, bufA, E);
    k_bn_relu<<<nb_nh, t256>>>(bufA, bufB, hi, lo, b2, g2, be2, m2, v2, n);

    // ---- layer 3 ----
    k_gemm_out<<<nb_n, t256>>>(bufB, W3, h3, n);
    k_out_init<<<nb_n, t256>>>(h3, snorm, b3, out, n);
    k_scatter_out<<<nb_e, t256>>>(h3, norm, row, col, out, E);
}

// round 5
// speedup vs baseline: 3.1458x; 2.7386x over previous
#include <cuda_runtime.h>
#include <cuda_bf16.h>
#include <stdint.h>

#define NN   50000
#define EE   800000
#define FIN  512
#define HH   256
#define OUTF 2
#define BN_EPS 1e-5f

// -------------------- scratch --------------------
__device__ int   g_is64;
__device__ int   g_row[EE];
__device__ int   g_col[EE];
__device__ float g_deg[NN];
__device__ float g_dinv[NN];
__device__ float g_snorm[NN];
__device__ float g_norm[EE];
__device__ float g_bufA[(size_t)NN * HH];
__device__ float g_bufB[(size_t)NN * HH];
__device__ float g_h3[(size_t)NN * OUTF];
__device__ __nv_bfloat16 g_hi[(size_t)NN * FIN];
__device__ __nv_bfloat16 g_lo[(size_t)NN * FIN];
__device__ __nv_bfloat16 g_Whi[(size_t)HH * FIN];
__device__ __nv_bfloat16 g_Wlo[(size_t)HH * FIN];
// CSR (by destination col)
__device__ int   g_cnt[NN];
__device__ int   g_incl[NN];
__device__ int   g_blksum[128];
__device__ int   g_blkoff[128];
__device__ int   g_rowptr[NN + 1];
__device__ int   g_fill[NN];
__device__ int   g_src[EE];
__device__ float g_wedge[EE];
__device__ float g_kA[HH];
__device__ float g_kB[HH];

// -------------------- edge-index dtype --------------------
__global__ void k_detect(const unsigned int* __restrict__ w) {
    if (blockIdx.x == 0 && threadIdx.x == 0) {
        int is64 = 1;
        for (int i = 0; i < 2048; i++)
            if (w[2 * i + 1] != 0u) { is64 = 0; break; }
        g_is64 = is64;
    }
}
__global__ void k_extract(const unsigned int* __restrict__ w,
                          int* __restrict__ row, int* __restrict__ col, int E) {
    int e = blockIdx.x * blockDim.x + threadIdx.x;
    if (e >= E) return;
    if (g_is64) { row[e] = (int)w[2 * e]; col[e] = (int)w[2 * (E + e)]; }
    else        { row[e] = (int)w[e];     col[e] = (int)w[E + e]; }
}

// -------------------- degree / norm --------------------
__global__ void k_set_deg(float* deg, int* cnt, int* fill, int n) {
    int i = blockIdx.x * blockDim.x + threadIdx.x;
    if (i < n) { deg[i] = 1.0f; cnt[i] = 0; fill[i] = 0; }
}
__global__ void k_deg_acc(const int* __restrict__ col, const float* __restrict__ w,
                          float* __restrict__ deg, int* __restrict__ cnt, int E) {
    int e = blockIdx.x * blockDim.x + threadIdx.x;
    if (e < E) {
        int c = col[e];
        atomicAdd(&deg[c], w[e]);
        atomicAdd(&cnt[c], 1);
    }
}
__global__ void k_dinv(const float* __restrict__ deg, float* __restrict__ dinv,
                       float* __restrict__ snorm, int n) {
    int i = blockIdx.x * blockDim.x + threadIdx.x;
    if (i < n) { float d = rsqrtf(deg[i]); dinv[i] = d; snorm[i] = d * d; }
}
__global__ void k_norm(const int* __restrict__ row, const int* __restrict__ col,
                       const float* __restrict__ w, const float* __restrict__ dinv,
                       float* __restrict__ norm, int E) {
    int e = blockIdx.x * blockDim.x + threadIdx.x;
    if (e < E) norm[e] = dinv[row[e]] * w[e] * dinv[col[e]];
}

// -------------------- scan (3 tiny kernels) --------------------
__global__ void k_scan1(const int* __restrict__ cnt, int* __restrict__ incl,
                        int* __restrict__ blksum, int n) {
    __shared__ int sh[512];
    int t = threadIdx.x;
    int i = blockIdx.x * 512 + t;
    int v = (i < n) ? cnt[i] : 0;
    sh[t] = v;
    __syncthreads();
#pragma unroll
    for (int off = 1; off < 512; off <<= 1) {
        int x = (t >= off) ? sh[t - off] : 0;
        __syncthreads();
        sh[t] += x;
        __syncthreads();
    }
    if (i < n) incl[i] = sh[t];
    if (t == 511) blksum[blockIdx.x] = sh[511];
}
__global__ void k_scan2(const int* __restrict__ blksum, int* __restrict__ blkoff, int nb) {
    if (threadIdx.x == 0) {
        int acc = 0;
        for (int b = 0; b < nb; b++) { blkoff[b] = acc; acc += blksum[b]; }
    }
}
__global__ void k_scan3(const int* __restrict__ incl, const int* __restrict__ cnt,
                        const int* __restrict__ blkoff, int* __restrict__ rowptr,
                        int n, int E) {
    int i = blockIdx.x * blockDim.x + threadIdx.x;
    if (i < n) rowptr[i] = incl[i] - cnt[i] + blkoff[i / 512];
    if (i == 0) rowptr[n] = E;
}
__global__ void k_fill(const int* __restrict__ row, const int* __restrict__ col,
                       const float* __restrict__ norm, const int* __restrict__ rowptr,
                       int* __restrict__ fill, int* __restrict__ src,
                       float* __restrict__ wedge, int E) {
    int e = blockIdx.x * blockDim.x + threadIdx.x;
    if (e >= E) return;
    int c = col[e];
    int p = rowptr[c] + atomicAdd(&fill[c], 1);
    src[p] = row[e];
    wedge[p] = norm[e];
}

// -------------------- bn param precompute --------------------
__global__ void k_bnparams(const float* __restrict__ b, const float* __restrict__ g,
                           const float* __restrict__ be, const float* __restrict__ m,
                           const float* __restrict__ v,
                           float* __restrict__ kA, float* __restrict__ kB) {
    int c = threadIdx.x;   // 256
    float inv = rsqrtf(v[c] + BN_EPS) * g[c];
    kA[c] = inv;
    kB[c] = (b[c] - m[c]) * inv + be[c];
}

// -------------------- fp32 -> bf16 hi/lo split --------------------
__device__ __forceinline__ void split4(float4 v, __nv_bfloat162* H, __nv_bfloat162* L, size_t i2) {
    __nv_bfloat16 h0 = __float2bfloat16_rn(v.x);
    __nv_bfloat16 h1 = __float2bfloat16_rn(v.y);
    __nv_bfloat16 h2 = __float2bfloat16_rn(v.z);
    __nv_bfloat16 h3 = __float2bfloat16_rn(v.w);
    __nv_bfloat16 l0 = __float2bfloat16_rn(v.x - __bfloat162float(h0));
    __nv_bfloat16 l1 = __float2bfloat16_rn(v.y - __bfloat162float(h1));
    __nv_bfloat16 l2 = __float2bfloat16_rn(v.z - __bfloat162float(h2));
    __nv_bfloat16 l3 = __float2bfloat16_rn(v.w - __bfloat162float(h3));
    H[i2]     = __nv_bfloat162(h0, h1);
    H[i2 + 1] = __nv_bfloat162(h2, h3);
    L[i2]     = __nv_bfloat162(l0, l1);
    L[i2 + 1] = __nv_bfloat162(l2, l3);
}

__global__ void k_split_x(const float* __restrict__ x,
                          __nv_bfloat16* __restrict__ hi, __nv_bfloat16* __restrict__ lo,
                          size_t n4) {
    size_t i = (size_t)blockIdx.x * blockDim.x + threadIdx.x;
    if (i >= n4) return;
    split4(reinterpret_cast<const float4*>(x)[i],
           reinterpret_cast<__nv_bfloat162*>(hi),
           reinterpret_cast<__nv_bfloat162*>(lo), 2 * i);
}

// W [K,256] fp32 -> B [256,K] bf16 hi/lo (transposed; n-major, k contiguous)
__global__ void k_splitW(const float* __restrict__ W,
                         __nv_bfloat16* __restrict__ bhi, __nv_bfloat16* __restrict__ blo,
                         int K) {
    int idx = blockIdx.x * blockDim.x + threadIdx.x;
    if (idx >= 256 * K) return;
    int n = idx / K, k = idx - n * K;
    float v = W[(size_t)k * 256 + n];
    __nv_bfloat16 h = __float2bfloat16_rn(v);
    bhi[idx] = h;
    blo[idx] = __float2bfloat16_rn(v - __bfloat162float(h));
}

// -------------------- mma.sync helpers --------------------
__device__ __forceinline__ void mma16816(float* d, const uint32_t* a, const uint32_t* b) {
    asm volatile(
        "mma.sync.aligned.m16n8k16.row.col.f32.bf16.bf16.f32 "
        "{%0,%1,%2,%3}, {%4,%5,%6,%7}, {%8,%9}, {%0,%1,%2,%3};"
        : "+f"(d[0]), "+f"(d[1]), "+f"(d[2]), "+f"(d[3])
        : "r"(a[0]), "r"(a[1]), "r"(a[2]), "r"(a[3]), "r"(b[0]), "r"(b[1]));
}
__device__ __forceinline__ void cp_async16(uint32_t saddr, const void* gaddr, int src_sz) {
    asm volatile("cp.async.cg.shared.global [%0], [%1], 16, %2;"
                 :: "r"(saddr), "l"(gaddr), "r"(src_sz));
}
__device__ __forceinline__ void cp_commit() { asm volatile("cp.async.commit_group;"); }
__device__ __forceinline__ void cp_wait1()  { asm volatile("cp.async.wait_group 1;"); }
__device__ __forceinline__ void cp_wait0()  { asm volatile("cp.async.wait_group 0;"); }

// -------------------- split-bf16 HMMA GEMM --------------------
// C[Nr,256] = A[Nr,K] * B[256,K]^T  (3 split terms).
// Tiles: BM=128, BN=128, BK=32. 256 thr = 8 warps (4 x 2), warp tile 32x64.
template <int K>
__global__ __launch_bounds__(256, 2)
void mma_gemm(const __nv_bfloat16* __restrict__ Ahi, const __nv_bfloat16* __restrict__ Alo,
              const __nv_bfloat16* __restrict__ Bhi, const __nv_bfloat16* __restrict__ Blo,
              float* __restrict__ C, int Nr) {
    constexpr int NCH = K / 32;
    constexpr int NQ  = 3 * NCH;
    __shared__ uint32_t As[2][2560];   // 128 rows x 20 words
    __shared__ uint32_t Bs[2][2560];

    const int tid  = threadIdx.x;
    const int lane = tid & 31;
    const int wid  = tid >> 5;
    const int warp_m = wid & 3;
    const int warp_n = wid >> 2;
    const int bm = blockIdx.x * 128;
    const int bn = blockIdx.y * 128;

    const __nv_bfloat16* APtr[3] = {Ahi, Ahi, Alo};
    const __nv_bfloat16* BPtr[3] = {Bhi, Blo, Bhi};

    float acc[2][8][4];
#pragma unroll
    for (int mt = 0; mt < 2; mt++)
#pragma unroll
        for (int nt = 0; nt < 8; nt++)
#pragma unroll
            for (int q = 0; q < 4; q++) acc[mt][nt][q] = 0.0f;

    auto load_stage = [&](int st, int q) {
        int t  = q / NCH;
        int kt = (q - t * NCH) * 32;
        const __nv_bfloat16* Ap = APtr[t];
        const __nv_bfloat16* Bp = BPtr[t];
#pragma unroll
        for (int i = 0; i < 2; i++) {
            int u = tid + i * 256;
            int r = u >> 2, k8 = u & 3;
            int woff = r * 20 + k8 * 4;
            int gr = bm + r;
            int ok = (gr < Nr);
            const void* gA = Ap + (size_t)(ok ? gr : 0) * K + kt + k8 * 8;
            cp_async16((uint32_t)__cvta_generic_to_shared(&As[st][woff]), gA, ok ? 16 : 0);
            const void* gB = Bp + (size_t)(bn + r) * K + kt + k8 * 8;
            cp_async16((uint32_t)__cvta_generic_to_shared(&Bs[st][woff]), gB, 16);
        }
        cp_commit();
    };

    auto compute_stage = [&](int st) {
        const int lr4 = lane >> 2, lk = lane & 3;
#pragma unroll
        for (int ks = 0; ks < 2; ks++) {
            const int kw = ks * 8;
            uint32_t a[2][4], b[8][2];
#pragma unroll
            for (int mt = 0; mt < 2; mt++) {
                int base = (warp_m * 32 + mt * 16 + lr4) * 20 + kw + lk;
                a[mt][0] = As[st][base];
                a[mt][1] = As[st][base + 160];
                a[mt][2] = As[st][base + 4];
                a[mt][3] = As[st][base + 164];
            }
#pragma unroll
            for (int nt = 0; nt < 8; nt++) {
                int base = (warp_n * 64 + nt * 8 + lr4) * 20 + kw + lk;
                b[nt][0] = Bs[st][base];
                b[nt][1] = Bs[st][base + 4];
            }
#pragma unroll
            for (int mt = 0; mt < 2; mt++)
#pragma unroll
                for (int nt = 0; nt < 8; nt++)
                    mma16816(acc[mt][nt], a[mt], b[nt]);
        }
    };

    load_stage(0, 0);
    for (int q = 0; q < NQ; q++) {
        if (q + 1 < NQ) {
            load_stage((q + 1) & 1, q + 1);
            cp_wait1();
        } else {
            cp_wait0();
        }
        __syncthreads();
        compute_stage(q & 1);
        __syncthreads();
    }

    const int lr4 = lane >> 2, lk = lane & 3;
#pragma unroll
    for (int mt = 0; mt < 2; mt++) {
#pragma unroll
        for (int half = 0; half < 2; half++) {
            int r = bm + warp_m * 32 + mt * 16 + half * 8 + lr4;
            if (r >= Nr) continue;
#pragma unroll
            for (int nt = 0; nt < 8; nt++) {
                int c = bn + warp_n * 64 + nt * 8 + lk * 2;
                *reinterpret_cast<float2*>(C + (size_t)r * 256 + c) =
                    make_float2(acc[mt][nt][half * 2], acc[mt][nt][half * 2 + 1]);
            }
        }
    }
}

// -------------------- fused gather + BN + ReLU (+ optional bf16 split) --------------------
// 4 nodes per 256-thr block; 64 threads per node, thread owns 4 channels.
template <bool SPLIT>
__global__ __launch_bounds__(256)
void k_gather_bn(const float* __restrict__ h,
                 const int* __restrict__ rowptr, const int* __restrict__ src,
                 const float* __restrict__ wedge, const float* __restrict__ snorm,
                 const float* __restrict__ kA, const float* __restrict__ kB,
                 float* __restrict__ out,
                 __nv_bfloat16* __restrict__ hi, __nv_bfloat16* __restrict__ lo,
                 int n) {
    int i = blockIdx.x * 4 + (threadIdx.x >> 6);
    if (i >= n) return;
    int t = threadIdx.x & 63;
    int c = t * 4;

    float4 acc = *reinterpret_cast<const float4*>(h + (size_t)i * HH + c);
    float s = snorm[i];
    acc.x *= s; acc.y *= s; acc.z *= s; acc.w *= s;

    int p   = rowptr[i];
    int end = rowptr[i + 1];
    for (; p < end; p++) {
        int r = __ldg(&src[p]);
        float wv = __ldg(&wedge[p]);
        float4 v = *reinterpret_cast<const float4*>(h + (size_t)r * HH + c);
        acc.x += wv * v.x; acc.y += wv * v.y; acc.z += wv * v.z; acc.w += wv * v.w;
    }

    float4 a = *reinterpret_cast<const float4*>(kA + c);
    float4 b = *reinterpret_cast<const float4*>(kB + c);
    float4 o;
    o.x = fmaxf(acc.x * a.x + b.x, 0.0f);
    o.y = fmaxf(acc.y * a.y + b.y, 0.0f);
    o.z = fmaxf(acc.z * a.z + b.z, 0.0f);
    o.w = fmaxf(acc.w * a.w + b.w, 0.0f);

    if (SPLIT) {
        split4(o, reinterpret_cast<__nv_bfloat162*>(hi),
                  reinterpret_cast<__nv_bfloat162*>(lo),
               2 * ((size_t)i * (HH / 4) + t));
    } else {
        *reinterpret_cast<float4*>(out + (size_t)i * HH + c) = o;
    }
}

// -------------------- layer 3 (OUT=2) --------------------
__global__ void k_gemm_out(const float* __restrict__ Hin, const float* __restrict__ W3,
                           float* __restrict__ h3, int n) {
    int i = blockIdx.x * blockDim.x + threadIdx.x;
    if (i >= n) return;
    const float4* hr = reinterpret_cast<const float4*>(Hin + (size_t)i * HH);
    float s0 = 0.f, s1 = 0.f;
#pragma unroll 16
    for (int k4 = 0; k4 < HH / 4; k4++) {
        float4 hv = hr[k4];
        int k = k4 * 4;
        s0 += hv.x * W3[(k + 0) * 2]     + hv.y * W3[(k + 1) * 2]
            + hv.z * W3[(k + 2) * 2]     + hv.w * W3[(k + 3) * 2];
        s1 += hv.x * W3[(k + 0) * 2 + 1] + hv.y * W3[(k + 1) * 2 + 1]
            + hv.z * W3[(k + 2) * 2 + 1] + hv.w * W3[(k + 3) * 2 + 1];
    }
    h3[i * 2] = s0;
    h3[i * 2 + 1] = s1;
}
__global__ void k_gather_out(const float* __restrict__ h3,
                             const int* __restrict__ rowptr, const int* __restrict__ src,
                             const float* __restrict__ wedge, const float* __restrict__ snorm,
                             const float* __restrict__ b3, float* __restrict__ out, int n) {
    int i = blockIdx.x * blockDim.x + threadIdx.x;
    if (i >= n) return;
    float s = snorm[i];
    float a0 = s * h3[2 * i]     + b3[0];
    float a1 = s * h3[2 * i + 1] + b3[1];
    int p = rowptr[i], end = rowptr[i + 1];
    for (; p < end; p++) {
        int r = __ldg(&src[p]);
        float wv = __ldg(&wedge[p]);
        a0 += wv * h3[2 * r];
        a1 += wv * h3[2 * r + 1];
    }
    out[2 * i]     = a0;
    out[2 * i + 1] = a1;
}

// -------------------- launch --------------------
extern "C" void kernel_launch(void* const* d_in, const int* in_sizes, int n_in,
                              void* d_out, int out_size) {
    const float*        x   = (const float*)d_in[0];
    const unsigned int* eiw = (const unsigned int*)d_in[1];
    const float*        w   = (const float*)d_in[2];
    const float*        W1  = (const float*)d_in[3];
    const float*        b1  = (const float*)d_in[4];
    const float*        g1  = (const float*)d_in[5];
    const float*        be1 = (const float*)d_in[6];
    const float*        m1  = (const float*)d_in[7];
    const float*        v1  = (const float*)d_in[8];
    const float*        W2  = (const float*)d_in[9];
    const float*        b2  = (const float*)d_in[10];
    const float*        g2  = (const float*)d_in[11];
    const float*        be2 = (const float*)d_in[12];
    const float*        m2  = (const float*)d_in[13];
    const float*        v2  = (const float*)d_in[14];
    const float*        W3  = (const float*)d_in[15];
    const float*        b3  = (const float*)d_in[16];
    float* out = (float*)d_out;

    int *row, *col, *cnt, *incl, *blksum, *blkoff, *rowptr, *fill, *src;
    float *deg, *dinv, *snorm, *norm, *bufA, *bufB, *h3, *wedge, *kA, *kB;
    __nv_bfloat16 *hi, *lo, *Whi, *Wlo;
    cudaGetSymbolAddress((void**)&row,    g_row);
    cudaGetSymbolAddress((void**)&col,    g_col);
    cudaGetSymbolAddress((void**)&cnt,    g_cnt);
    cudaGetSymbolAddress((void**)&incl,   g_incl);
    cudaGetSymbolAddress((void**)&blksum, g_blksum);
    cudaGetSymbolAddress((void**)&blkoff, g_blkoff);
    cudaGetSymbolAddress((void**)&rowptr, g_rowptr);
    cudaGetSymbolAddress((void**)&fill,   g_fill);
    cudaGetSymbolAddress((void**)&src,    g_src);
    cudaGetSymbolAddress((void**)&wedge,  g_wedge);
    cudaGetSymbolAddress((void**)&deg,    g_deg);
    cudaGetSymbolAddress((void**)&dinv,   g_dinv);
    cudaGetSymbolAddress((void**)&snorm,  g_snorm);
    cudaGetSymbolAddress((void**)&norm,   g_norm);
    cudaGetSymbolAddress((void**)&bufA,   g_bufA);
    cudaGetSymbolAddress((void**)&bufB,   g_bufB);
    cudaGetSymbolAddress((void**)&h3,     g_h3);
    cudaGetSymbolAddress((void**)&kA,     g_kA);
    cudaGetSymbolAddress((void**)&kB,     g_kB);
    cudaGetSymbolAddress((void**)&hi,     g_hi);
    cudaGetSymbolAddress((void**)&lo,     g_lo);
    cudaGetSymbolAddress((void**)&Whi,    g_Whi);
    cudaGetSymbolAddress((void**)&Wlo,    g_Wlo);

    const int n = NN, E = EE;
    dim3 t256(256);
    int nb_n  = (n + 255) / 256;
    int nb_e  = (E + 255) / 256;
    int nb_sx = (int)(((size_t)n * FIN / 4 + 255) / 256);
    int nb_sc = (n + 511) / 512;          // 98 scan blocks
    int nb_g  = (n + 3) / 4;              // gather blocks
    dim3 gemm_grid((n + 127) / 128, 2);

    // edges + CSR
    k_detect<<<1, 32>>>(eiw);
    k_extract<<<nb_e, t256>>>(eiw, row, col, E);
    k_set_deg<<<nb_n, t256>>>(deg, cnt, fill, n);
    k_deg_acc<<<nb_e, t256>>>(col, w, deg, cnt, E);
    k_dinv<<<nb_n, t256>>>(deg, dinv, snorm, n);
    k_norm<<<nb_e, t256>>>(row, col, w, dinv, norm, E);
    k_scan1<<<nb_sc, 512>>>(cnt, incl, blksum, n);
    k_scan2<<<1, 32>>>(blksum, blkoff, nb_sc);
    k_scan3<<<nb_n, t256>>>(incl, cnt, blkoff, rowptr, n, E);
    k_fill<<<nb_e, t256>>>(row, col, norm, rowptr, fill, src, wedge, E);

    // ---- layer 1 ----
    k_split_x<<<nb_sx, t256>>>(x, hi, lo, (size_t)n * FIN / 4);
    k_splitW<<<(256 * FIN + 255) / 256, t256>>>(W1, Whi, Wlo, FIN);
    mma_gemm<FIN><<<gemm_grid, t256>>>(hi, lo, Whi, Wlo, bufA, n);
    k_bnparams<<<1, 256>>>(b1, g1, be1, m1, v1, kA, kB);
    k_gather_bn<true><<<nb_g, t256>>>(bufA, rowptr, src, wedge, snorm, kA, kB,
                                      nullptr, hi, lo, n);

    // ---- layer 2 ----
    k_splitW<<<(256 * HH + 255) / 256, t256>>>(W2, Whi, Wlo, HH);
    mma_gemm<HH><<<gemm_grid, t256>>>(hi, lo, Whi, Wlo, bufB, n);
    k_bnparams<<<1, 256>>>(b2, g2, be2, m2, v2, kA, kB);
    k_gather_bn<false><<<nb_g, t256>>>(bufB, rowptr, src, wedge, snorm, kA, kB,
                                       bufA, nullptr, nullptr, n);

    // ---- layer 3 ----
    k_gemm_out<<<nb_n, t256>>>(bufA, W3, h3, n);
    k_gather_out<<<nb_n, t256>>>(h3, rowptr, src, wedge, snorm, b3, out, n);
}

// round 6
// speedup vs baseline: 3.1491x; 1.0011x over previous
#include <cuda_runtime.h>
#include <cuda_bf16.h>
#include <stdint.h>

#define NN   50000
#define EE   800000
#define FIN  512
#define HH   256
#define OUTF 2
#define BN_EPS 1e-5f

// -------------------- scratch --------------------
__device__ int   g_is64;
__device__ int   g_row[EE];
__device__ int   g_col[EE];
__device__ float g_deg[NN];
__device__ float g_dinv[NN];
__device__ float g_snorm[NN];
__device__ float g_bufA[(size_t)NN * HH];
__device__ float g_bufB[(size_t)NN * HH];
__device__ float g_h3[(size_t)NN * OUTF];
__device__ __nv_bfloat16 g_hi[(size_t)NN * FIN];
__device__ __nv_bfloat16 g_lo[(size_t)NN * FIN];
__device__ __nv_bfloat16 g_Whi[(size_t)HH * FIN];
__device__ __nv_bfloat16 g_Wlo[(size_t)HH * FIN];
// CSR (by destination col)
__device__ int   g_cnt[NN];
__device__ int   g_incl[NN];
__device__ int   g_blksum[128];
__device__ int   g_blkoff[128];
__device__ int   g_rowptr[NN + 1];
__device__ int   g_fill[NN];
__device__ int   g_src[EE];
__device__ float g_wedge[EE];

// -------------------- edge-index dtype --------------------
__global__ void k_detect(const unsigned int* __restrict__ w) {
    if (blockIdx.x == 0 && threadIdx.x == 0) {
        int is64 = 1;
        for (int i = 0; i < 2048; i++)
            if (w[2 * i + 1] != 0u) { is64 = 0; break; }
        g_is64 = is64;
    }
}

// -------------------- init --------------------
__global__ void k_init(float* deg, int* cnt, int* fill, int n) {
    int i = blockIdx.x * blockDim.x + threadIdx.x;
    if (i < n) { deg[i] = 1.0f; cnt[i] = 0; fill[i] = 0; }
}

// fused: extract indices (either dtype) + degree/count atomics
__global__ void k_extract_deg(const unsigned int* __restrict__ wr,
                              const float* __restrict__ w,
                              int* __restrict__ row, int* __restrict__ col,
                              float* __restrict__ deg, int* __restrict__ cnt, int E) {
    int e = blockIdx.x * blockDim.x + threadIdx.x;
    if (e >= E) return;
    int r, c;
    if (g_is64) { r = (int)wr[2 * e]; c = (int)wr[2 * (E + e)]; }
    else        { r = (int)wr[e];     c = (int)wr[E + e]; }
    row[e] = r;
    col[e] = c;
    atomicAdd(&deg[c], w[e]);
    atomicAdd(&cnt[c], 1);
}

__global__ void k_dinv(const float* __restrict__ deg, float* __restrict__ dinv,
                       float* __restrict__ snorm, int n) {
    int i = blockIdx.x * blockDim.x + threadIdx.x;
    if (i < n) { float d = rsqrtf(deg[i]); dinv[i] = d; snorm[i] = d * d; }
}

// -------------------- scan --------------------
__global__ void k_scan1(const int* __restrict__ cnt, int* __restrict__ incl,
                        int* __restrict__ blksum, int n) {
    __shared__ int sh[512];
    int t = threadIdx.x;
    int i = blockIdx.x * 512 + t;
    int v = (i < n) ? cnt[i] : 0;
    sh[t] = v;
    __syncthreads();
#pragma unroll
    for (int off = 1; off < 512; off <<= 1) {
        int x = (t >= off) ? sh[t - off] : 0;
        __syncthreads();
        sh[t] += x;
        __syncthreads();
    }
    if (i < n) incl[i] = sh[t];
    if (t == 511) blksum[blockIdx.x] = sh[511];
}
__global__ void k_scan2(const int* __restrict__ blksum, int* __restrict__ blkoff, int nb) {
    __shared__ int sh[128];
    int t = threadIdx.x;
    sh[t] = (t < nb) ? blksum[t] : 0;
    __syncthreads();
#pragma unroll
    for (int off = 1; off < 128; off <<= 1) {
        int x = (t >= off) ? sh[t - off] : 0;
        __syncthreads();
        sh[t] += x;
        __syncthreads();
    }
    if (t < nb) blkoff[t] = sh[t] - blksum[t];   // exclusive
}
__global__ void k_scan3(const int* __restrict__ incl, const int* __restrict__ cnt,
                        const int* __restrict__ blkoff, int* __restrict__ rowptr,
                        int n, int E) {
    int i = blockIdx.x * blockDim.x + threadIdx.x;
    if (i < n) rowptr[i] = incl[i] - cnt[i] + blkoff[i / 512];
    if (i == 0) rowptr[n] = E;
}

// fused: norm compute + CSR fill
__global__ void k_norm_fill(const int* __restrict__ row, const int* __restrict__ col,
                            const float* __restrict__ w, const float* __restrict__ dinv,
                            const int* __restrict__ rowptr, int* __restrict__ fill,
                            int* __restrict__ src, float* __restrict__ wedge, int E) {
    int e = blockIdx.x * blockDim.x + threadIdx.x;
    if (e >= E) return;
    int r = row[e], c = col[e];
    float nv = dinv[r] * w[e] * dinv[c];
    int p = rowptr[c] + atomicAdd(&fill[c], 1);
    src[p] = r;
    wedge[p] = nv;
}

// -------------------- fp32 -> bf16 hi/lo split --------------------
__device__ __forceinline__ void split4(float4 v, __nv_bfloat162* H, __nv_bfloat162* L, size_t i2) {
    __nv_bfloat16 h0 = __float2bfloat16_rn(v.x);
    __nv_bfloat16 h1 = __float2bfloat16_rn(v.y);
    __nv_bfloat16 h2 = __float2bfloat16_rn(v.z);
    __nv_bfloat16 h3 = __float2bfloat16_rn(v.w);
    __nv_bfloat16 l0 = __float2bfloat16_rn(v.x - __bfloat162float(h0));
    __nv_bfloat16 l1 = __float2bfloat16_rn(v.y - __bfloat162float(h1));
    __nv_bfloat16 l2 = __float2bfloat16_rn(v.z - __bfloat162float(h2));
    __nv_bfloat16 l3 = __float2bfloat16_rn(v.w - __bfloat162float(h3));
    H[i2]     = __nv_bfloat162(h0, h1);
    H[i2 + 1] = __nv_bfloat162(h2, h3);
    L[i2]     = __nv_bfloat162(l0, l1);
    L[i2 + 1] = __nv_bfloat162(l2, l3);
}

__global__ void k_split_x(const float* __restrict__ x,
                          __nv_bfloat16* __restrict__ hi, __nv_bfloat16* __restrict__ lo,
                          size_t n4) {
    size_t i = (size_t)blockIdx.x * blockDim.x + threadIdx.x;
    if (i >= n4) return;
    split4(reinterpret_cast<const float4*>(x)[i],
           reinterpret_cast<__nv_bfloat162*>(hi),
           reinterpret_cast<__nv_bfloat162*>(lo), 2 * i);
}

// W [K,256] fp32 -> B [256,K] bf16 hi/lo (transposed; n-major, k contiguous)
__global__ void k_splitW(const float* __restrict__ W,
                         __nv_bfloat16* __restrict__ bhi, __nv_bfloat16* __restrict__ blo,
                         int K) {
    int idx = blockIdx.x * blockDim.x + threadIdx.x;
    if (idx >= 256 * K) return;
    int n = idx / K, k = idx - n * K;
    float v = W[(size_t)k * 256 + n];
    __nv_bfloat16 h = __float2bfloat16_rn(v);
    bhi[idx] = h;
    blo[idx] = __float2bfloat16_rn(v - __bfloat162float(h));
}

// -------------------- mma.sync / ldmatrix helpers --------------------
__device__ __forceinline__ void mma16816(float* d, const uint32_t* a, const uint32_t* b) {
    asm volatile(
        "mma.sync.aligned.m16n8k16.row.col.f32.bf16.bf16.f32 "
        "{%0,%1,%2,%3}, {%4,%5,%6,%7}, {%8,%9}, {%0,%1,%2,%3};"
        : "+f"(d[0]), "+f"(d[1]), "+f"(d[2]), "+f"(d[3])
        : "r"(a[0]), "r"(a[1]), "r"(a[2]), "r"(a[3]), "r"(b[0]), "r"(b[1]));
}
__device__ __forceinline__ void ldmatrix_x4(uint32_t& r0, uint32_t& r1, uint32_t& r2,
                                            uint32_t& r3, uint32_t saddr) {
    asm volatile("ldmatrix.sync.aligned.m8n8.x4.shared.b16 {%0,%1,%2,%3}, [%4];"
                 : "=r"(r0), "=r"(r1), "=r"(r2), "=r"(r3) : "r"(saddr));
}
__device__ __forceinline__ void cp_async16(uint32_t saddr, const void* gaddr, int src_sz) {
    asm volatile("cp.async.cg.shared.global [%0], [%1], 16, %2;"
                 :: "r"(saddr), "l"(gaddr), "r"(src_sz));
}
__device__ __forceinline__ void cp_commit() { asm volatile("cp.async.commit_group;"); }
__device__ __forceinline__ void cp_wait1()  { asm volatile("cp.async.wait_group 1;"); }
__device__ __forceinline__ void cp_wait0()  { asm volatile("cp.async.wait_group 0;"); }

// -------------------- split-bf16 HMMA GEMM (ldmatrix fragments) --------------------
// C[Nr,256] = A[Nr,K] * B[256,K]^T  (3 split terms).
// BM=128, BN=128, BK=32. 8 warps (4 M x 2 N), warp tile 32x64.
template <int K>
__global__ __launch_bounds__(256, 2)
void mma_gemm(const __nv_bfloat16* __restrict__ Ahi, const __nv_bfloat16* __restrict__ Alo,
              const __nv_bfloat16* __restrict__ Bhi, const __nv_bfloat16* __restrict__ Blo,
              float* __restrict__ C, int Nr) {
    constexpr int NCH = K / 32;
    constexpr int NQ  = 3 * NCH;
    __shared__ uint32_t As[2][2560];   // 128 rows x 20 words (40 halves)
    __shared__ uint32_t Bs[2][2560];

    const int tid  = threadIdx.x;
    const int lane = tid & 31;
    const int wid  = tid >> 5;
    const int warp_m = wid & 3;
    const int warp_n = wid >> 2;
    const int bm = blockIdx.x * 128;
    const int bn = blockIdx.y * 128;

    const __nv_bfloat16* APtr[3] = {Ahi, Ahi, Alo};
    const __nv_bfloat16* BPtr[3] = {Bhi, Blo, Bhi};

    float acc[2][8][4];
#pragma unroll
    for (int mt = 0; mt < 2; mt++)
#pragma unroll
        for (int nt = 0; nt < 8; nt++)
#pragma unroll
            for (int q = 0; q < 4; q++) acc[mt][nt][q] = 0.0f;

    auto load_stage = [&](int st, int q) {
        int t  = q / NCH;
        int kt = (q - t * NCH) * 32;
        const __nv_bfloat16* Ap = APtr[t];
        const __nv_bfloat16* Bp = BPtr[t];
#pragma unroll
        for (int i = 0; i < 2; i++) {
            int u = tid + i * 256;
            int r = u >> 2, k8 = u & 3;
            int woff = r * 20 + k8 * 4;
            int gr = bm + r;
            int ok = (gr < Nr);
            const void* gA = Ap + (size_t)(ok ? gr : 0) * K + kt + k8 * 8;
            cp_async16((uint32_t)__cvta_generic_to_shared(&As[st][woff]), gA, ok ? 16 : 0);
            const void* gB = Bp + (size_t)(bn + r) * K + kt + k8 * 8;
            cp_async16((uint32_t)__cvta_generic_to_shared(&Bs[st][woff]), gB, 16);
        }
        cp_commit();
    };

    // ldmatrix lane-address components
    const int aRow  = warp_m * 32 + (lane & 7) + ((lane >> 3) & 1) * 8;  // + mt*16
    const int aWsel = (lane >> 4) * 4;                                    // + kw
    const int bRow  = warp_n * 64 + (lane & 7) + (lane >> 4) * 8;        // + np*16
    const int bWsel = ((lane >> 3) & 1) * 4;                              // + kw

    auto compute_stage = [&](int st) {
#pragma unroll
        for (int ks = 0; ks < 2; ks++) {
            const int kw = ks * 8;
            uint32_t a[2][4], b[8][2];
#pragma unroll
            for (int mt = 0; mt < 2; mt++) {
                uint32_t ad = (uint32_t)__cvta_generic_to_shared(
                    &As[st][(aRow + mt * 16) * 20 + kw + aWsel]);
                ldmatrix_x4(a[mt][0], a[mt][1], a[mt][2], a[mt][3], ad);
            }
#pragma unroll
            for (int np = 0; np < 4; np++) {
                uint32_t bd = (uint32_t)__cvta_generic_to_shared(
                    &Bs[st][(bRow + np * 16) * 20 + kw + bWsel]);
                ldmatrix_x4(b[2 * np][0], b[2 * np][1], b[2 * np + 1][0], b[2 * np + 1][1], bd);
            }
#pragma unroll
            for (int mt = 0; mt < 2; mt++)
#pragma unroll
                for (int nt = 0; nt < 8; nt++)
                    mma16816(acc[mt][nt], a[mt], b[nt]);
        }
    };

    load_stage(0, 0);
    for (int q = 0; q < NQ; q++) {
        if (q + 1 < NQ) {
            load_stage((q + 1) & 1, q + 1);
            cp_wait1();
        } else {
            cp_wait0();
        }
        __syncthreads();
        compute_stage(q & 1);
        __syncthreads();
    }

    const int lr4 = lane >> 2, lk = lane & 3;
#pragma unroll
    for (int mt = 0; mt < 2; mt++) {
#pragma unroll
        for (int half = 0; half < 2; half++) {
            int r = bm + warp_m * 32 + mt * 16 + half * 8 + lr4;
            if (r >= Nr) continue;
#pragma unroll
            for (int nt = 0; nt < 8; nt++) {
                int c = bn + warp_n * 64 + nt * 8 + lk * 2;
                *reinterpret_cast<float2*>(C + (size_t)r * 256 + c) =
                    make_float2(acc[mt][nt][half * 2], acc[mt][nt][half * 2 + 1]);
            }
        }
    }
}

// -------------------- fused gather + BN + ReLU --------------------
// 4 nodes per 256-thr block (NN divisible by 4); 64 threads/node, 4 ch/thread.
// Edge loop unrolled x2 for MLP. BN params computed inline.
// W3MODE: additionally reduce o @ W3 -> h3 (layer 2+3 fusion). Else SPLIT writes bf16 hi/lo.
template <bool W3MODE>
__global__ __launch_bounds__(256)
void k_gather_bn(const float* __restrict__ h,
                 const int* __restrict__ rowptr, const int* __restrict__ src,
                 const float* __restrict__ wedge, const float* __restrict__ snorm,
                 const float* __restrict__ bb, const float* __restrict__ gg,
                 const float* __restrict__ bee, const float* __restrict__ mm,
                 const float* __restrict__ vv,
                 __nv_bfloat16* __restrict__ hi, __nv_bfloat16* __restrict__ lo,
                 const float* __restrict__ W3, float* __restrict__ h3, int n) {
    __shared__ float red[4][2][2];
    int i = blockIdx.x * 4 + (threadIdx.x >> 6);
    int t = threadIdx.x & 63;
    int c = t * 4;

    float4 acc = *reinterpret_cast<const float4*>(h + (size_t)i * HH + c);
    float s = snorm[i];
    acc.x *= s; acc.y *= s; acc.z *= s; acc.w *= s;

    int p   = rowptr[i];
    int end = rowptr[i + 1];
    for (; p + 1 < end; p += 2) {
        int   r0 = __ldg(&src[p]),     r1 = __ldg(&src[p + 1]);
        float w0 = __ldg(&wedge[p]),   w1 = __ldg(&wedge[p + 1]);
        float4 v0 = *reinterpret_cast<const float4*>(h + (size_t)r0 * HH + c);
        float4 v1 = *reinterpret_cast<const float4*>(h + (size_t)r1 * HH + c);
        acc.x += w0 * v0.x + w1 * v1.x;
        acc.y += w0 * v0.y + w1 * v1.y;
        acc.z += w0 * v0.z + w1 * v1.z;
        acc.w += w0 * v0.w + w1 * v1.w;
    }
    if (p < end) {
        int r = __ldg(&src[p]);
        float wv = __ldg(&wedge[p]);
        float4 v = *reinterpret_cast<const float4*>(h + (size_t)r * HH + c);
        acc.x += wv * v.x; acc.y += wv * v.y; acc.z += wv * v.z; acc.w += wv * v.w;
    }

    // BN params inline (L1-hot)
    float4 B  = *reinterpret_cast<const float4*>(bb + c);
    float4 G  = *reinterpret_cast<const float4*>(gg + c);
    float4 BE = *reinterpret_cast<const float4*>(bee + c);
    float4 M  = *reinterpret_cast<const float4*>(mm + c);
    float4 V  = *reinterpret_cast<const float4*>(vv + c);
    float4 o;
    o.x = fmaxf((acc.x + B.x - M.x) * rsqrtf(V.x + BN_EPS) * G.x + BE.x, 0.0f);
    o.y = fmaxf((acc.y + B.y - M.y) * rsqrtf(V.y + BN_EPS) * G.y + BE.y, 0.0f);
    o.z = fmaxf((acc.z + B.z - M.z) * rsqrtf(V.z + BN_EPS) * G.z + BE.z, 0.0f);
    o.w = fmaxf((acc.w + B.w - M.w) * rsqrtf(V.w + BN_EPS) * G.w + BE.w, 0.0f);

    if (!W3MODE) {
        split4(o, reinterpret_cast<__nv_bfloat162*>(hi),
                  reinterpret_cast<__nv_bfloat162*>(lo),
               2 * ((size_t)i * (HH / 4) + t));
    } else {
        // per-thread partial of o @ W3 (W3 is [256,2] row-major, 2KB -> L1)
        float p0 = o.x * __ldg(&W3[(c + 0) * 2])     + o.y * __ldg(&W3[(c + 1) * 2])
                 + o.z * __ldg(&W3[(c + 2) * 2])     + o.w * __ldg(&W3[(c + 3) * 2]);
        float p1 = o.x * __ldg(&W3[(c + 0) * 2 + 1]) + o.y * __ldg(&W3[(c + 1) * 2 + 1])
                 + o.z * __ldg(&W3[(c + 2) * 2 + 1]) + o.w * __ldg(&W3[(c + 3) * 2 + 1]);
#pragma unroll
        for (int off = 16; off; off >>= 1) {
            p0 += __shfl_xor_sync(0xFFFFFFFFu, p0, off);
            p1 += __shfl_xor_sync(0xFFFFFFFFu, p1, off);
        }
        int node = threadIdx.x >> 6;
        int wIn  = (threadIdx.x >> 5) & 1;
        if ((threadIdx.x & 31) == 0) {
            red[node][wIn][0] = p0;
            red[node][wIn][1] = p1;
        }
        __syncthreads();
        if (t == 0) {
            h3[2 * i]     = red[node][0][0] + red[node][1][0];
            h3[2 * i + 1] = red[node][0][1] + red[node][1][1];
        }
    }
}

// -------------------- final gather (OUT=2) --------------------
__global__ void k_gather_out(const float* __restrict__ h3,
                             const int* __restrict__ rowptr, const int* __restrict__ src,
                             const float* __restrict__ wedge, const float* __restrict__ snorm,
                             const float* __restrict__ b3, float* __restrict__ out, int n) {
    int i = blockIdx.x * blockDim.x + threadIdx.x;
    if (i >= n) return;
    float s = snorm[i];
    float a0 = s * h3[2 * i]     + b3[0];
    float a1 = s * h3[2 * i + 1] + b3[1];
    int p = rowptr[i], end = rowptr[i + 1];
    for (; p + 1 < end; p += 2) {
        int   r0 = __ldg(&src[p]),   r1 = __ldg(&src[p + 1]);
        float w0 = __ldg(&wedge[p]), w1 = __ldg(&wedge[p + 1]);
        a0 += w0 * h3[2 * r0]     + w1 * h3[2 * r1];
        a1 += w0 * h3[2 * r0 + 1] + w1 * h3[2 * r1 + 1];
    }
    if (p < end) {
        int r = __ldg(&src[p]);
        float wv = __ldg(&wedge[p]);
        a0 += wv * h3[2 * r];
        a1 += wv * h3[2 * r + 1];
    }
    out[2 * i]     = a0;
    out[2 * i + 1] = a1;
}

// -------------------- launch --------------------
extern "C" void kernel_launch(void* const* d_in, const int* in_sizes, int n_in,
                              void* d_out, int out_size) {
    const float*        x   = (const float*)d_in[0];
    const unsigned int* eiw = (const unsigned int*)d_in[1];
    const float*        w   = (const float*)d_in[2];
    const float*        W1  = (const float*)d_in[3];
    const float*        b1  = (const float*)d_in[4];
    const float*        g1  = (const float*)d_in[5];
    const float*        be1 = (const float*)d_in[6];
    const float*        m1  = (const float*)d_in[7];
    const float*        v1  = (const float*)d_in[8];
    const float*        W2  = (const float*)d_in[9];
    const float*        b2  = (const float*)d_in[10];
    const float*        g2  = (const float*)d_in[11];
    const float*        be2 = (const float*)d_in[12];
    const float*        m2  = (const float*)d_in[13];
    const float*        v2  = (const float*)d_in[14];
    const float*        W3  = (const float*)d_in[15];
    const float*        b3  = (const float*)d_in[16];
    float* out = (float*)d_out;

    int *row, *col, *cnt, *incl, *blksum, *blkoff, *rowptr, *fill, *src;
    float *deg, *dinv, *snorm, *bufA, *bufB, *h3, *wedge;
    __nv_bfloat16 *hi, *lo, *Whi, *Wlo;
    cudaGetSymbolAddress((void**)&row,    g_row);
    cudaGetSymbolAddress((void**)&col,    g_col);
    cudaGetSymbolAddress((void**)&cnt,    g_cnt);
    cudaGetSymbolAddress((void**)&incl,   g_incl);
    cudaGetSymbolAddress((void**)&blksum, g_blksum);
    cudaGetSymbolAddress((void**)&blkoff, g_blkoff);
    cudaGetSymbolAddress((void**)&rowptr, g_rowptr);
    cudaGetSymbolAddress((void**)&fill,   g_fill);
    cudaGetSymbolAddress((void**)&src,    g_src);
    cudaGetSymbolAddress((void**)&wedge,  g_wedge);
    cudaGetSymbolAddress((void**)&deg,    g_deg);
    cudaGetSymbolAddress((void**)&dinv,   g_dinv);
    cudaGetSymbolAddress((void**)&snorm,  g_snorm);
    cudaGetSymbolAddress((void**)&bufA,   g_bufA);
    cudaGetSymbolAddress((void**)&bufB,   g_bufB);
    cudaGetSymbolAddress((void**)&h3,     g_h3);
    cudaGetSymbolAddress((void**)&hi,     g_hi);
    cudaGetSymbolAddress((void**)&lo,     g_lo);
    cudaGetSymbolAddress((void**)&Whi,    g_Whi);
    cudaGetSymbolAddress((void**)&Wlo,    g_Wlo);

    const int n = NN, E = EE;
    dim3 t256(256);
    int nb_n  = (n + 255) / 256;
    int nb_e  = (E + 255) / 256;
    int nb_sx = (int)(((size_t)n * FIN / 4 + 255) / 256);
    int nb_sc = (n + 511) / 512;          // 98 scan blocks
    int nb_g  = n / 4;                    // 12500 (NN % 4 == 0)
    dim3 gemm_grid((n + 127) / 128, 2);

    // edges + CSR
    k_detect<<<1, 32>>>(eiw);
    k_init<<<nb_n, t256>>>(deg, cnt, fill, n);
    k_extract_deg<<<nb_e, t256>>>(eiw, w, row, col, deg, cnt, E);
    k_dinv<<<nb_n, t256>>>(deg, dinv, snorm, n);
    k_scan1<<<nb_sc, 512>>>(cnt, incl, blksum, n);
    k_scan2<<<1, 128>>>(blksum, blkoff, nb_sc);
    k_scan3<<<nb_n, t256>>>(incl, cnt, blkoff, rowptr, n, E);
    k_norm_fill<<<nb_e, t256>>>(row, col, w, dinv, rowptr, fill, src, wedge, E);

    // ---- layer 1 ----
    k_split_x<<<nb_sx, t256>>>(x, hi, lo, (size_t)n * FIN / 4);
    k_splitW<<<(256 * FIN + 255) / 256, t256>>>(W1, Whi, Wlo, FIN);
    mma_gemm<FIN><<<gemm_grid, t256>>>(hi, lo, Whi, Wlo, bufA, n);
    k_gather_bn<false><<<nb_g, t256>>>(bufA, rowptr, src, wedge, snorm,
                                       b1, g1, be1, m1, v1, hi, lo, nullptr, nullptr, n);

    // ---- layer 2 (+W3 fused) ----
    k_splitW<<<(256 * HH + 255) / 256, t256>>>(W2, Whi, Wlo, HH);
    mma_gemm<HH><<<gemm_grid, t256>>>(hi, lo, Whi, Wlo, bufB, n);
    k_gather_bn<true><<<nb_g, t256>>>(bufB, rowptr, src, wedge, snorm,
                                      b2, g2, be2, m2, v2, nullptr, nullptr, W3, h3, n);

    // ---- layer 3 ----
    k_gather_out<<<nb_n, t256>>>(h3, rowptr, src, wedge, snorm, b3, out, n);
}

// round 7
// speedup vs baseline: 4.2481x; 1.3490x over previous
#include <cuda_runtime.h>
#include <cuda_fp16.h>
#include <stdint.h>

#define NN   50000
#define EE   800000
#define FIN  512
#define HH   256
#define OUTF 2
#define BN_EPS 1e-5f

// -------------------- scratch --------------------
__device__ int    g_is64;
__device__ int    g_row[EE];
__device__ int    g_col[EE];
__device__ float  g_deg[NN];
__device__ float  g_dinv[NN];
__device__ float  g_snorm[NN];
__device__ __half g_h16[(size_t)NN * HH];     // GEMM output, fp16
__device__ float  g_h3[(size_t)NN * OUTF];
__device__ __half g_hi[(size_t)NN * FIN];     // A hi (fp16 split)
__device__ __half g_lo[(size_t)NN * FIN];     // A lo
__device__ __half g_Wh1[(size_t)HH * FIN];    // W1^T fp16
__device__ __half g_Wh2[(size_t)HH * HH];     // W2^T fp16
// CSR (by destination col)
__device__ int    g_cnt[NN];
__device__ int    g_incl[NN];
__device__ int    g_blksum[128];
__device__ int    g_blkoff[128];
__device__ int    g_rowptr[NN + 1];
__device__ int    g_fill[NN];
__device__ int    g_src[EE];
__device__ float  g_wedge[EE];

// -------------------- init (+ parallel dtype detect in block 0) --------------------
__global__ void k_init(const unsigned int* __restrict__ wr,
                       float* deg, int* cnt, int* fill, int n) {
    int i = blockIdx.x * blockDim.x + threadIdx.x;
    if (i < n) { deg[i] = 1.0f; cnt[i] = 0; fill[i] = 0; }
    if (blockIdx.x == 0) {
        int ok = 1;
        for (int j = threadIdx.x; j < 2048; j += 256)
            if (wr[2 * j + 1] != 0u) ok = 0;
        int all = __syncthreads_and(ok);
        if (threadIdx.x == 0) g_is64 = all;
    }
}

// fused: extract indices (either dtype) + degree/count atomics
__global__ void k_extract_deg(const unsigned int* __restrict__ wr,
                              const float* __restrict__ w,
                              int* __restrict__ row, int* __restrict__ col,
                              float* __restrict__ deg, int* __restrict__ cnt, int E) {
    int e = blockIdx.x * blockDim.x + threadIdx.x;
    if (e >= E) return;
    int r, c;
    if (g_is64) { r = (int)wr[2 * e]; c = (int)wr[2 * (E + e)]; }
    else        { r = (int)wr[e];     c = (int)wr[E + e]; }
    row[e] = r;
    col[e] = c;
    atomicAdd(&deg[c], w[e]);
    atomicAdd(&cnt[c], 1);
}

// -------------------- scan --------------------
__global__ void k_scan1(const int* __restrict__ cnt, int* __restrict__ incl,
                        int* __restrict__ blksum, int n) {
    __shared__ int sh[512];
    int t = threadIdx.x;
    int i = blockIdx.x * 512 + t;
    int v = (i < n) ? cnt[i] : 0;
    sh[t] = v;
    __syncthreads();
#pragma unroll
    for (int off = 1; off < 512; off <<= 1) {
        int x = (t >= off) ? sh[t - off] : 0;
        __syncthreads();
        sh[t] += x;
        __syncthreads();
    }
    if (i < n) incl[i] = sh[t];
    if (t == 511) blksum[blockIdx.x] = sh[511];
}
__global__ void k_scan2(const int* __restrict__ blksum, int* __restrict__ blkoff, int nb) {
    __shared__ int sh[128];
    int t = threadIdx.x;
    sh[t] = (t < nb) ? blksum[t] : 0;
    __syncthreads();
#pragma unroll
    for (int off = 1; off < 128; off <<= 1) {
        int x = (t >= off) ? sh[t - off] : 0;
        __syncthreads();
        sh[t] += x;
        __syncthreads();
    }
    if (t < nb) blkoff[t] = sh[t] - blksum[t];   // exclusive
}
// fused: rowptr finalize + dinv/snorm
__global__ void k_scan3_dinv(const int* __restrict__ incl, const int* __restrict__ cnt,
                             const int* __restrict__ blkoff, int* __restrict__ rowptr,
                             const float* __restrict__ deg, float* __restrict__ dinv,
                             float* __restrict__ snorm, int n, int E) {
    int i = blockIdx.x * blockDim.x + threadIdx.x;
    if (i < n) {
        rowptr[i] = incl[i] - cnt[i] + blkoff[i / 512];
        float d = rsqrtf(deg[i]);
        dinv[i] = d;
        snorm[i] = d * d;
    }
    if (i == 0) rowptr[n] = E;
}

// fused: norm compute + CSR fill
__global__ void k_norm_fill(const int* __restrict__ row, const int* __restrict__ col,
                            const float* __restrict__ w, const float* __restrict__ dinv,
                            const int* __restrict__ rowptr, int* __restrict__ fill,
                            int* __restrict__ src, float* __restrict__ wedge, int E) {
    int e = blockIdx.x * blockDim.x + threadIdx.x;
    if (e >= E) return;
    int r = row[e], c = col[e];
    float nv = dinv[r] * w[e] * dinv[c];
    int p = rowptr[c] + atomicAdd(&fill[c], 1);
    src[p] = r;
    wedge[p] = nv;
}

// -------------------- fp32 -> fp16 hi/lo split --------------------
__device__ __forceinline__ void split4h(float4 v, __half2* H, __half2* L, size_t i2) {
    __half h0 = __float2half_rn(v.x);
    __half h1 = __float2half_rn(v.y);
    __half h2 = __float2half_rn(v.z);
    __half h3 = __float2half_rn(v.w);
    __half l0 = __float2half_rn(v.x - __half2float(h0));
    __half l1 = __float2half_rn(v.y - __half2float(h1));
    __half l2 = __float2half_rn(v.z - __half2float(h2));
    __half l3 = __float2half_rn(v.w - __half2float(h3));
    H[i2]     = __halves2half2(h0, h1);
    H[i2 + 1] = __halves2half2(h2, h3);
    L[i2]     = __halves2half2(l0, l1);
    L[i2 + 1] = __halves2half2(l2, l3);
}

// one kernel: split x (hi/lo), transpose+round W1, W2 to fp16
#define XB   25000   // n*FIN/4/256
#define W1B  512     // 256*512/256
#define W2B  256     // 256*256/256
__global__ void k_split_all(const float* __restrict__ x,
                            __half* __restrict__ hi, __half* __restrict__ lo,
                            const float* __restrict__ W1, __half* __restrict__ Wh1,
                            const float* __restrict__ W2, __half* __restrict__ Wh2) {
    int b = blockIdx.x;
    int tid = threadIdx.x;
    if (b < XB) {
        size_t i = (size_t)b * 256 + tid;
        split4h(reinterpret_cast<const float4*>(x)[i],
                reinterpret_cast<__half2*>(hi),
                reinterpret_cast<__half2*>(lo), 2 * i);
    } else if (b < XB + W1B) {
        int u = (b - XB) * 256 + tid;          // [256,512]
        int n = u >> 9, k = u & 511;
        Wh1[u] = __float2half_rn(W1[(size_t)k * 256 + n]);
    } else {
        int u = (b - XB - W1B) * 256 + tid;    // [256,256]
        int n = u >> 8, k = u & 255;
        Wh2[u] = __float2half_rn(W2[(size_t)k * 256 + n]);
    }
}

// -------------------- mma.sync / ldmatrix helpers --------------------
__device__ __forceinline__ void mma16816(float* d, const uint32_t* a, const uint32_t* b) {
    asm volatile(
        "mma.sync.aligned.m16n8k16.row.col.f32.f16.f16.f32 "
        "{%0,%1,%2,%3}, {%4,%5,%6,%7}, {%8,%9}, {%0,%1,%2,%3};"
        : "+f"(d[0]), "+f"(d[1]), "+f"(d[2]), "+f"(d[3])
        : "r"(a[0]), "r"(a[1]), "r"(a[2]), "r"(a[3]), "r"(b[0]), "r"(b[1]));
}
__device__ __forceinline__ void ldmatrix_x4(uint32_t& r0, uint32_t& r1, uint32_t& r2,
                                            uint32_t& r3, uint32_t saddr) {
    asm volatile("ldmatrix.sync.aligned.m8n8.x4.shared.b16 {%0,%1,%2,%3}, [%4];"
                 : "=r"(r0), "=r"(r1), "=r"(r2), "=r"(r3) : "r"(saddr));
}
__device__ __forceinline__ void cp_async16(uint32_t saddr, const void* gaddr, int src_sz) {
    asm volatile("cp.async.cg.shared.global [%0], [%1], 16, %2;"
                 :: "r"(saddr), "l"(gaddr), "r"(src_sz));
}
__device__ __forceinline__ void cp_commit() { asm volatile("cp.async.commit_group;"); }
__device__ __forceinline__ void cp_wait1()  { asm volatile("cp.async.wait_group 1;"); }
__device__ __forceinline__ void cp_wait0()  { asm volatile("cp.async.wait_group 0;"); }

// -------------------- 2-term fp16 HMMA GEMM --------------------
// C[Nr,256] = (Ahi+Alo)[Nr,K] * B[256,K]^T, fp16 in / fp32 accum, C stored fp16.
// BM=128, BN=128, BK=32. 8 warps (4 M x 2 N), warp tile 32x64.
template <int K>
__global__ __launch_bounds__(256, 2)
void mma_gemm(const __half* __restrict__ Ahi, const __half* __restrict__ Alo,
              const __half* __restrict__ Bh,
              __half* __restrict__ C, int Nr) {
    constexpr int NCH = K / 32;
    constexpr int NQ  = 2 * NCH;
    __shared__ uint32_t As[2][2560];   // 128 rows x 20 words (40 halves)
    __shared__ uint32_t Bs[2][2560];

    const int tid  = threadIdx.x;
    const int lane = tid & 31;
    const int wid  = tid >> 5;
    const int warp_m = wid & 3;
    const int warp_n = wid >> 2;
    const int bm = blockIdx.x * 128;
    const int bn = blockIdx.y * 128;

    const __half* APtr[2] = {Ahi, Alo};

    float acc[2][8][4];
#pragma unroll
    for (int mt = 0; mt < 2; mt++)
#pragma unroll
        for (int nt = 0; nt < 8; nt++)
#pragma unroll
            for (int q = 0; q < 4; q++) acc[mt][nt][q] = 0.0f;

    auto load_stage = [&](int st, int q) {
        int t  = q / NCH;
        int kt = (q - t * NCH) * 32;
        const __half* Ap = APtr[t];
#pragma unroll
        for (int i = 0; i < 2; i++) {
            int u = tid + i * 256;
            int r = u >> 2, k8 = u & 3;
            int woff = r * 20 + k8 * 4;
            int gr = bm + r;
            int ok = (gr < Nr);
            const void* gA = Ap + (size_t)(ok ? gr : 0) * K + kt + k8 * 8;
            cp_async16((uint32_t)__cvta_generic_to_shared(&As[st][woff]), gA, ok ? 16 : 0);
            const void* gB = Bh + (size_t)(bn + r) * K + kt + k8 * 8;
            cp_async16((uint32_t)__cvta_generic_to_shared(&Bs[st][woff]), gB, 16);
        }
        cp_commit();
    };

    const int aRow  = warp_m * 32 + (lane & 7) + ((lane >> 3) & 1) * 8;
    const int aWsel = (lane >> 4) * 4;
    const int bRow  = warp_n * 64 + (lane & 7) + (lane >> 4) * 8;
    const int bWsel = ((lane >> 3) & 1) * 4;

    auto compute_stage = [&](int st) {
#pragma unroll
        for (int ks = 0; ks < 2; ks++) {
            const int kw = ks * 8;
            uint32_t a[2][4], b[8][2];
#pragma unroll
            for (int mt = 0; mt < 2; mt++) {
                uint32_t ad = (uint32_t)__cvta_generic_to_shared(
                    &As[st][(aRow + mt * 16) * 20 + kw + aWsel]);
                ldmatrix_x4(a[mt][0], a[mt][1], a[mt][2], a[mt][3], ad);
            }
#pragma unroll
            for (int np = 0; np < 4; np++) {
                uint32_t bd = (uint32_t)__cvta_generic_to_shared(
                    &Bs[st][(bRow + np * 16) * 20 + kw + bWsel]);
                ldmatrix_x4(b[2 * np][0], b[2 * np][1], b[2 * np + 1][0], b[2 * np + 1][1], bd);
            }
#pragma unroll
            for (int mt = 0; mt < 2; mt++)
#pragma unroll
                for (int nt = 0; nt < 8; nt++)
                    mma16816(acc[mt][nt], a[mt], b[nt]);
        }
    };

    load_stage(0, 0);
    for (int q = 0; q < NQ; q++) {
        if (q + 1 < NQ) {
            load_stage((q + 1) & 1, q + 1);
            cp_wait1();
        } else {
            cp_wait0();
        }
        __syncthreads();
        compute_stage(q & 1);
        __syncthreads();
    }

    const int lr4 = lane >> 2, lk = lane & 3;
#pragma unroll
    for (int mt = 0; mt < 2; mt++) {
#pragma unroll
        for (int half = 0; half < 2; half++) {
            int r = bm + warp_m * 32 + mt * 16 + half * 8 + lr4;
            if (r >= Nr) continue;
#pragma unroll
            for (int nt = 0; nt < 8; nt++) {
                int c = bn + warp_n * 64 + nt * 8 + lk * 2;
                *reinterpret_cast<__half2*>(C + (size_t)r * 256 + c) =
                    __floats2half2_rn(acc[mt][nt][half * 2], acc[mt][nt][half * 2 + 1]);
            }
        }
    }
}

// -------------------- fused gather + BN + ReLU (fp16 h input) --------------------
// 4 nodes per 256-thr block; 64 threads/node, 4 ch/thread. Edge loop unrolled x2.
// W3MODE: reduce o @ W3 -> h3 (layer 2+3 fusion). Else write fp16 hi/lo split.
__device__ __forceinline__ float4 ld_h4(const __half* h, size_t off) {
    uint2 raw = *reinterpret_cast<const uint2*>(h + off);
    __half2 p0 = *reinterpret_cast<__half2*>(&raw.x);
    __half2 p1 = *reinterpret_cast<__half2*>(&raw.y);
    float2 f0 = __half22float2(p0);
    float2 f1 = __half22float2(p1);
    return make_float4(f0.x, f0.y, f1.x, f1.y);
}

template <bool W3MODE>
__global__ __launch_bounds__(256)
void k_gather_bn(const __half* __restrict__ h,
                 const int* __restrict__ rowptr, const int* __restrict__ src,
                 const float* __restrict__ wedge, const float* __restrict__ snorm,
                 const float* __restrict__ bb, const float* __restrict__ gg,
                 const float* __restrict__ bee, const float* __restrict__ mm,
                 const float* __restrict__ vv,
                 __half* __restrict__ hi, __half* __restrict__ lo,
                 const float* __restrict__ W3, float* __restrict__ h3, int n) {
    __shared__ float red[4][2][2];
    int i = blockIdx.x * 4 + (threadIdx.x >> 6);
    int t = threadIdx.x & 63;
    int c = t * 4;

    float4 acc = ld_h4(h, (size_t)i * HH + c);
    float s = snorm[i];
    acc.x *= s; acc.y *= s; acc.z *= s; acc.w *= s;

    int p   = rowptr[i];
    int end = rowptr[i + 1];
    for (; p + 1 < end; p += 2) {
        int   r0 = __ldg(&src[p]),     r1 = __ldg(&src[p + 1]);
        float w0 = __ldg(&wedge[p]),   w1 = __ldg(&wedge[p + 1]);
        float4 v0 = ld_h4(h, (size_t)r0 * HH + c);
        float4 v1 = ld_h4(h, (size_t)r1 * HH + c);
        acc.x += w0 * v0.x + w1 * v1.x;
        acc.y += w0 * v0.y + w1 * v1.y;
        acc.z += w0 * v0.z + w1 * v1.z;
        acc.w += w0 * v0.w + w1 * v1.w;
    }
    if (p < end) {
        int r = __ldg(&src[p]);
        float wv = __ldg(&wedge[p]);
        float4 v = ld_h4(h, (size_t)r * HH + c);
        acc.x += wv * v.x; acc.y += wv * v.y; acc.z += wv * v.z; acc.w += wv * v.w;
    }

    float4 B  = *reinterpret_cast<const float4*>(bb + c);
    float4 G  = *reinterpret_cast<const float4*>(gg + c);
    float4 BE = *reinterpret_cast<const float4*>(bee + c);
    float4 M  = *reinterpret_cast<const float4*>(mm + c);
    float4 V  = *reinterpret_cast<const float4*>(vv + c);
    float4 o;
    o.x = fmaxf((acc.x + B.x - M.x) * rsqrtf(V.x + BN_EPS) * G.x + BE.x, 0.0f);
    o.y = fmaxf((acc.y + B.y - M.y) * rsqrtf(V.y + BN_EPS) * G.y + BE.y, 0.0f);
    o.z = fmaxf((acc.z + B.z - M.z) * rsqrtf(V.z + BN_EPS) * G.z + BE.z, 0.0f);
    o.w = fmaxf((acc.w + B.w - M.w) * rsqrtf(V.w + BN_EPS) * G.w + BE.w, 0.0f);

    if (!W3MODE) {
        split4h(o, reinterpret_cast<__half2*>(hi),
                   reinterpret_cast<__half2*>(lo),
                2 * ((size_t)i * (HH / 4) + t));
    } else {
        float p0 = o.x * __ldg(&W3[(c + 0) * 2])     + o.y * __ldg(&W3[(c + 1) * 2])
                 + o.z * __ldg(&W3[(c + 2) * 2])     + o.w * __ldg(&W3[(c + 3) * 2]);
        float p1 = o.x * __ldg(&W3[(c + 0) * 2 + 1]) + o.y * __ldg(&W3[(c + 1) * 2 + 1])
                 + o.z * __ldg(&W3[(c + 2) * 2 + 1]) + o.w * __ldg(&W3[(c + 3) * 2 + 1]);
#pragma unroll
        for (int off = 16; off; off >>= 1) {
            p0 += __shfl_xor_sync(0xFFFFFFFFu, p0, off);
            p1 += __shfl_xor_sync(0xFFFFFFFFu, p1, off);
        }
        int node = threadIdx.x >> 6;
        int wIn  = (threadIdx.x >> 5) & 1;
        if ((threadIdx.x & 31) == 0) {
            red[node][wIn][0] = p0;
            red[node][wIn][1] = p1;
        }
        __syncthreads();
        if (t == 0) {
            h3[2 * i]     = red[node][0][0] + red[node][1][0];
            h3[2 * i + 1] = red[node][0][1] + red[node][1][1];
        }
    }
}

// -------------------- final gather (OUT=2) --------------------
__global__ void k_gather_out(const float* __restrict__ h3,
                             const int* __restrict__ rowptr, const int* __restrict__ src,
                             const float* __restrict__ wedge, const float* __restrict__ snorm,
                             const float* __restrict__ b3, float* __restrict__ out, int n) {
    int i = blockIdx.x * blockDim.x + threadIdx.x;
    if (i >= n) return;
    float s = snorm[i];
    float a0 = s * h3[2 * i]     + b3[0];
    float a1 = s * h3[2 * i + 1] + b3[1];
    int p = rowptr[i], end = rowptr[i + 1];
    for (; p + 1 < end; p += 2) {
        int   r0 = __ldg(&src[p]),   r1 = __ldg(&src[p + 1]);
        float w0 = __ldg(&wedge[p]), w1 = __ldg(&wedge[p + 1]);
        a0 += w0 * h3[2 * r0]     + w1 * h3[2 * r1];
        a1 += w0 * h3[2 * r0 + 1] + w1 * h3[2 * r1 + 1];
    }
    if (p < end) {
        int r = __ldg(&src[p]);
        float wv = __ldg(&wedge[p]);
        a0 += wv * h3[2 * r];
        a1 += wv * h3[2 * r + 1];
    }
    out[2 * i]     = a0;
    out[2 * i + 1] = a1;
}

// -------------------- launch --------------------
extern "C" void kernel_launch(void* const* d_in, const int* in_sizes, int n_in,
                              void* d_out, int out_size) {
    const float*        x   = (const float*)d_in[0];
    const unsigned int* eiw = (const unsigned int*)d_in[1];
    const float*        w   = (const float*)d_in[2];
    const float*        W1  = (const float*)d_in[3];
    const float*        b1  = (const float*)d_in[4];
    const float*        g1  = (const float*)d_in[5];
    const float*        be1 = (const float*)d_in[6];
    const float*        m1  = (const float*)d_in[7];
    const float*        v1  = (const float*)d_in[8];
    const float*        W2  = (const float*)d_in[9];
    const float*        b2  = (const float*)d_in[10];
    const float*        g2  = (const float*)d_in[11];
    const float*        be2 = (const float*)d_in[12];
    const float*        m2  = (const float*)d_in[13];
    const float*        v2  = (const float*)d_in[14];
    const float*        W3  = (const float*)d_in[15];
    const float*        b3  = (const float*)d_in[16];
    float* out = (float*)d_out;

    int *row, *col, *cnt, *incl, *blksum, *blkoff, *rowptr, *fill, *src;
    float *deg, *dinv, *snorm, *h3, *wedge;
    __half *h16, *hi, *lo, *Wh1, *Wh2;
    cudaGetSymbolAddress((void**)&row,    g_row);
    cudaGetSymbolAddress((void**)&col,    g_col);
    cudaGetSymbolAddress((void**)&cnt,    g_cnt);
    cudaGetSymbolAddress((void**)&incl,   g_incl);
    cudaGetSymbolAddress((void**)&blksum, g_blksum);
    cudaGetSymbolAddress((void**)&blkoff, g_blkoff);
    cudaGetSymbolAddress((void**)&rowptr, g_rowptr);
    cudaGetSymbolAddress((void**)&fill,   g_fill);
    cudaGetSymbolAddress((void**)&src,    g_src);
    cudaGetSymbolAddress((void**)&wedge,  g_wedge);
    cudaGetSymbolAddress((void**)&deg,    g_deg);
    cudaGetSymbolAddress((void**)&dinv,   g_dinv);
    cudaGetSymbolAddress((void**)&snorm,  g_snorm);
    cudaGetSymbolAddress((void**)&h16,    g_h16);
    cudaGetSymbolAddress((void**)&h3,     g_h3);
    cudaGetSymbolAddress((void**)&hi,     g_hi);
    cudaGetSymbolAddress((void**)&lo,     g_lo);
    cudaGetSymbolAddress((void**)&Wh1,    g_Wh1);
    cudaGetSymbolAddress((void**)&Wh2,    g_Wh2);

    const int n = NN, E = EE;
    dim3 t256(256);
    int nb_n  = (n + 255) / 256;
    int nb_e  = (E + 255) / 256;
    int nb_sc = (n + 511) / 512;
    int nb_g  = n / 4;
    dim3 gemm_grid((n + 127) / 128, 2);

    // preprocessing
    k_split_all<<<XB + W1B + W2B, t256>>>(x, hi, lo, W1, Wh1, W2, Wh2);
    k_init<<<nb_n, t256>>>(eiw, deg, cnt, fill, n);
    k_extract_deg<<<nb_e, t256>>>(eiw, w, row, col, deg, cnt, E);
    k_scan1<<<nb_sc, 512>>>(cnt, incl, blksum, n);
    k_scan2<<<1, 128>>>(blksum, blkoff, nb_sc);
    k_scan3_dinv<<<nb_n, t256>>>(incl, cnt, blkoff, rowptr, deg, dinv, snorm, n, E);
    k_norm_fill<<<nb_e, t256>>>(row, col, w, dinv, rowptr, fill, src, wedge, E);

    // ---- layer 1 ----
    mma_gemm<FIN><<<gemm_grid, t256>>>(hi, lo, Wh1, h16, n);
    k_gather_bn<false><<<nb_g, t256>>>(h16, rowptr, src, wedge, snorm,
                                       b1, g1, be1, m1, v1, hi, lo, nullptr, nullptr, n);

    // ---- layer 2 (+W3 fused) ----
    mma_gemm<HH><<<gemm_grid, t256>>>(hi, lo, Wh2, h16, n);
    k_gather_bn<true><<<nb_g, t256>>>(h16, rowptr, src, wedge, snorm,
                                      b2, g2, be2, m2, v2, nullptr, nullptr, W3, h3, n);

    // ---- layer 3 ----
    k_gather_out<<<nb_n, t256>>>(h3, rowptr, src, wedge, snorm, b3, out, n);
}

// round 8
// speedup vs baseline: 4.8475x; 1.1411x over previous
#include <cuda_runtime.h>
#include <cuda_fp16.h>
#include <stdint.h>

#define NN   50000
#define EE   800000
#define FIN  512
#define HH   256
#define OUTF 2
#define BN_EPS 1e-5f

// -------------------- scratch --------------------
__device__ int    g_is64;
__device__ int    g_row[EE];
__device__ int    g_col[EE];
__device__ float  g_deg[NN];
__device__ float  g_dinv[NN];
__device__ float  g_snorm[NN];
__device__ __half g_h16[(size_t)NN * HH];     // GEMM output, fp16
__device__ float  g_h3[(size_t)NN * OUTF];
__device__ __half g_hi[(size_t)NN * HH];      // layer-2 A hi (fp16 split)
__device__ __half g_lo[(size_t)NN * HH];      // layer-2 A lo
__device__ __half g_Wh1[(size_t)HH * FIN];    // W1^T fp16
__device__ __half g_Wh2[(size_t)HH * HH];     // W2^T fp16
// CSR (by destination col)
__device__ int    g_cnt[NN];
__device__ int    g_incl[NN];
__device__ int    g_blksum[128];
__device__ int    g_blkoff[128];
__device__ int    g_rowptr[NN + 1];
__device__ int    g_fill[NN];
__device__ int    g_src[EE];
__device__ float  g_wedge[EE];

// -------------------- init (+ parallel dtype detect in block 0) --------------------
__global__ void k_init(const unsigned int* __restrict__ wr,
                       float* deg, int* cnt, int* fill, int n) {
    int i = blockIdx.x * blockDim.x + threadIdx.x;
    if (i < n) { deg[i] = 1.0f; cnt[i] = 0; fill[i] = 0; }
    if (blockIdx.x == 0) {
        int ok = 1;
        for (int j = threadIdx.x; j < 2048; j += 256)
            if (wr[2 * j + 1] != 0u) ok = 0;
        int all = __syncthreads_and(ok);
        if (threadIdx.x == 0) g_is64 = all;
    }
}

__global__ void k_extract_deg(const unsigned int* __restrict__ wr,
                              const float* __restrict__ w,
                              int* __restrict__ row, int* __restrict__ col,
                              float* __restrict__ deg, int* __restrict__ cnt, int E) {
    int e = blockIdx.x * blockDim.x + threadIdx.x;
    if (e >= E) return;
    int r, c;
    if (g_is64) { r = (int)wr[2 * e]; c = (int)wr[2 * (E + e)]; }
    else        { r = (int)wr[e];     c = (int)wr[E + e]; }
    row[e] = r;
    col[e] = c;
    atomicAdd(&deg[c], w[e]);
    atomicAdd(&cnt[c], 1);
}

// -------------------- scan --------------------
__global__ void k_scan1(const int* __restrict__ cnt, int* __restrict__ incl,
                        int* __restrict__ blksum, int n) {
    __shared__ int sh[512];
    int t = threadIdx.x;
    int i = blockIdx.x * 512 + t;
    int v = (i < n) ? cnt[i] : 0;
    sh[t] = v;
    __syncthreads();
#pragma unroll
    for (int off = 1; off < 512; off <<= 1) {
        int x = (t >= off) ? sh[t - off] : 0;
        __syncthreads();
        sh[t] += x;
        __syncthreads();
    }
    if (i < n) incl[i] = sh[t];
    if (t == 511) blksum[blockIdx.x] = sh[511];
}
__global__ void k_scan2(const int* __restrict__ blksum, int* __restrict__ blkoff, int nb) {
    __shared__ int sh[128];
    int t = threadIdx.x;
    sh[t] = (t < nb) ? blksum[t] : 0;
    __syncthreads();
#pragma unroll
    for (int off = 1; off < 128; off <<= 1) {
        int x = (t >= off) ? sh[t - off] : 0;
        __syncthreads();
        sh[t] += x;
        __syncthreads();
    }
    if (t < nb) blkoff[t] = sh[t] - blksum[t];
}
__global__ void k_scan3_dinv(const int* __restrict__ incl, const int* __restrict__ cnt,
                             const int* __restrict__ blkoff, int* __restrict__ rowptr,
                             const float* __restrict__ deg, float* __restrict__ dinv,
                             float* __restrict__ snorm, int n, int E) {
    int i = blockIdx.x * blockDim.x + threadIdx.x;
    if (i < n) {
        rowptr[i] = incl[i] - cnt[i] + blkoff[i / 512];
        float d = rsqrtf(deg[i]);
        dinv[i] = d;
        snorm[i] = d * d;
    }
    if (i == 0) rowptr[n] = E;
}

__global__ void k_norm_fill(const int* __restrict__ row, const int* __restrict__ col,
                            const float* __restrict__ w, const float* __restrict__ dinv,
                            const int* __restrict__ rowptr, int* __restrict__ fill,
                            int* __restrict__ src, float* __restrict__ wedge, int E) {
    int e = blockIdx.x * blockDim.x + threadIdx.x;
    if (e >= E) return;
    int r = row[e], c = col[e];
    float nv = dinv[r] * w[e] * dinv[c];
    int p = rowptr[c] + atomicAdd(&fill[c], 1);
    src[p] = r;
    wedge[p] = nv;
}

// -------------------- weight transpose + fp16 round --------------------
__global__ void k_splitW_all(const float* __restrict__ W1, __half* __restrict__ Wh1,
                             const float* __restrict__ W2, __half* __restrict__ Wh2) {
    int b = blockIdx.x, tid = threadIdx.x;
    if (b < 512) {
        int u = b * 256 + tid;                 // [256,512]
        int n = u >> 9, k = u & 511;
        Wh1[u] = __float2half_rn(W1[(size_t)k * 256 + n]);
    } else {
        int u = (b - 512) * 256 + tid;         // [256,256]
        int n = u >> 8, k = u & 255;
        Wh2[u] = __float2half_rn(W2[(size_t)k * 256 + n]);
    }
}

// -------------------- fp32 -> fp16 hi/lo split helper --------------------
__device__ __forceinline__ void split4h(float4 v, __half2* H, __half2* L, size_t i2) {
    __half h0 = __float2half_rn(v.x);
    __half h1 = __float2half_rn(v.y);
    __half h2 = __float2half_rn(v.z);
    __half h3 = __float2half_rn(v.w);
    __half l0 = __float2half_rn(v.x - __half2float(h0));
    __half l1 = __float2half_rn(v.y - __half2float(h1));
    __half l2 = __float2half_rn(v.z - __half2float(h2));
    __half l3 = __float2half_rn(v.w - __half2float(h3));
    H[i2]     = __halves2half2(h0, h1);
    H[i2 + 1] = __halves2half2(h2, h3);
    L[i2]     = __halves2half2(l0, l1);
    L[i2 + 1] = __halves2half2(l2, l3);
}
__device__ __forceinline__ uint32_t pack2h(__half a, __half b) {
    __half2 p = __halves2half2(a, b);
    return *reinterpret_cast<uint32_t*>(&p);
}

// -------------------- mma.sync / ldmatrix / cp.async --------------------
__device__ __forceinline__ void mma16816(float* d, const uint32_t* a, const uint32_t* b) {
    asm volatile(
        "mma.sync.aligned.m16n8k16.row.col.f32.f16.f16.f32 "
        "{%0,%1,%2,%3}, {%4,%5,%6,%7}, {%8,%9}, {%0,%1,%2,%3};"
        : "+f"(d[0]), "+f"(d[1]), "+f"(d[2]), "+f"(d[3])
        : "r"(a[0]), "r"(a[1]), "r"(a[2]), "r"(a[3]), "r"(b[0]), "r"(b[1]));
}
__device__ __forceinline__ void ldmatrix_x4(uint32_t& r0, uint32_t& r1, uint32_t& r2,
                                            uint32_t& r3, uint32_t saddr) {
    asm volatile("ldmatrix.sync.aligned.m8n8.x4.shared.b16 {%0,%1,%2,%3}, [%4];"
                 : "=r"(r0), "=r"(r1), "=r"(r2), "=r"(r3) : "r"(saddr));
}
__device__ __forceinline__ void cp_async16(uint32_t saddr, const void* gaddr, int src_sz) {
    asm volatile("cp.async.cg.shared.global [%0], [%1], 16, %2;"
                 :: "r"(saddr), "l"(gaddr), "r"(src_sz));
}
__device__ __forceinline__ void cp_commit() { asm volatile("cp.async.commit_group;"); }
__device__ __forceinline__ void cp_wait1()  { asm volatile("cp.async.wait_group 1;"); }
__device__ __forceinline__ void cp_wait0()  { asm volatile("cp.async.wait_group 0;"); }

// -------------------- 2-term fp16 HMMA GEMM, BN=256 (single A read) --------------------
// C[Nr,256] = (Ahi+Alo) * B^T.  AFP32: A tiles split in-kernel from fp32 source.
// BM=128, BN=256, BK=32; 256 thr = 8 warps (2 M x 4 N), warp tile 64x64.
// Dynamic smem 80KB: Bs[2][5120] | Ah[2][2560] | Al[2][2560]  (20-word padded rows)
template <int K, bool AFP32>
__global__ __launch_bounds__(256, 1)
void mma_gemm(const float* __restrict__ Af,
              const __half* __restrict__ Ahi, const __half* __restrict__ Alo,
              const __half* __restrict__ Bh,
              __half* __restrict__ C, int Nr) {
    constexpr int NCH = K / 32;
    extern __shared__ char smem[];
    uint32_t* Bs = reinterpret_cast<uint32_t*>(smem);            // 2 x 5120
    uint32_t* Ah = reinterpret_cast<uint32_t*>(smem + 40960);    // 2 x 2560
    uint32_t* Al = reinterpret_cast<uint32_t*>(smem + 61440);    // 2 x 2560

    const int tid  = threadIdx.x;
    const int lane = tid & 31;
    const int wid  = tid >> 5;
    const int warp_m = wid & 1;        // 2 warps along M (64 rows)
    const int warp_n = wid >> 1;       // 4 warps along N (64 cols)
    const int bm = blockIdx.x * 128;

    float acc[4][8][4];
#pragma unroll
    for (int mt = 0; mt < 4; mt++)
#pragma unroll
        for (int nt = 0; nt < 8; nt++)
#pragma unroll
            for (int q = 0; q < 4; q++) acc[mt][nt][q] = 0.0f;

    float4 fa[2][2];   // A fp32 reg buffer (AFP32 path)

    auto loadAf = [&](int q) {
        const int kt = q * 32;
#pragma unroll
        for (int i = 0; i < 2; i++) {
            int u = tid + i * 256;
            int r = u >> 2, k8 = u & 3;
            int gr = bm + r;
            if (gr < Nr) {
                const float4* p = reinterpret_cast<const float4*>(
                    Af + (size_t)gr * K + kt + k8 * 8);
                fa[i][0] = p[0];
                fa[i][1] = p[1];
            } else {
                fa[i][0] = make_float4(0.f, 0.f, 0.f, 0.f);
                fa[i][1] = make_float4(0.f, 0.f, 0.f, 0.f);
            }
        }
    };
    auto storeAf = [&](int st) {
#pragma unroll
        for (int i = 0; i < 2; i++) {
            int u = tid + i * 256;
            int r = u >> 2, k8 = u & 3;
            float vs[8] = {fa[i][0].x, fa[i][0].y, fa[i][0].z, fa[i][0].w,
                           fa[i][1].x, fa[i][1].y, fa[i][1].z, fa[i][1].w};
            uint32_t hw[4], lw[4];
#pragma unroll
            for (int j = 0; j < 4; j++) {
                __half h0 = __float2half_rn(vs[2 * j]);
                __half h1 = __float2half_rn(vs[2 * j + 1]);
                __half l0 = __float2half_rn(vs[2 * j]     - __half2float(h0));
                __half l1 = __float2half_rn(vs[2 * j + 1] - __half2float(h1));
                hw[j] = pack2h(h0, h1);
                lw[j] = pack2h(l0, l1);
            }
            int woff = st * 2560 + r * 20 + k8 * 4;
            *reinterpret_cast<uint4*>(&Ah[woff]) = make_uint4(hw[0], hw[1], hw[2], hw[3]);
            *reinterpret_cast<uint4*>(&Al[woff]) = make_uint4(lw[0], lw[1], lw[2], lw[3]);
        }
    };
    auto asyncA16 = [&](int st, int q) {   // fp16 hi/lo path (layer 2)
        const int kt = q * 32;
#pragma unroll
        for (int i = 0; i < 2; i++) {
            int u = tid + i * 256;
            int r = u >> 2, k8 = u & 3;
            int gr = bm + r;
            int ok = (gr < Nr);
            size_t srcoff = (size_t)(ok ? gr : 0) * K + kt + k8 * 8;
            int woff = st * 2560 + r * 20 + k8 * 4;
            cp_async16((uint32_t)__cvta_generic_to_shared(&Ah[woff]), Ahi + srcoff, ok ? 16 : 0);
            cp_async16((uint32_t)__cvta_generic_to_shared(&Al[woff]), Alo + srcoff, ok ? 16 : 0);
        }
    };
    auto asyncB = [&](int st, int q) {
        const int kt = q * 32;
#pragma unroll
        for (int i = 0; i < 4; i++) {
            int u = tid + i * 256;
            int r = u >> 2, k8 = u & 3;
            int woff = st * 5120 + r * 20 + k8 * 4;
            cp_async16((uint32_t)__cvta_generic_to_shared(&Bs[woff]),
                       Bh + (size_t)r * K + kt + k8 * 8, 16);
        }
    };

    const int aRow  = warp_m * 64 + (lane & 7) + ((lane >> 3) & 1) * 8;
    const int aWsel = (lane >> 4) * 4;
    const int bRow  = warp_n * 64 + (lane & 7) + (lane >> 4) * 8;
    const int bWsel = ((lane >> 3) & 1) * 4;

    auto compute = [&](int st, const uint32_t* Asrc) {
#pragma unroll
        for (int ks = 0; ks < 2; ks++) {
            const int kw = ks * 8;
            uint32_t a[4][4], b[8][2];
#pragma unroll
            for (int mt = 0; mt < 4; mt++) {
                uint32_t ad = (uint32_t)__cvta_generic_to_shared(
                    &Asrc[st * 2560 + (aRow + mt * 16) * 20 + kw + aWsel]);
                ldmatrix_x4(a[mt][0], a[mt][1], a[mt][2], a[mt][3], ad);
            }
#pragma unroll
            for (int np = 0; np < 4; np++) {
                uint32_t bd = (uint32_t)__cvta_generic_to_shared(
                    &Bs[st * 5120 + (bRow + np * 16) * 20 + kw + bWsel]);
                ldmatrix_x4(b[2 * np][0], b[2 * np][1], b[2 * np + 1][0], b[2 * np + 1][1], bd);
            }
#pragma unroll
            for (int mt = 0; mt < 4; mt++)
#pragma unroll
                for (int nt = 0; nt < 8; nt++)
                    mma16816(acc[mt][nt], a[mt], b[nt]);
        }
    };

    // prologue
    if (AFP32) loadAf(0); else asyncA16(0, 0);
    asyncB(0, 0);
    cp_commit();
    if (AFP32) storeAf(0);

    for (int q = 0; q < NCH; q++) {
        if (q + 1 < NCH) {
            if (AFP32) loadAf(q + 1); else asyncA16((q + 1) & 1, q + 1);
            asyncB((q + 1) & 1, q + 1);
            cp_commit();
            cp_wait1();
        } else {
            cp_wait0();
        }
        __syncthreads();
        compute(q & 1, Ah);
        compute(q & 1, Al);
        if (AFP32 && q + 1 < NCH) storeAf((q + 1) & 1);
        __syncthreads();
    }

    // epilogue: C fp16
    const int lr4 = lane >> 2, lk = lane & 3;
#pragma unroll
    for (int mt = 0; mt < 4; mt++) {
#pragma unroll
        for (int half = 0; half < 2; half++) {
            int r = bm + warp_m * 64 + mt * 16 + half * 8 + lr4;
            if (r >= Nr) continue;
#pragma unroll
            for (int nt = 0; nt < 8; nt++) {
                int c = warp_n * 64 + nt * 8 + lk * 2;
                *reinterpret_cast<__half2*>(C + (size_t)r * 256 + c) =
                    __floats2half2_rn(acc[mt][nt][half * 2], acc[mt][nt][half * 2 + 1]);
            }
        }
    }
}

// -------------------- fused gather + BN + ReLU (fp16 h input) --------------------
__device__ __forceinline__ float4 ld_h4(const __half* h, size_t off) {
    uint2 raw = *reinterpret_cast<const uint2*>(h + off);
    __half2 p0 = *reinterpret_cast<__half2*>(&raw.x);
    __half2 p1 = *reinterpret_cast<__half2*>(&raw.y);
    float2 f0 = __half22float2(p0);
    float2 f1 = __half22float2(p1);
    return make_float4(f0.x, f0.y, f1.x, f1.y);
}

template <bool W3MODE>
__global__ __launch_bounds__(256)
void k_gather_bn(const __half* __restrict__ h,
                 const int* __restrict__ rowptr, const int* __restrict__ src,
                 const float* __restrict__ wedge, const float* __restrict__ snorm,
                 const float* __restrict__ bb, const float* __restrict__ gg,
                 const float* __restrict__ bee, const float* __restrict__ mm,
                 const float* __restrict__ vv,
                 __half* __restrict__ hi, __half* __restrict__ lo,
                 const float* __restrict__ W3, float* __restrict__ h3, int n) {
    __shared__ float red[4][2][2];
    int i = blockIdx.x * 4 + (threadIdx.x >> 6);
    int t = threadIdx.x & 63;
    int c = t * 4;

    float4 acc = ld_h4(h, (size_t)i * HH + c);
    float s = snorm[i];
    acc.x *= s; acc.y *= s; acc.z *= s; acc.w *= s;

    int p   = rowptr[i];
    int end = rowptr[i + 1];
    for (; p + 1 < end; p += 2) {
        int   r0 = __ldg(&src[p]),     r1 = __ldg(&src[p + 1]);
        float w0 = __ldg(&wedge[p]),   w1 = __ldg(&wedge[p + 1]);
        float4 v0 = ld_h4(h, (size_t)r0 * HH + c);
        float4 v1 = ld_h4(h, (size_t)r1 * HH + c);
        acc.x += w0 * v0.x + w1 * v1.x;
        acc.y += w0 * v0.y + w1 * v1.y;
        acc.z += w0 * v0.z + w1 * v1.z;
        acc.w += w0 * v0.w + w1 * v1.w;
    }
    if (p < end) {
        int r = __ldg(&src[p]);
        float wv = __ldg(&wedge[p]);
        float4 v = ld_h4(h, (size_t)r * HH + c);
        acc.x += wv * v.x; acc.y += wv * v.y; acc.z += wv * v.z; acc.w += wv * v.w;
    }

    float4 B  = *reinterpret_cast<const float4*>(bb + c);
    float4 G  = *reinterpret_cast<const float4*>(gg + c);
    float4 BE = *reinterpret_cast<const float4*>(bee + c);
    float4 M  = *reinterpret_cast<const float4*>(mm + c);
    float4 V  = *reinterpret_cast<const float4*>(vv + c);
    float4 o;
    o.x = fmaxf((acc.x + B.x - M.x) * rsqrtf(V.x + BN_EPS) * G.x + BE.x, 0.0f);
    o.y = fmaxf((acc.y + B.y - M.y) * rsqrtf(V.y + BN_EPS) * G.y + BE.y, 0.0f);
    o.z = fmaxf((acc.z + B.z - M.z) * rsqrtf(V.z + BN_EPS) * G.z + BE.z, 0.0f);
    o.w = fmaxf((acc.w + B.w - M.w) * rsqrtf(V.w + BN_EPS) * G.w + BE.w, 0.0f);

    if (!W3MODE) {
        split4h(o, reinterpret_cast<__half2*>(hi),
                   reinterpret_cast<__half2*>(lo),
                2 * ((size_t)i * (HH / 4) + t));
    } else {
        float p0 = o.x * __ldg(&W3[(c + 0) * 2])     + o.y * __ldg(&W3[(c + 1) * 2])
                 + o.z * __ldg(&W3[(c + 2) * 2])     + o.w * __ldg(&W3[(c + 3) * 2]);
        float p1 = o.x * __ldg(&W3[(c + 0) * 2 + 1]) + o.y * __ldg(&W3[(c + 1) * 2 + 1])
                 + o.z * __ldg(&W3[(c + 2) * 2 + 1]) + o.w * __ldg(&W3[(c + 3) * 2 + 1]);
#pragma unroll
        for (int off = 16; off; off >>= 1) {
            p0 += __shfl_xor_sync(0xFFFFFFFFu, p0, off);
            p1 += __shfl_xor_sync(0xFFFFFFFFu, p1, off);
        }
        int node = threadIdx.x >> 6;
        int wIn  = (threadIdx.x >> 5) & 1;
        if ((threadIdx.x & 31) == 0) {
            red[node][wIn][0] = p0;
            red[node][wIn][1] = p1;
        }
        __syncthreads();
        if (t == 0) {
            h3[2 * i]     = red[node][0][0] + red[node][1][0];
            h3[2 * i + 1] = red[node][0][1] + red[node][1][1];
        }
    }
}

// -------------------- final gather (OUT=2) --------------------
__global__ void k_gather_out(const float* __restrict__ h3,
                             const int* __restrict__ rowptr, const int* __restrict__ src,
                             const float* __restrict__ wedge, const float* __restrict__ snorm,
                             const float* __restrict__ b3, float* __restrict__ out, int n) {
    int i = blockIdx.x * blockDim.x + threadIdx.x;
    if (i >= n) return;
    float s = snorm[i];
    float a0 = s * h3[2 * i]     + b3[0];
    float a1 = s * h3[2 * i + 1] + b3[1];
    int p = rowptr[i], end = rowptr[i + 1];
    for (; p + 1 < end; p += 2) {
        int   r0 = __ldg(&src[p]),   r1 = __ldg(&src[p + 1]);
        float w0 = __ldg(&wedge[p]), w1 = __ldg(&wedge[p + 1]);
        a0 += w0 * h3[2 * r0]     + w1 * h3[2 * r1];
        a1 += w0 * h3[2 * r0 + 1] + w1 * h3[2 * r1 + 1];
    }
    if (p < end) {
        int r = __ldg(&src[p]);
        float wv = __ldg(&wedge[p]);
        a0 += wv * h3[2 * r];
        a1 += wv * h3[2 * r + 1];
    }
    out[2 * i]     = a0;
    out[2 * i + 1] = a1;
}

// -------------------- launch --------------------
extern "C" void kernel_launch(void* const* d_in, const int* in_sizes, int n_in,
                              void* d_out, int out_size) {
    const float*        x   = (const float*)d_in[0];
    const unsigned int* eiw = (const unsigned int*)d_in[1];
    const float*        w   = (const float*)d_in[2];
    const float*        W1  = (const float*)d_in[3];
    const float*        b1  = (const float*)d_in[4];
    const float*        g1  = (const float*)d_in[5];
    const float*        be1 = (const float*)d_in[6];
    const float*        m1  = (const float*)d_in[7];
    const float*        v1  = (const float*)d_in[8];
    const float*        W2  = (const float*)d_in[9];
    const float*        b2  = (const float*)d_in[10];
    const float*        g2  = (const float*)d_in[11];
    const float*        be2 = (const float*)d_in[12];
    const float*        m2  = (const float*)d_in[13];
    const float*        v2  = (const float*)d_in[14];
    const float*        W3  = (const float*)d_in[15];
    const float*        b3  = (const float*)d_in[16];
    float* out = (float*)d_out;

    int *row, *col, *cnt, *incl, *blksum, *blkoff, *rowptr, *fill, *src;
    float *deg, *dinv, *snorm, *h3, *wedge;
    __half *h16, *hi, *lo, *Wh1, *Wh2;
    cudaGetSymbolAddress((void**)&row,    g_row);
    cudaGetSymbolAddress((void**)&col,    g_col);
    cudaGetSymbolAddress((void**)&cnt,    g_cnt);
    cudaGetSymbolAddress((void**)&incl,   g_incl);
    cudaGetSymbolAddress((void**)&blksum, g_blksum);
    cudaGetSymbolAddress((void**)&blkoff, g_blkoff);
    cudaGetSymbolAddress((void**)&rowptr, g_rowptr);
    cudaGetSymbolAddress((void**)&fill,   g_fill);
    cudaGetSymbolAddress((void**)&src,    g_src);
    cudaGetSymbolAddress((void**)&wedge,  g_wedge);
    cudaGetSymbolAddress((void**)&deg,    g_deg);
    cudaGetSymbolAddress((void**)&dinv,   g_dinv);
    cudaGetSymbolAddress((void**)&snorm,  g_snorm);
    cudaGetSymbolAddress((void**)&h16,    g_h16);
    cudaGetSymbolAddress((void**)&h3,     g_h3);
    cudaGetSymbolAddress((void**)&hi,     g_hi);
    cudaGetSymbolAddress((void**)&lo,     g_lo);
    cudaGetSymbolAddress((void**)&Wh1,    g_Wh1);
    cudaGetSymbolAddress((void**)&Wh2,    g_Wh2);

    const int n = NN, E = EE;
    const int SMEM_BYTES = 81920;
    cudaFuncSetAttribute(mma_gemm<FIN, true>,
                         cudaFuncAttributeMaxDynamicSharedMemorySize, SMEM_BYTES);
    cudaFuncSetAttribute(mma_gemm<HH, false>,
                         cudaFuncAttributeMaxDynamicSharedMemorySize, SMEM_BYTES);

    dim3 t256(256);
    int nb_n  = (n + 255) / 256;
    int nb_e  = (E + 255) / 256;
    int nb_sc = (n + 511) / 512;
    int nb_g  = n / 4;
    int gemm_grid = (n + 127) / 128;

    // preprocessing
    k_splitW_all<<<512 + 256, t256>>>(W1, Wh1, W2, Wh2);
    k_init<<<nb_n, t256>>>(eiw, deg, cnt, fill, n);
    k_extract_deg<<<nb_e, t256>>>(eiw, w, row, col, deg, cnt, E);
    k_scan1<<<nb_sc, 512>>>(cnt, incl, blksum, n);
    k_scan2<<<1, 128>>>(blksum, blkoff, nb_sc);
    k_scan3_dinv<<<nb_n, t256>>>(incl, cnt, blkoff, rowptr, deg, dinv, snorm, n, E);
    k_norm_fill<<<nb_e, t256>>>(row, col, w, dinv, rowptr, fill, src, wedge, E);

    // ---- layer 1 (A = x fp32, split in-kernel) ----
    mma_gemm<FIN, true><<<gemm_grid, t256, SMEM_BYTES>>>(x, nullptr, nullptr, Wh1, h16, n);
    k_gather_bn<false><<<nb_g, t256>>>(h16, rowptr, src, wedge, snorm,
                                       b1, g1, be1, m1, v1, hi, lo, nullptr, nullptr, n);

    // ---- layer 2 (+W3 fused) ----
    mma_gemm<HH, false><<<gemm_grid, t256, SMEM_BYTES>>>(nullptr, hi, lo, Wh2, h16, n);
    k_gather_bn<true><<<nb_g, t256>>>(h16, rowptr, src, wedge, snorm,
                                      b2, g2, be2, m2, v2, nullptr, nullptr, W3, h3, n);

    // ---- layer 3 ----
    k_gather_out<<<nb_n, t256>>>(h3, rowptr, src, wedge, snorm, b3, out, n);
}

// round 10
// speedup vs baseline: 4.8908x; 1.0089x over previous
#include <cuda_runtime.h>
#include <cuda_fp16.h>
#include <stdint.h>

#define NN   50000
#define EE   800000
#define FIN  512
#define HH   256
#define OUTF 2
#define BN_EPS 1e-5f

// -------------------- scratch --------------------
__device__ int    g_is64;
__device__ int    g_row[EE];
__device__ int    g_col[EE];
__device__ float  g_deg[NN];
__device__ float  g_dinv[NN];
__device__ float  g_snorm[NN];
__device__ __half g_h16[(size_t)NN * HH];     // GEMM output, fp16
__device__ float  g_h3[(size_t)NN * OUTF];
__device__ __half g_hi[(size_t)NN * HH];      // layer-2 A (single fp16)
__device__ __half g_Wh1[(size_t)HH * FIN];    // W1^T fp16
__device__ __half g_Wh2[(size_t)HH * HH];     // W2^T fp16
// CSR (by destination col)
__device__ int    g_cnt[NN];
__device__ int    g_incl[NN];
__device__ int    g_blksum[128];
__device__ int    g_blkoff[128];
__device__ int    g_rowptr[NN + 1];
__device__ int    g_fill[NN];
__device__ int    g_src[EE];
__device__ float  g_wedge[EE];

// -------------------- fused pre: W transpose/round + init + dtype detect --------------------
__global__ void k_pre(const float* __restrict__ W1, __half* __restrict__ Wh1,
                      const float* __restrict__ W2, __half* __restrict__ Wh2,
                      const unsigned int* __restrict__ wr,
                      float* __restrict__ deg, int* __restrict__ cnt,
                      int* __restrict__ fill, int n) {
    int b = blockIdx.x, tid = threadIdx.x;
    if (b < 512) {
        int u = b * 256 + tid;                 // [256,512]
        int nn = u >> 9, k = u & 511;
        Wh1[u] = __float2half_rn(W1[(size_t)k * 256 + nn]);
    } else if (b < 768) {
        int u = (b - 512) * 256 + tid;         // [256,256]
        int nn = u >> 8, k = u & 255;
        Wh2[u] = __float2half_rn(W2[(size_t)k * 256 + nn]);
    } else {
        int i = (b - 768) * 256 + tid;
        if (i < n) { deg[i] = 1.0f; cnt[i] = 0; fill[i] = 0; }
        if (b == 768) {
            int ok = 1;
            for (int j = tid; j < 2048; j += 256)
                if (wr[2 * j + 1] != 0u) ok = 0;
            int all = __syncthreads_and(ok);
            if (tid == 0) g_is64 = all;
        }
    }
}

__global__ void k_extract_deg(const unsigned int* __restrict__ wr,
                              const float* __restrict__ w,
                              int* __restrict__ row, int* __restrict__ col,
                              float* __restrict__ deg, int* __restrict__ cnt, int E) {
    int e = blockIdx.x * blockDim.x + threadIdx.x;
    if (e >= E) return;
    int r, c;
    if (g_is64) { r = (int)wr[2 * e]; c = (int)wr[2 * (E + e)]; }
    else        { r = (int)wr[e];     c = (int)wr[E + e]; }
    row[e] = r;
    col[e] = c;
    atomicAdd(&deg[c], w[e]);
    atomicAdd(&cnt[c], 1);
}

// -------------------- scan --------------------
__global__ void k_scan1(const int* __restrict__ cnt, int* __restrict__ incl,
                        int* __restrict__ blksum, int n) {
    __shared__ int sh[512];
    int t = threadIdx.x;
    int i = blockIdx.x * 512 + t;
    int v = (i < n) ? cnt[i] : 0;
    sh[t] = v;
    __syncthreads();
#pragma unroll
    for (int off = 1; off < 512; off <<= 1) {
        int x = (t >= off) ? sh[t - off] : 0;
        __syncthreads();
        sh[t] += x;
        __syncthreads();
    }
    if (i < n) incl[i] = sh[t];
    if (t == 511) blksum[blockIdx.x] = sh[511];
}
__global__ void k_scan2(const int* __restrict__ blksum, int* __restrict__ blkoff, int nb) {
    __shared__ int sh[128];
    int t = threadIdx.x;
    sh[t] = (t < nb) ? blksum[t] : 0;
    __syncthreads();
#pragma unroll
    for (int off = 1; off < 128; off <<= 1) {
        int x = (t >= off) ? sh[t - off] : 0;
        __syncthreads();
        sh[t] += x;
        __syncthreads();
    }
    if (t < nb) blkoff[t] = sh[t] - blksum[t];
}
__global__ void k_scan3_dinv(const int* __restrict__ incl, const int* __restrict__ cnt,
                             const int* __restrict__ blkoff, int* __restrict__ rowptr,
                             const float* __restrict__ deg, float* __restrict__ dinv,
                             float* __restrict__ snorm, int n, int E) {
    int i = blockIdx.x * blockDim.x + threadIdx.x;
    if (i < n) {
        rowptr[i] = incl[i] - cnt[i] + blkoff[i / 512];
        float d = rsqrtf(deg[i]);
        dinv[i] = d;
        snorm[i] = d * d;
    }
    if (i == 0) rowptr[n] = E;
}

__global__ void k_norm_fill(const int* __restrict__ row, const int* __restrict__ col,
                            const float* __restrict__ w, const float* __restrict__ dinv,
                            const int* __restrict__ rowptr, int* __restrict__ fill,
                            int* __restrict__ src, float* __restrict__ wedge, int E) {
    int e = blockIdx.x * blockDim.x + threadIdx.x;
    if (e >= E) return;
    int r = row[e], c = col[e];
    float nv = dinv[r] * w[e] * dinv[c];
    int p = rowptr[c] + atomicAdd(&fill[c], 1);
    src[p] = r;
    wedge[p] = nv;
}

// -------------------- helpers --------------------
__device__ __forceinline__ uint32_t pack2h(__half a, __half b) {
    __half2 p = __halves2half2(a, b);
    return *reinterpret_cast<uint32_t*>(&p);
}
__device__ __forceinline__ void h8_to_f8(uint4 raw, float* f) {
    __half2* p = reinterpret_cast<__half2*>(&raw);
#pragma unroll
    for (int j = 0; j < 4; j++) {
        float2 t = __half22float2(p[j]);
        f[2 * j] = t.x;
        f[2 * j + 1] = t.y;
    }
}

__device__ __forceinline__ void mma16816(float* d, const uint32_t* a, const uint32_t* b) {
    asm volatile(
        "mma.sync.aligned.m16n8k16.row.col.f32.f16.f16.f32 "
        "{%0,%1,%2,%3}, {%4,%5,%6,%7}, {%8,%9}, {%0,%1,%2,%3};"
        : "+f"(d[0]), "+f"(d[1]), "+f"(d[2]), "+f"(d[3])
        : "r"(a[0]), "r"(a[1]), "r"(a[2]), "r"(a[3]), "r"(b[0]), "r"(b[1]));
}
__device__ __forceinline__ void ldmatrix_x4(uint32_t& r0, uint32_t& r1, uint32_t& r2,
                                            uint32_t& r3, uint32_t saddr) {
    asm volatile("ldmatrix.sync.aligned.m8n8.x4.shared.b16 {%0,%1,%2,%3}, [%4];"
                 : "=r"(r0), "=r"(r1), "=r"(r2), "=r"(r3) : "r"(saddr));
}
__device__ __forceinline__ void cp_async16(uint32_t saddr, const void* gaddr, int src_sz) {
    asm volatile("cp.async.cg.shared.global [%0], [%1], 16, %2;"
                 :: "r"(saddr), "l"(gaddr), "r"(src_sz));
}
__device__ __forceinline__ void cp_commit() { asm volatile("cp.async.commit_group;"); }
__device__ __forceinline__ void cp_wait1()  { asm volatile("cp.async.wait_group 1;"); }
__device__ __forceinline__ void cp_wait0()  { asm volatile("cp.async.wait_group 0;"); }

// -------------------- fp16 HMMA GEMM, BN=256 --------------------
// AFP32=true : A fp32, split hi/lo in-kernel, 2-term (layer 1)
// AFP32=false: A fp16 single-term (layer 2)
// BM=128, BN=256, BK=32; 256 thr = 8 warps (2 M x 4 N), warp tile 64x64.
// smem: Bs[2][5120] @0 | Ah[2][2560] @40960 | Al[2][2560] @61440 (AFP32 only)
template <int K, bool AFP32>
__global__ __launch_bounds__(256, 1)
void mma_gemm(const float* __restrict__ Af, const __half* __restrict__ Ahalf,
              const __half* __restrict__ Bh,
              __half* __restrict__ C, int Nr) {
    constexpr int NCH = K / 32;
    extern __shared__ char smem[];
    uint32_t* Bs = reinterpret_cast<uint32_t*>(smem);
    uint32_t* Ah = reinterpret_cast<uint32_t*>(smem + 40960);
    uint32_t* Al = reinterpret_cast<uint32_t*>(smem + 61440);

    const int tid  = threadIdx.x;
    const int lane = tid & 31;
    const int wid  = tid >> 5;
    const int warp_m = wid & 1;
    const int warp_n = wid >> 1;
    const int bm = blockIdx.x * 128;

    float acc[4][8][4];
#pragma unroll
    for (int mt = 0; mt < 4; mt++)
#pragma unroll
        for (int nt = 0; nt < 8; nt++)
#pragma unroll
            for (int q = 0; q < 4; q++) acc[mt][nt][q] = 0.0f;

    float4 fa[2][2];

    auto loadAf = [&](int q) {
        const int kt = q * 32;
#pragma unroll
        for (int i = 0; i < 2; i++) {
            int u = tid + i * 256;
            int r = u >> 2, k8 = u & 3;
            int gr = bm + r;
            if (gr < Nr) {
                const float4* p = reinterpret_cast<const float4*>(
                    Af + (size_t)gr * K + kt + k8 * 8);
                fa[i][0] = p[0];
                fa[i][1] = p[1];
            } else {
                fa[i][0] = make_float4(0.f, 0.f, 0.f, 0.f);
                fa[i][1] = make_float4(0.f, 0.f, 0.f, 0.f);
            }
        }
    };
    auto storeAf = [&](int st) {
#pragma unroll
        for (int i = 0; i < 2; i++) {
            int u = tid + i * 256;
            int r = u >> 2, k8 = u & 3;
            float vs[8] = {fa[i][0].x, fa[i][0].y, fa[i][0].z, fa[i][0].w,
                           fa[i][1].x, fa[i][1].y, fa[i][1].z, fa[i][1].w};
            uint32_t hw[4], lw[4];
#pragma unroll
            for (int j = 0; j < 4; j++) {
                __half h0 = __float2half_rn(vs[2 * j]);
                __half h1 = __float2half_rn(vs[2 * j + 1]);
                __half l0 = __float2half_rn(vs[2 * j]     - __half2float(h0));
                __half l1 = __float2half_rn(vs[2 * j + 1] - __half2float(h1));
                hw[j] = pack2h(h0, h1);
                lw[j] = pack2h(l0, l1);
            }
            int woff = st * 2560 + r * 20 + k8 * 4;
            *reinterpret_cast<uint4*>(&Ah[woff]) = make_uint4(hw[0], hw[1], hw[2], hw[3]);
            *reinterpret_cast<uint4*>(&Al[woff]) = make_uint4(lw[0], lw[1], lw[2], lw[3]);
        }
    };
    auto asyncA16 = [&](int st, int q) {
        const int kt = q * 32;
#pragma unroll
        for (int i = 0; i < 2; i++) {
            int u = tid + i * 256;
            int r = u >> 2, k8 = u & 3;
            int gr = bm + r;
            int ok = (gr < Nr);
            size_t srcoff = (size_t)(ok ? gr : 0) * K + kt + k8 * 8;
            int woff = st * 2560 + r * 20 + k8 * 4;
            cp_async16((uint32_t)__cvta_generic_to_shared(&Ah[woff]), Ahalf + srcoff, ok ? 16 : 0);
        }
    };
    auto asyncB = [&](int st, int q) {
        const int kt = q * 32;
#pragma unroll
        for (int i = 0; i < 4; i++) {
            int u = tid + i * 256;
            int r = u >> 2, k8 = u & 3;
            int woff = st * 5120 + r * 20 + k8 * 4;
            cp_async16((uint32_t)__cvta_generic_to_shared(&Bs[woff]),
                       Bh + (size_t)r * K + kt + k8 * 8, 16);
        }
    };

    const int aRow  = warp_m * 64 + (lane & 7) + ((lane >> 3) & 1) * 8;
    const int aWsel = (lane >> 4) * 4;
    const int bRow  = warp_n * 64 + (lane & 7) + (lane >> 4) * 8;
    const int bWsel = ((lane >> 3) & 1) * 4;

    auto compute = [&](int st, const uint32_t* Asrc) {
#pragma unroll
        for (int ks = 0; ks < 2; ks++) {
            const int kw = ks * 8;
            uint32_t a[4][4], b[8][2];
#pragma unroll
            for (int mt = 0; mt < 4; mt++) {
                uint32_t ad = (uint32_t)__cvta_generic_to_shared(
                    &Asrc[st * 2560 + (aRow + mt * 16) * 20 + kw + aWsel]);
                ldmatrix_x4(a[mt][0], a[mt][1], a[mt][2], a[mt][3], ad);
            }
#pragma unroll
            for (int np = 0; np < 4; np++) {
                uint32_t bd = (uint32_t)__cvta_generic_to_shared(
                    &Bs[st * 5120 + (bRow + np * 16) * 20 + kw + bWsel]);
                ldmatrix_x4(b[2 * np][0], b[2 * np][1], b[2 * np + 1][0], b[2 * np + 1][1], bd);
            }
#pragma unroll
            for (int mt = 0; mt < 4; mt++)
#pragma unroll
                for (int nt = 0; nt < 8; nt++)
                    mma16816(acc[mt][nt], a[mt], b[nt]);
        }
    };

    if (AFP32) loadAf(0); else asyncA16(0, 0);
    asyncB(0, 0);
    cp_commit();
    if (AFP32) storeAf(0);

    for (int q = 0; q < NCH; q++) {
        if (q + 1 < NCH) {
            if (AFP32) loadAf(q + 1); else asyncA16((q + 1) & 1, q + 1);
            asyncB((q + 1) & 1, q + 1);
            cp_commit();
            cp_wait1();
        } else {
            cp_wait0();
        }
        __syncthreads();
        compute(q & 1, Ah);
        if (AFP32) {
            compute(q & 1, Al);
            if (q + 1 < NCH) storeAf((q + 1) & 1);
        }
        __syncthreads();
    }

    const int lr4 = lane >> 2, lk = lane & 3;
#pragma unroll
    for (int mt = 0; mt < 4; mt++) {
#pragma unroll
        for (int half = 0; half < 2; half++) {
            int r = bm + warp_m * 64 + mt * 16 + half * 8 + lr4;
            if (r >= Nr) continue;
#pragma unroll
            for (int nt = 0; nt < 8; nt++) {
                int c = warp_n * 64 + nt * 8 + lk * 2;
                *reinterpret_cast<__half2*>(C + (size_t)r * 256 + c) =
                    __floats2half2_rn(acc[mt][nt][half * 2], acc[mt][nt][half * 2 + 1]);
            }
        }
    }
}

// -------------------- fused gather + BN + ReLU (warp per node) --------------------
template <bool W3MODE>
__global__ __launch_bounds__(256)
void k_gather_bn(const __half* __restrict__ h,
                 const int* __restrict__ rowptr, const int* __restrict__ src,
                 const float* __restrict__ wedge, const float* __restrict__ snorm,
                 const float* __restrict__ bb, const float* __restrict__ gg,
                 const float* __restrict__ bee, const float* __restrict__ mm,
                 const float* __restrict__ vv,
                 __half* __restrict__ hnext,
                 const float* __restrict__ W3, float* __restrict__ h3, int n) {
    int i = blockIdx.x * 8 + (threadIdx.x >> 5);
    int lane = threadIdx.x & 31;
    int c = lane * 8;

    float acc[8], f[8];
    h8_to_f8(*reinterpret_cast<const uint4*>(h + (size_t)i * HH + c), f);
    float s = snorm[i];
#pragma unroll
    for (int j = 0; j < 8; j++) acc[j] = f[j] * s;

    int p   = rowptr[i];
    int end = rowptr[i + 1];
    for (; p + 1 < end; p += 2) {
        int   r0 = __ldg(&src[p]),   r1 = __ldg(&src[p + 1]);
        float w0 = __ldg(&wedge[p]), w1 = __ldg(&wedge[p + 1]);
        float f0[8], f1[8];
        h8_to_f8(*reinterpret_cast<const uint4*>(h + (size_t)r0 * HH + c), f0);
        h8_to_f8(*reinterpret_cast<const uint4*>(h + (size_t)r1 * HH + c), f1);
#pragma unroll
        for (int j = 0; j < 8; j++) acc[j] += w0 * f0[j] + w1 * f1[j];
    }
    if (p < end) {
        int r = __ldg(&src[p]);
        float wv = __ldg(&wedge[p]);
        float f0[8];
        h8_to_f8(*reinterpret_cast<const uint4*>(h + (size_t)r * HH + c), f0);
#pragma unroll
        for (int j = 0; j < 8; j++) acc[j] += wv * f0[j];
    }

    float o[8];
#pragma unroll
    for (int halfp = 0; halfp < 2; halfp++) {
        int cc = c + halfp * 4;
        float4 B  = *reinterpret_cast<const float4*>(bb + cc);
        float4 G  = *reinterpret_cast<const float4*>(gg + cc);
        float4 BE = *reinterpret_cast<const float4*>(bee + cc);
        float4 M  = *reinterpret_cast<const float4*>(mm + cc);
        float4 V  = *reinterpret_cast<const float4*>(vv + cc);
        float* op = o + halfp * 4;
        float* ap = acc + halfp * 4;
        op[0] = fmaxf((ap[0] + B.x - M.x) * rsqrtf(V.x + BN_EPS) * G.x + BE.x, 0.0f);
        op[1] = fmaxf((ap[1] + B.y - M.y) * rsqrtf(V.y + BN_EPS) * G.y + BE.y, 0.0f);
        op[2] = fmaxf((ap[2] + B.z - M.z) * rsqrtf(V.z + BN_EPS) * G.z + BE.z, 0.0f);
        op[3] = fmaxf((ap[3] + B.w - M.w) * rsqrtf(V.w + BN_EPS) * G.w + BE.w, 0.0f);
    }

    if (!W3MODE) {
        uint32_t hw[4];
#pragma unroll
        for (int j = 0; j < 4; j++) {
            __half2 hp = __floats2half2_rn(o[2 * j], o[2 * j + 1]);
            hw[j] = *reinterpret_cast<uint32_t*>(&hp);
        }
        *reinterpret_cast<uint4*>(hnext + (size_t)i * HH + c) =
            make_uint4(hw[0], hw[1], hw[2], hw[3]);
    } else {
        float p0 = 0.f, p1 = 0.f;
#pragma unroll
        for (int j = 0; j < 8; j++) {
            p0 += o[j] * __ldg(&W3[(c + j) * 2]);
            p1 += o[j] * __ldg(&W3[(c + j) * 2 + 1]);
        }
#pragma unroll
        for (int off = 16; off; off >>= 1) {
            p0 += __shfl_xor_sync(0xFFFFFFFFu, p0, off);
            p1 += __shfl_xor_sync(0xFFFFFFFFu, p1, off);
        }
        if (lane == 0) {
            h3[2 * i]     = p0;
            h3[2 * i + 1] = p1;
        }
    }
}

// -------------------- final gather (OUT=2) --------------------
__global__ void k_gather_out(const float* __restrict__ h3,
                             const int* __restrict__ rowptr, const int* __restrict__ src,
                             const float* __restrict__ wedge, const float* __restrict__ snorm,
                             const float* __restrict__ b3, float* __restrict__ out, int n) {
    int i = blockIdx.x * blockDim.x + threadIdx.x;
    if (i >= n) return;
    float s = snorm[i];
    float a0 = s * h3[2 * i]     + b3[0];
    float a1 = s * h3[2 * i + 1] + b3[1];
    int p = rowptr[i], end = rowptr[i + 1];
    for (; p + 1 < end; p += 2) {
        int   r0 = __ldg(&src[p]),   r1 = __ldg(&src[p + 1]);
        float w0 = __ldg(&wedge[p]), w1 = __ldg(&wedge[p + 1]);
        a0 += w0 * h3[2 * r0]     + w1 * h3[2 * r1];
        a1 += w0 * h3[2 * r0 + 1] + w1 * h3[2 * r1 + 1];
    }
    if (p < end) {
        int r = __ldg(&src[p]);
        float wv = __ldg(&wedge[p]);
        a0 += wv * h3[2 * r];
        a1 += wv * h3[2 * r + 1];
    }
    out[2 * i]     = a0;
    out[2 * i + 1] = a1;
}

// -------------------- launch --------------------
extern "C" void kernel_launch(void* const* d_in, const int* in_sizes, int n_in,
                              void* d_out, int out_size) {
    const float*        x   = (const float*)d_in[0];
    const unsigned int* eiw = (const unsigned int*)d_in[1];
    const float*        w   = (const float*)d_in[2];
    const float*        W1  = (const float*)d_in[3];
    const float*        b1  = (const float*)d_in[4];
    const float*        g1  = (const float*)d_in[5];
    const float*        be1 = (const float*)d_in[6];
    const float*        m1  = (const float*)d_in[7];
    const float*        v1  = (const float*)d_in[8];
    const float*        W2  = (const float*)d_in[9];
    const float*        b2  = (const float*)d_in[10];
    const float*        g2  = (const float*)d_in[11];
    const float*        be2 = (const float*)d_in[12];
    const float*        m2  = (const float*)d_in[13];
    const float*        v2  = (const float*)d_in[14];
    const float*        W3  = (const float*)d_in[15];
    const float*        b3  = (const float*)d_in[16];
    float* out = (float*)d_out;

    int *row, *col, *cnt, *incl, *blksum, *blkoff, *rowptr, *fill, *src;
    float *deg, *dinv, *snorm, *h3, *wedge;
    __half *h16, *hi, *Wh1, *Wh2;
    cudaGetSymbolAddress((void**)&row,    g_row);
    cudaGetSymbolAddress((void**)&col,    g_col);
    cudaGetSymbolAddress((void**)&cnt,    g_cnt);
    cudaGetSymbolAddress((void**)&incl,   g_incl);
    cudaGetSymbolAddress((void**)&blksum, g_blksum);
    cudaGetSymbolAddress((void**)&blkoff, g_blkoff);
    cudaGetSymbolAddress((void**)&rowptr, g_rowptr);
    cudaGetSymbolAddress((void**)&fill,   g_fill);
    cudaGetSymbolAddress((void**)&src,    g_src);
    cudaGetSymbolAddress((void**)&wedge,  g_wedge);
    cudaGetSymbolAddress((void**)&deg,    g_deg);
    cudaGetSymbolAddress((void**)&dinv,   g_dinv);
    cudaGetSymbolAddress((void**)&snorm,  g_snorm);
    cudaGetSymbolAddress((void**)&h16,    g_h16);
    cudaGetSymbolAddress((void**)&h3,     g_h3);
    cudaGetSymbolAddress((void**)&hi,     g_hi);
    cudaGetSymbolAddress((void**)&Wh1,    g_Wh1);
    cudaGetSymbolAddress((void**)&Wh2,    g_Wh2);

    const int n = NN, E = EE;
    const int SMEM1 = 81920;   // Bs(40960) + Ah(20480) + Al(20480)
    const int SMEM2 = 61440;   // Bs(40960) + Ah(20480)  -- Ah lives at offset 40960..61440
    cudaFuncSetAttribute(mma_gemm<FIN, true>,
                         cudaFuncAttributeMaxDynamicSharedMemorySize, SMEM1);
    cudaFuncSetAttribute(mma_gemm<HH, false>,
                         cudaFuncAttributeMaxDynamicSharedMemorySize, SMEM2);

    dim3 t256(256);
    int nb_n  = (n + 255) / 256;
    int nb_e  = (E + 255) / 256;
    int nb_sc = (n + 511) / 512;
    int nb_g  = n / 8;                 // 6250 (NN % 8 == 0)
    int gemm_grid = (n + 127) / 128;

    // preprocessing
    k_pre<<<768 + nb_n, t256>>>(W1, Wh1, W2, Wh2, eiw, deg, cnt, fill, n);
    k_extract_deg<<<nb_e, t256>>>(eiw, w, row, col, deg, cnt, E);
    k_scan1<<<nb_sc, 512>>>(cnt, incl, blksum, n);
    k_scan2<<<1, 128>>>(blksum, blkoff, nb_sc);
    k_scan3_dinv<<<nb_n, t256>>>(incl, cnt, blkoff, rowptr, deg, dinv, snorm, n, E);
    k_norm_fill<<<nb_e, t256>>>(row, col, w, dinv, rowptr, fill, src, wedge, E);

    // ---- layer 1 (A = x fp32, 2-term split in-kernel) ----
    mma_gemm<FIN, true><<<gemm_grid, t256, SMEM1>>>(x, nullptr, Wh1, h16, n);
    k_gather_bn<false><<<nb_g, t256>>>(h16, rowptr, src, wedge, snorm,
                                       b1, g1, be1, m1, v1, hi, nullptr, nullptr, n);

    // ---- layer 2 (A fp16 single-term, +W3 fused) ----
    mma_gemm<HH, false><<<gemm_grid, t256, SMEM2>>>(nullptr, hi, Wh2, h16, n);
    k_gather_bn<true><<<nb_g, t256>>>(h16, rowptr, src, wedge, snorm,
                                      b2, g2, be2, m2, v2, nullptr, W3, h3, n);

    // ---- layer 3 ----
    k_gather_out<<<nb_n, t256>>>(h3, rowptr, src, wedge, snorm, b3, out, n);
}

// round 11
// speedup vs baseline: 5.3344x; 1.0907x over previous
#include <cuda_runtime.h>
#include <cuda_fp16.h>
#include <stdint.h>

#define NN   50000
#define EE   800000
#define FIN  512
#define HH   256
#define OUTF 2
#define BN_EPS 1e-5f

// -------------------- scratch --------------------
__device__ int    g_is64;
__device__ int    g_row[EE];
__device__ int    g_col[EE];
__device__ float  g_deg[NN];
__device__ float  g_dinv[NN];
__device__ float  g_snorm[NN];
__device__ __half g_h16[(size_t)NN * HH];     // GEMM output, fp16
__device__ float  g_h3[(size_t)NN * OUTF];
__device__ __half g_hi[(size_t)NN * HH];      // layer-2 A (fp16)
__device__ __half g_Wh1[(size_t)HH * FIN];    // W1^T fp16
__device__ __half g_Wh2[(size_t)HH * HH];     // W2^T fp16
// CSR (by destination col)
__device__ int    g_cnt[NN];
__device__ int    g_incl[NN];
__device__ int    g_blksum[128];
__device__ int    g_rowptr[NN + 1];
__device__ int    g_fill[NN];
__device__ int    g_src[EE];
__device__ float  g_wedge[EE];

// -------------------- fused pre: W transpose/round + init + dtype detect --------------------
__global__ void k_pre(const float* __restrict__ W1, __half* __restrict__ Wh1,
                      const float* __restrict__ W2, __half* __restrict__ Wh2,
                      const unsigned int* __restrict__ wr,
                      float* __restrict__ deg, int* __restrict__ cnt,
                      int* __restrict__ fill, int n) {
    int b = blockIdx.x, tid = threadIdx.x;
    if (b < 512) {
        int u = b * 256 + tid;                 // [256,512]
        int nn = u >> 9, k = u & 511;
        Wh1[u] = __float2half_rn(W1[(size_t)k * 256 + nn]);
    } else if (b < 768) {
        int u = (b - 512) * 256 + tid;         // [256,256]
        int nn = u >> 8, k = u & 255;
        Wh2[u] = __float2half_rn(W2[(size_t)k * 256 + nn]);
    } else {
        int i = (b - 768) * 256 + tid;
        if (i < n) { deg[i] = 1.0f; cnt[i] = 0; fill[i] = 0; }
        if (b == 768) {
            int ok = 1;
            for (int j = tid; j < 2048; j += 256)
                if (wr[2 * j + 1] != 0u) ok = 0;
            int all = __syncthreads_and(ok);
            if (tid == 0) g_is64 = all;
        }
    }
}

__global__ void k_extract_deg(const unsigned int* __restrict__ wr,
                              const float* __restrict__ w,
                              int* __restrict__ row, int* __restrict__ col,
                              float* __restrict__ deg, int* __restrict__ cnt, int E) {
    int e = blockIdx.x * blockDim.x + threadIdx.x;
    if (e >= E) return;
    int r, c;
    if (g_is64) { r = (int)wr[2 * e]; c = (int)wr[2 * (E + e)]; }
    else        { r = (int)wr[e];     c = (int)wr[E + e]; }
    row[e] = r;
    col[e] = c;
    atomicAdd(&deg[c], w[e]);
    atomicAdd(&cnt[c], 1);
}

// -------------------- scan --------------------
__global__ void k_scan1(const int* __restrict__ cnt, int* __restrict__ incl,
                        int* __restrict__ blksum, int n) {
    __shared__ int sh[512];
    int t = threadIdx.x;
    int i = blockIdx.x * 512 + t;
    int v = (i < n) ? cnt[i] : 0;
    sh[t] = v;
    __syncthreads();
#pragma unroll
    for (int off = 1; off < 512; off <<= 1) {
        int x = (t >= off) ? sh[t - off] : 0;
        __syncthreads();
        sh[t] += x;
        __syncthreads();
    }
    if (i < n) incl[i] = sh[t];
    if (t == 511) blksum[blockIdx.x] = sh[511];
}

// fused scan2+scan3+dinv: every block re-scans the (<=128) block sums in smem
__global__ void k_scan23(const int* __restrict__ incl, const int* __restrict__ cnt,
                         const int* __restrict__ blksum, int* __restrict__ rowptr,
                         const float* __restrict__ deg, float* __restrict__ dinv,
                         float* __restrict__ snorm, int n, int E, int nb) {
    __shared__ int sh[128];
    int t = threadIdx.x;
    if (t < 128) sh[t] = (t < nb) ? blksum[t] : 0;
    __syncthreads();
#pragma unroll
    for (int off = 1; off < 128; off <<= 1) {
        int x = 0;
        if (t < 128 && t >= off) x = sh[t - off];
        __syncthreads();
        if (t < 128) sh[t] += x;
        __syncthreads();
    }
    int i = blockIdx.x * blockDim.x + t;
    if (i < n) {
        int blk = i / 512;
        int exoff = sh[blk] - blksum[blk];   // exclusive block offset
        rowptr[i] = incl[i] - cnt[i] + exoff;
        float d = rsqrtf(deg[i]);
        dinv[i] = d;
        snorm[i] = d * d;
    }
    if (i == 0) rowptr[n] = E;
}

__global__ void k_norm_fill(const int* __restrict__ row, const int* __restrict__ col,
                            const float* __restrict__ w, const float* __restrict__ dinv,
                            const int* __restrict__ rowptr, int* __restrict__ fill,
                            int* __restrict__ src, float* __restrict__ wedge, int E) {
    int e = blockIdx.x * blockDim.x + threadIdx.x;
    if (e >= E) return;
    int r = row[e], c = col[e];
    float nv = dinv[r] * w[e] * dinv[c];
    int p = rowptr[c] + atomicAdd(&fill[c], 1);
    src[p] = r;
    wedge[p] = nv;
}

// -------------------- helpers --------------------
__device__ __forceinline__ uint32_t pack2h(__half a, __half b) {
    __half2 p = __halves2half2(a, b);
    return *reinterpret_cast<uint32_t*>(&p);
}
__device__ __forceinline__ void h8_to_f8(uint4 raw, float* f) {
    __half2* p = reinterpret_cast<__half2*>(&raw);
#pragma unroll
    for (int j = 0; j < 4; j++) {
        float2 t = __half22float2(p[j]);
        f[2 * j] = t.x;
        f[2 * j + 1] = t.y;
    }
}

__device__ __forceinline__ void mma16816(float* d, const uint32_t* a, const uint32_t* b) {
    asm volatile(
        "mma.sync.aligned.m16n8k16.row.col.f32.f16.f16.f32 "
        "{%0,%1,%2,%3}, {%4,%5,%6,%7}, {%8,%9}, {%0,%1,%2,%3};"
        : "+f"(d[0]), "+f"(d[1]), "+f"(d[2]), "+f"(d[3])
        : "r"(a[0]), "r"(a[1]), "r"(a[2]), "r"(a[3]), "r"(b[0]), "r"(b[1]));
}
__device__ __forceinline__ void ldmatrix_x4(uint32_t& r0, uint32_t& r1, uint32_t& r2,
                                            uint32_t& r3, uint32_t saddr) {
    asm volatile("ldmatrix.sync.aligned.m8n8.x4.shared.b16 {%0,%1,%2,%3}, [%4];"
                 : "=r"(r0), "=r"(r1), "=r"(r2), "=r"(r3) : "r"(saddr));
}
__device__ __forceinline__ void cp_async16(uint32_t saddr, const void* gaddr, int src_sz) {
    asm volatile("cp.async.cg.shared.global [%0], [%1], 16, %2;"
                 :: "r"(saddr), "l"(gaddr), "r"(src_sz));
}
__device__ __forceinline__ void cp_commit() { asm volatile("cp.async.commit_group;"); }
__device__ __forceinline__ void cp_wait1()  { asm volatile("cp.async.wait_group 1;"); }
__device__ __forceinline__ void cp_wait0()  { asm volatile("cp.async.wait_group 0;"); }

// -------------------- single-term fp16 HMMA GEMM, BN=256 --------------------
// AFP32=true : A fp32 in gmem, rounded to fp16 in-kernel (layer 1)
// AFP32=false: A fp16 in gmem, cp.async (layer 2)
// BM=128, BN=256, BK=32; 256 thr = 8 warps (2 M x 4 N), warp tile 64x64.
// smem 61440: Bs[2][5120] @0 | Ah[2][2560] @40960
template <int K, bool AFP32>
__global__ __launch_bounds__(256, 1)
void mma_gemm(const float* __restrict__ Af, const __half* __restrict__ Ahalf,
              const __half* __restrict__ Bh,
              __half* __restrict__ C, int Nr) {
    constexpr int NCH = K / 32;
    extern __shared__ char smem[];
    uint32_t* Bs = reinterpret_cast<uint32_t*>(smem);
    uint32_t* Ah = reinterpret_cast<uint32_t*>(smem + 40960);

    const int tid  = threadIdx.x;
    const int lane = tid & 31;
    const int wid  = tid >> 5;
    const int warp_m = wid & 1;
    const int warp_n = wid >> 1;
    const int bm = blockIdx.x * 128;

    float acc[4][8][4];
#pragma unroll
    for (int mt = 0; mt < 4; mt++)
#pragma unroll
        for (int nt = 0; nt < 8; nt++)
#pragma unroll
            for (int q = 0; q < 4; q++) acc[mt][nt][q] = 0.0f;

    float4 fa[2][2];

    auto loadAf = [&](int q) {
        const int kt = q * 32;
#pragma unroll
        for (int i = 0; i < 2; i++) {
            int u = tid + i * 256;
            int r = u >> 2, k8 = u & 3;
            int gr = bm + r;
            if (gr < Nr) {
                const float4* p = reinterpret_cast<const float4*>(
                    Af + (size_t)gr * K + kt + k8 * 8);
                fa[i][0] = p[0];
                fa[i][1] = p[1];
            } else {
                fa[i][0] = make_float4(0.f, 0.f, 0.f, 0.f);
                fa[i][1] = make_float4(0.f, 0.f, 0.f, 0.f);
            }
        }
    };
    auto storeA = [&](int st) {
#pragma unroll
        for (int i = 0; i < 2; i++) {
            int u = tid + i * 256;
            int r = u >> 2, k8 = u & 3;
            uint32_t hw[4];
            hw[0] = pack2h(__float2half_rn(fa[i][0].x), __float2half_rn(fa[i][0].y));
            hw[1] = pack2h(__float2half_rn(fa[i][0].z), __float2half_rn(fa[i][0].w));
            hw[2] = pack2h(__float2half_rn(fa[i][1].x), __float2half_rn(fa[i][1].y));
            hw[3] = pack2h(__float2half_rn(fa[i][1].z), __float2half_rn(fa[i][1].w));
            int woff = st * 2560 + r * 20 + k8 * 4;
            *reinterpret_cast<uint4*>(&Ah[woff]) = make_uint4(hw[0], hw[1], hw[2], hw[3]);
        }
    };
    auto asyncA16 = [&](int st, int q) {
        const int kt = q * 32;
#pragma unroll
        for (int i = 0; i < 2; i++) {
            int u = tid + i * 256;
            int r = u >> 2, k8 = u & 3;
            int gr = bm + r;
            int ok = (gr < Nr);
            size_t srcoff = (size_t)(ok ? gr : 0) * K + kt + k8 * 8;
            int woff = st * 2560 + r * 20 + k8 * 4;
            cp_async16((uint32_t)__cvta_generic_to_shared(&Ah[woff]), Ahalf + srcoff, ok ? 16 : 0);
        }
    };
    auto asyncB = [&](int st, int q) {
        const int kt = q * 32;
#pragma unroll
        for (int i = 0; i < 4; i++) {
            int u = tid + i * 256;
            int r = u >> 2, k8 = u & 3;
            int woff = st * 5120 + r * 20 + k8 * 4;
            cp_async16((uint32_t)__cvta_generic_to_shared(&Bs[woff]),
                       Bh + (size_t)r * K + kt + k8 * 8, 16);
        }
    };

    const int aRow  = warp_m * 64 + (lane & 7) + ((lane >> 3) & 1) * 8;
    const int aWsel = (lane >> 4) * 4;
    const int bRow  = warp_n * 64 + (lane & 7) + (lane >> 4) * 8;
    const int bWsel = ((lane >> 3) & 1) * 4;

    auto compute = [&](int st) {
#pragma unroll
        for (int ks = 0; ks < 2; ks++) {
            const int kw = ks * 8;
            uint32_t a[4][4], b[8][2];
#pragma unroll
            for (int mt = 0; mt < 4; mt++) {
                uint32_t ad = (uint32_t)__cvta_generic_to_shared(
                    &Ah[st * 2560 + (aRow + mt * 16) * 20 + kw + aWsel]);
                ldmatrix_x4(a[mt][0], a[mt][1], a[mt][2], a[mt][3], ad);
            }
#pragma unroll
            for (int np = 0; np < 4; np++) {
                uint32_t bd = (uint32_t)__cvta_generic_to_shared(
                    &Bs[st * 5120 + (bRow + np * 16) * 20 + kw + bWsel]);
                ldmatrix_x4(b[2 * np][0], b[2 * np][1], b[2 * np + 1][0], b[2 * np + 1][1], bd);
            }
#pragma unroll
            for (int mt = 0; mt < 4; mt++)
#pragma unroll
                for (int nt = 0; nt < 8; nt++)
                    mma16816(acc[mt][nt], a[mt], b[nt]);
        }
    };

    if (AFP32) loadAf(0); else asyncA16(0, 0);
    asyncB(0, 0);
    cp_commit();
    if (AFP32) storeA(0);

    for (int q = 0; q < NCH; q++) {
        if (q + 1 < NCH) {
            if (AFP32) loadAf(q + 1); else asyncA16((q + 1) & 1, q + 1);
            asyncB((q + 1) & 1, q + 1);
            cp_commit();
            cp_wait1();
        } else {
            cp_wait0();
        }
        __syncthreads();
        compute(q & 1);
        if (AFP32 && q + 1 < NCH) storeA((q + 1) & 1);
        __syncthreads();
    }

    const int lr4 = lane >> 2, lk = lane & 3;
#pragma unroll
    for (int mt = 0; mt < 4; mt++) {
#pragma unroll
        for (int half = 0; half < 2; half++) {
            int r = bm + warp_m * 64 + mt * 16 + half * 8 + lr4;
            if (r >= Nr) continue;
#pragma unroll
            for (int nt = 0; nt < 8; nt++) {
                int c = warp_n * 64 + nt * 8 + lk * 2;
                *reinterpret_cast<__half2*>(C + (size_t)r * 256 + c) =
                    __floats2half2_rn(acc[mt][nt][half * 2], acc[mt][nt][half * 2 + 1]);
            }
        }
    }
}

// -------------------- fused gather + BN + ReLU (warp per node) --------------------
template <bool W3MODE>
__global__ __launch_bounds__(256)
void k_gather_bn(const __half* __restrict__ h,
                 const int* __restrict__ rowptr, const int* __restrict__ src,
                 const float* __restrict__ wedge, const float* __restrict__ snorm,
                 const float* __restrict__ bb, const float* __restrict__ gg,
                 const float* __restrict__ bee, const float* __restrict__ mm,
                 const float* __restrict__ vv,
                 __half* __restrict__ hnext,
                 const float* __restrict__ W3, float* __restrict__ h3, int n) {
    int i = blockIdx.x * 8 + (threadIdx.x >> 5);
    int lane = threadIdx.x & 31;
    int c = lane * 8;

    float acc[8], f[8];
    h8_to_f8(*reinterpret_cast<const uint4*>(h + (size_t)i * HH + c), f);
    float s = snorm[i];
#pragma unroll
    for (int j = 0; j < 8; j++) acc[j] = f[j] * s;

    int p   = rowptr[i];
    int end = rowptr[i + 1];
    for (; p + 1 < end; p += 2) {
        int   r0 = __ldg(&src[p]),   r1 = __ldg(&src[p + 1]);
        float w0 = __ldg(&wedge[p]), w1 = __ldg(&wedge[p + 1]);
        float f0[8], f1[8];
        h8_to_f8(*reinterpret_cast<const uint4*>(h + (size_t)r0 * HH + c), f0);
        h8_to_f8(*reinterpret_cast<const uint4*>(h + (size_t)r1 * HH + c), f1);
#pragma unroll
        for (int j = 0; j < 8; j++) acc[j] += w0 * f0[j] + w1 * f1[j];
    }
    if (p < end) {
        int r = __ldg(&src[p]);
        float wv = __ldg(&wedge[p]);
        float f0[8];
        h8_to_f8(*reinterpret_cast<const uint4*>(h + (size_t)r * HH + c), f0);
#pragma unroll
        for (int j = 0; j < 8; j++) acc[j] += wv * f0[j];
    }

    float o[8];
#pragma unroll
    for (int halfp = 0; halfp < 2; halfp++) {
        int cc = c + halfp * 4;
        float4 B  = *reinterpret_cast<const float4*>(bb + cc);
        float4 G  = *reinterpret_cast<const float4*>(gg + cc);
        float4 BE = *reinterpret_cast<const float4*>(bee + cc);
        float4 M  = *reinterpret_cast<const float4*>(mm + cc);
        float4 V  = *reinterpret_cast<const float4*>(vv + cc);
        float* op = o + halfp * 4;
        float* ap = acc + halfp * 4;
        op[0] = fmaxf((ap[0] + B.x - M.x) * rsqrtf(V.x + BN_EPS) * G.x + BE.x, 0.0f);
        op[1] = fmaxf((ap[1] + B.y - M.y) * rsqrtf(V.y + BN_EPS) * G.y + BE.y, 0.0f);
        op[2] = fmaxf((ap[2] + B.z - M.z) * rsqrtf(V.z + BN_EPS) * G.z + BE.z, 0.0f);
        op[3] = fmaxf((ap[3] + B.w - M.w) * rsqrtf(V.w + BN_EPS) * G.w + BE.w, 0.0f);
    }

    if (!W3MODE) {
        uint32_t hw[4];
#pragma unroll
        for (int j = 0; j < 4; j++) {
            __half2 hp = __floats2half2_rn(o[2 * j], o[2 * j + 1]);
            hw[j] = *reinterpret_cast<uint32_t*>(&hp);
        }
        *reinterpret_cast<uint4*>(hnext + (size_t)i * HH + c) =
            make_uint4(hw[0], hw[1], hw[2], hw[3]);
    } else {
        float p0 = 0.f, p1 = 0.f;
#pragma unroll
        for (int j = 0; j < 8; j++) {
            p0 += o[j] * __ldg(&W3[(c + j) * 2]);
            p1 += o[j] * __ldg(&W3[(c + j) * 2 + 1]);
        }
#pragma unroll
        for (int off = 16; off; off >>= 1) {
            p0 += __shfl_xor_sync(0xFFFFFFFFu, p0, off);
            p1 += __shfl_xor_sync(0xFFFFFFFFu, p1, off);
        }
        if (lane == 0) {
            h3[2 * i]     = p0;
            h3[2 * i + 1] = p1;
        }
    }
}

// -------------------- final gather (OUT=2) --------------------
__global__ void k_gather_out(const float* __restrict__ h3,
                             const int* __restrict__ rowptr, const int* __restrict__ src,
                             const float* __restrict__ wedge, const float* __restrict__ snorm,
                             const float* __restrict__ b3, float* __restrict__ out, int n) {
    int i = blockIdx.x * blockDim.x + threadIdx.x;
    if (i >= n) return;
    float s = snorm[i];
    float a0 = s * h3[2 * i]     + b3[0];
    float a1 = s * h3[2 * i + 1] + b3[1];
    int p = rowptr[i], end = rowptr[i + 1];
    for (; p + 1 < end; p += 2) {
        int   r0 = __ldg(&src[p]),   r1 = __ldg(&src[p + 1]);
        float w0 = __ldg(&wedge[p]), w1 = __ldg(&wedge[p + 1]);
        a0 += w0 * h3[2 * r0]     + w1 * h3[2 * r1];
        a1 += w0 * h3[2 * r0 + 1] + w1 * h3[2 * r1 + 1];
    }
    if (p < end) {
        int r = __ldg(&src[p]);
        float wv = __ldg(&wedge[p]);
        a0 += wv * h3[2 * r];
        a1 += wv * h3[2 * r + 1];
    }
    out[2 * i]     = a0;
    out[2 * i + 1] = a1;
}

// -------------------- launch --------------------
extern "C" void kernel_launch(void* const* d_in, const int* in_sizes, int n_in,
                              void* d_out, int out_size) {
    const float*        x   = (const float*)d_in[0];
    const unsigned int* eiw = (const unsigned int*)d_in[1];
    const float*        w   = (const float*)d_in[2];
    const float*        W1  = (const float*)d_in[3];
    const float*        b1  = (const float*)d_in[4];
    const float*        g1  = (const float*)d_in[5];
    const float*        be1 = (const float*)d_in[6];
    const float*        m1  = (const float*)d_in[7];
    const float*        v1  = (const float*)d_in[8];
    const float*        W2  = (const float*)d_in[9];
    const float*        b2  = (const float*)d_in[10];
    const float*        g2  = (const float*)d_in[11];
    const float*        be2 = (const float*)d_in[12];
    const float*        m2  = (const float*)d_in[13];
    const float*        v2  = (const float*)d_in[14];
    const float*        W3  = (const float*)d_in[15];
    const float*        b3  = (const float*)d_in[16];
    float* out = (float*)d_out;

    int *row, *col, *cnt, *incl, *blksum, *rowptr, *fill, *src;
    float *deg, *dinv, *snorm, *h3, *wedge;
    __half *h16, *hi, *Wh1, *Wh2;
    cudaGetSymbolAddress((void**)&row,    g_row);
    cudaGetSymbolAddress((void**)&col,    g_col);
    cudaGetSymbolAddress((void**)&cnt,    g_cnt);
    cudaGetSymbolAddress((void**)&incl,   g_incl);
    cudaGetSymbolAddress((void**)&blksum, g_blksum);
    cudaGetSymbolAddress((void**)&rowptr, g_rowptr);
    cudaGetSymbolAddress((void**)&fill,   g_fill);
    cudaGetSymbolAddress((void**)&src,    g_src);
    cudaGetSymbolAddress((void**)&wedge,  g_wedge);
    cudaGetSymbolAddress((void**)&deg,    g_deg);
    cudaGetSymbolAddress((void**)&dinv,   g_dinv);
    cudaGetSymbolAddress((void**)&snorm,  g_snorm);
    cudaGetSymbolAddress((void**)&h16,    g_h16);
    cudaGetSymbolAddress((void**)&h3,     g_h3);
    cudaGetSymbolAddress((void**)&hi,     g_hi);
    cudaGetSymbolAddress((void**)&Wh1,    g_Wh1);
    cudaGetSymbolAddress((void**)&Wh2,    g_Wh2);

    const int n = NN, E = EE;
    const int SMEM = 61440;    // Bs(40960) + Ah(20480)
    cudaFuncSetAttribute(mma_gemm<FIN, true>,
                         cudaFuncAttributeMaxDynamicSharedMemorySize, SMEM);
    cudaFuncSetAttribute(mma_gemm<HH, false>,
                         cudaFuncAttributeMaxDynamicSharedMemorySize, SMEM);

    dim3 t256(256);
    int nb_n  = (n + 255) / 256;
    int nb_e  = (E + 255) / 256;
    int nb_sc = (n + 511) / 512;       // 98
    int nb_g  = n / 8;                 // 6250
    int gemm_grid = (n + 127) / 128;

    // preprocessing
    k_pre<<<768 + nb_n, t256>>>(W1, Wh1, W2, Wh2, eiw, deg, cnt, fill, n);
    k_extract_deg<<<nb_e, t256>>>(eiw, w, row, col, deg, cnt, E);
    k_scan1<<<nb_sc, 512>>>(cnt, incl, blksum, n);
    k_scan23<<<nb_n, t256>>>(incl, cnt, blksum, rowptr, deg, dinv, snorm, n, E, nb_sc);
    k_norm_fill<<<nb_e, t256>>>(row, col, w, dinv, rowptr, fill, src, wedge, E);

    // ---- layer 1 (A = x fp32, rounded to fp16 in-kernel) ----
    mma_gemm<FIN, true><<<gemm_grid, t256, SMEM>>>(x, nullptr, Wh1, h16, n);
    k_gather_bn<false><<<nb_g, t256>>>(h16, rowptr, src, wedge, snorm,
                                       b1, g1, be1, m1, v1, hi, nullptr, nullptr, n);

    // ---- layer 2 (A fp16, +W3 fused) ----
    mma_gemm<HH, false><<<gemm_grid, t256, SMEM>>>(nullptr, hi, Wh2, h16, n);
    k_gather_bn<true><<<nb_g, t256>>>(h16, rowptr, src, wedge, snorm,
                                      b2, g2, be2, m2, v2, nullptr, W3, h3, n);

    // ---- layer 3 ----
    k_gather_out<<<nb_n, t256>>>(h3, rowptr, src, wedge, snorm, b3, out, n);
}

// round 12
// speedup vs baseline: 5.4053x; 1.0133x over previous
#include <cuda_runtime.h>
#include <cuda_fp16.h>
#include <stdint.h>

#define NN   50000
#define EE   800000
#define FIN  512
#define HH   256
#define OUTF 2
#define BN_EPS 1e-5f

// -------------------- scratch --------------------
__device__ int    g_is64;
__device__ int    g_row[EE];
__device__ int    g_col[EE];
__device__ float  g_deg[NN];
__device__ float  g_dinv[NN];
__device__ float  g_snorm[NN];
__device__ __half g_h16[(size_t)NN * HH];
__device__ float  g_h3[(size_t)NN * OUTF];
__device__ __half g_hi[(size_t)NN * HH];
__device__ __half g_Wh1[(size_t)HH * FIN];
__device__ __half g_Wh2[(size_t)HH * HH];
// CSR (by destination col)
__device__ int    g_cnt[NN];
__device__ int    g_incl[NN];
__device__ int    g_blksum[128];
__device__ int    g_rowptr[NN + 1];
__device__ int    g_fill[NN];
__device__ int    g_src[EE];
__device__ float  g_wedge[EE];

// -------------------- fused pre --------------------
__global__ void k_pre(const float* __restrict__ W1, __half* __restrict__ Wh1,
                      const float* __restrict__ W2, __half* __restrict__ Wh2,
                      const unsigned int* __restrict__ wr,
                      float* __restrict__ deg, int* __restrict__ cnt,
                      int* __restrict__ fill, int n) {
    int b = blockIdx.x, tid = threadIdx.x;
    if (b < 512) {
        int u = b * 256 + tid;
        int nn = u >> 9, k = u & 511;
        Wh1[u] = __float2half_rn(W1[(size_t)k * 256 + nn]);
    } else if (b < 768) {
        int u = (b - 512) * 256 + tid;
        int nn = u >> 8, k = u & 255;
        Wh2[u] = __float2half_rn(W2[(size_t)k * 256 + nn]);
    } else {
        int i = (b - 768) * 256 + tid;
        if (i < n) { deg[i] = 1.0f; cnt[i] = 0; fill[i] = 0; }
        if (b == 768) {
            int ok = 1;
            for (int j = tid; j < 2048; j += 256)
                if (wr[2 * j + 1] != 0u) ok = 0;
            int all = __syncthreads_and(ok);
            if (tid == 0) g_is64 = all;
        }
    }
}

__global__ void k_extract_deg(const unsigned int* __restrict__ wr,
                              const float* __restrict__ w,
                              int* __restrict__ row, int* __restrict__ col,
                              float* __restrict__ deg, int* __restrict__ cnt, int E) {
    int e = blockIdx.x * blockDim.x + threadIdx.x;
    if (e >= E) return;
    int r, c;
    if (g_is64) { r = (int)wr[2 * e]; c = (int)wr[2 * (E + e)]; }
    else        { r = (int)wr[e];     c = (int)wr[E + e]; }
    row[e] = r;
    col[e] = c;
    atomicAdd(&deg[c], w[e]);
    atomicAdd(&cnt[c], 1);
}

// -------------------- scan --------------------
__global__ void k_scan1(const int* __restrict__ cnt, int* __restrict__ incl,
                        int* __restrict__ blksum, int n) {
    __shared__ int sh[512];
    int t = threadIdx.x;
    int i = blockIdx.x * 512 + t;
    int v = (i < n) ? cnt[i] : 0;
    sh[t] = v;
    __syncthreads();
#pragma unroll
    for (int off = 1; off < 512; off <<= 1) {
        int x = (t >= off) ? sh[t - off] : 0;
        __syncthreads();
        sh[t] += x;
        __syncthreads();
    }
    if (i < n) incl[i] = sh[t];
    if (t == 511) blksum[blockIdx.x] = sh[511];
}

__global__ void k_scan23(const int* __restrict__ incl, const int* __restrict__ cnt,
                         const int* __restrict__ blksum, int* __restrict__ rowptr,
                         const float* __restrict__ deg, float* __restrict__ dinv,
                         float* __restrict__ snorm, int n, int E, int nb) {
    __shared__ int sh[128];
    int t = threadIdx.x;
    if (t < 128) sh[t] = (t < nb) ? blksum[t] : 0;
    __syncthreads();
#pragma unroll
    for (int off = 1; off < 128; off <<= 1) {
        int x = 0;
        if (t < 128 && t >= off) x = sh[t - off];
        __syncthreads();
        if (t < 128) sh[t] += x;
        __syncthreads();
    }
    int i = blockIdx.x * blockDim.x + t;
    if (i < n) {
        int blk = i / 512;
        int exoff = sh[blk] - blksum[blk];
        rowptr[i] = incl[i] - cnt[i] + exoff;
        float d = rsqrtf(deg[i]);
        dinv[i] = d;
        snorm[i] = d * d;
    }
    if (i == 0) rowptr[n] = E;
}

__global__ void k_norm_fill(const int* __restrict__ row, const int* __restrict__ col,
                            const float* __restrict__ w, const float* __restrict__ dinv,
                            const int* __restrict__ rowptr, int* __restrict__ fill,
                            int* __restrict__ src, float* __restrict__ wedge, int E) {
    int e = blockIdx.x * blockDim.x + threadIdx.x;
    if (e >= E) return;
    int r = row[e], c = col[e];
    float nv = dinv[r] * w[e] * dinv[c];
    int p = rowptr[c] + atomicAdd(&fill[c], 1);
    src[p] = r;
    wedge[p] = nv;
}

// -------------------- helpers --------------------
__device__ __forceinline__ uint32_t pack2h(__half a, __half b) {
    __half2 p = __halves2half2(a, b);
    return *reinterpret_cast<uint32_t*>(&p);
}
__device__ __forceinline__ void h8_to_f8(uint4 raw, float* f) {
    __half2* p = reinterpret_cast<__half2*>(&raw);
#pragma unroll
    for (int j = 0; j < 4; j++) {
        float2 t = __half22float2(p[j]);
        f[2 * j] = t.x;
        f[2 * j + 1] = t.y;
    }
}

__device__ __forceinline__ void mma16816(float* d, const uint32_t* a, const uint32_t* b) {
    asm volatile(
        "mma.sync.aligned.m16n8k16.row.col.f32.f16.f16.f32 "
        "{%0,%1,%2,%3}, {%4,%5,%6,%7}, {%8,%9}, {%0,%1,%2,%3};"
        : "+f"(d[0]), "+f"(d[1]), "+f"(d[2]), "+f"(d[3])
        : "r"(a[0]), "r"(a[1]), "r"(a[2]), "r"(a[3]), "r"(b[0]), "r"(b[1]));
}
__device__ __forceinline__ void ldmatrix_x4(uint32_t& r0, uint32_t& r1, uint32_t& r2,
                                            uint32_t& r3, uint32_t saddr) {
    asm volatile("ldmatrix.sync.aligned.m8n8.x4.shared.b16 {%0,%1,%2,%3}, [%4];"
                 : "=r"(r0), "=r"(r1), "=r"(r2), "=r"(r3) : "r"(saddr));
}
__device__ __forceinline__ void cp_async16(uint32_t saddr, const void* gaddr, int src_sz) {
    asm volatile("cp.async.cg.shared.global [%0], [%1], 16, %2;"
                 :: "r"(saddr), "l"(gaddr), "r"(src_sz));
}
__device__ __forceinline__ void cp_commit() { asm volatile("cp.async.commit_group;"); }
__device__ __forceinline__ void cp_wait1()  { asm volatile("cp.async.wait_group 1;"); }
__device__ __forceinline__ void cp_wait0()  { asm volatile("cp.async.wait_group 0;"); }

// -------------------- single-term fp16 HMMA GEMM, BM=64/BN=256, occ 2 --------------------
// AFP32=true : A fp32 in gmem, rounded to fp16 in-kernel (layer 1)
// AFP32=false: A fp16 in gmem, cp.async (layer 2)
// 256 thr = 8 warps (2 M x 4 N), warp tile 32x64.
// smem 51200: Bs[2][5120] @0 | Ah[2][1280] @40960
template <int K, bool AFP32>
__global__ __launch_bounds__(256, 2)
void mma_gemm(const float* __restrict__ Af, const __half* __restrict__ Ahalf,
              const __half* __restrict__ Bh,
              __half* __restrict__ C, int Nr) {
    constexpr int NCH = K / 32;
    extern __shared__ char smem[];
    uint32_t* Bs = reinterpret_cast<uint32_t*>(smem);
    uint32_t* Ah = reinterpret_cast<uint32_t*>(smem + 40960);

    const int tid  = threadIdx.x;
    const int lane = tid & 31;
    const int wid  = tid >> 5;
    const int warp_m = wid & 1;        // 2 warps along M (32 rows each)
    const int warp_n = wid >> 1;       // 4 warps along N (64 cols each)
    const int bm = blockIdx.x * 64;

    float acc[2][8][4];
#pragma unroll
    for (int mt = 0; mt < 2; mt++)
#pragma unroll
        for (int nt = 0; nt < 8; nt++)
#pragma unroll
            for (int q = 0; q < 4; q++) acc[mt][nt][q] = 0.0f;

    float4 fa[2];   // one row-segment (8 floats) per thread

    auto loadAf = [&](int q) {
        const int kt = q * 32;
        int r = tid >> 2, k8 = tid & 3;   // 64 rows x 4 segs = 256
        int gr = bm + r;
        if (gr < Nr) {
            const float4* p = reinterpret_cast<const float4*>(
                Af + (size_t)gr * K + kt + k8 * 8);
            fa[0] = p[0];
            fa[1] = p[1];
        } else {
            fa[0] = make_float4(0.f, 0.f, 0.f, 0.f);
            fa[1] = make_float4(0.f, 0.f, 0.f, 0.f);
        }
    };
    auto storeA = [&](int st) {
        int r = tid >> 2, k8 = tid & 3;
        uint32_t hw[4];
        hw[0] = pack2h(__float2half_rn(fa[0].x), __float2half_rn(fa[0].y));
        hw[1] = pack2h(__float2half_rn(fa[0].z), __float2half_rn(fa[0].w));
        hw[2] = pack2h(__float2half_rn(fa[1].x), __float2half_rn(fa[1].y));
        hw[3] = pack2h(__float2half_rn(fa[1].z), __float2half_rn(fa[1].w));
        int woff = st * 1280 + r * 20 + k8 * 4;
        *reinterpret_cast<uint4*>(&Ah[woff]) = make_uint4(hw[0], hw[1], hw[2], hw[3]);
    };
    auto asyncA16 = [&](int st, int q) {
        const int kt = q * 32;
        int r = tid >> 2, k8 = tid & 3;
        int gr = bm + r;
        int ok = (gr < Nr);
        size_t srcoff = (size_t)(ok ? gr : 0) * K + kt + k8 * 8;
        int woff = st * 1280 + r * 20 + k8 * 4;
        cp_async16((uint32_t)__cvta_generic_to_shared(&Ah[woff]), Ahalf + srcoff, ok ? 16 : 0);
    };
    auto asyncB = [&](int st, int q) {
        const int kt = q * 32;
#pragma unroll
        for (int i = 0; i < 4; i++) {
            int u = tid + i * 256;
            int r = u >> 2, k8 = u & 3;
            int woff = st * 5120 + r * 20 + k8 * 4;
            cp_async16((uint32_t)__cvta_generic_to_shared(&Bs[woff]),
                       Bh + (size_t)r * K + kt + k8 * 8, 16);
        }
    };

    const int aRow  = warp_m * 32 + (lane & 7) + ((lane >> 3) & 1) * 8;
    const int aWsel = (lane >> 4) * 4;
    const int bRow  = warp_n * 64 + (lane & 7) + (lane >> 4) * 8;
    const int bWsel = ((lane >> 3) & 1) * 4;

    auto compute = [&](int st) {
#pragma unroll
        for (int ks = 0; ks < 2; ks++) {
            const int kw = ks * 8;
            uint32_t a[2][4], b[8][2];
#pragma unroll
            for (int mt = 0; mt < 2; mt++) {
                uint32_t ad = (uint32_t)__cvta_generic_to_shared(
                    &Ah[st * 1280 + (aRow + mt * 16) * 20 + kw + aWsel]);
                ldmatrix_x4(a[mt][0], a[mt][1], a[mt][2], a[mt][3], ad);
            }
#pragma unroll
            for (int np = 0; np < 4; np++) {
                uint32_t bd = (uint32_t)__cvta_generic_to_shared(
                    &Bs[st * 5120 + (bRow + np * 16) * 20 + kw + bWsel]);
                ldmatrix_x4(b[2 * np][0], b[2 * np][1], b[2 * np + 1][0], b[2 * np + 1][1], bd);
            }
#pragma unroll
            for (int mt = 0; mt < 2; mt++)
#pragma unroll
                for (int nt = 0; nt < 8; nt++)
                    mma16816(acc[mt][nt], a[mt], b[nt]);
        }
    };

    if (AFP32) loadAf(0); else asyncA16(0, 0);
    asyncB(0, 0);
    cp_commit();
    if (AFP32) storeA(0);

    for (int q = 0; q < NCH; q++) {
        if (q + 1 < NCH) {
            if (AFP32) loadAf(q + 1); else asyncA16((q + 1) & 1, q + 1);
            asyncB((q + 1) & 1, q + 1);
            cp_commit();
            cp_wait1();
        } else {
            cp_wait0();
        }
        __syncthreads();
        compute(q & 1);
        if (AFP32 && q + 1 < NCH) storeA((q + 1) & 1);
        __syncthreads();
    }

    const int lr4 = lane >> 2, lk = lane & 3;
#pragma unroll
    for (int mt = 0; mt < 2; mt++) {
#pragma unroll
        for (int half = 0; half < 2; half++) {
            int r = bm + warp_m * 32 + mt * 16 + half * 8 + lr4;
            if (r >= Nr) continue;
#pragma unroll
            for (int nt = 0; nt < 8; nt++) {
                int c = warp_n * 64 + nt * 8 + lk * 2;
                *reinterpret_cast<__half2*>(C + (size_t)r * 256 + c) =
                    __floats2half2_rn(acc[mt][nt][half * 2], acc[mt][nt][half * 2 + 1]);
            }
        }
    }
}

// -------------------- fused gather + BN + ReLU (warp per node, unroll x4) --------------------
template <bool W3MODE>
__global__ __launch_bounds__(256)
void k_gather_bn(const __half* __restrict__ h,
                 const int* __restrict__ rowptr, const int* __restrict__ src,
                 const float* __restrict__ wedge, const float* __restrict__ snorm,
                 const float* __restrict__ bb, const float* __restrict__ gg,
                 const float* __restrict__ bee, const float* __restrict__ mm,
                 const float* __restrict__ vv,
                 __half* __restrict__ hnext,
                 const float* __restrict__ W3, float* __restrict__ h3, int n) {
    int i = blockIdx.x * 8 + (threadIdx.x >> 5);
    int lane = threadIdx.x & 31;
    int c = lane * 8;

    float acc[8], f[8];
    h8_to_f8(*reinterpret_cast<const uint4*>(h + (size_t)i * HH + c), f);
    float s = snorm[i];
#pragma unroll
    for (int j = 0; j < 8; j++) acc[j] = f[j] * s;

    int p   = rowptr[i];
    int end = rowptr[i + 1];
    for (; p + 3 < end; p += 4) {
        int   r0 = __ldg(&src[p]),     r1 = __ldg(&src[p + 1]);
        int   r2 = __ldg(&src[p + 2]), r3 = __ldg(&src[p + 3]);
        float w0 = __ldg(&wedge[p]),     w1 = __ldg(&wedge[p + 1]);
        float w2 = __ldg(&wedge[p + 2]), w3 = __ldg(&wedge[p + 3]);
        uint4 q0 = *reinterpret_cast<const uint4*>(h + (size_t)r0 * HH + c);
        uint4 q1 = *reinterpret_cast<const uint4*>(h + (size_t)r1 * HH + c);
        uint4 q2 = *reinterpret_cast<const uint4*>(h + (size_t)r2 * HH + c);
        uint4 q3 = *reinterpret_cast<const uint4*>(h + (size_t)r3 * HH + c);
        float f0[8], f1[8], f2[8], f3[8];
        h8_to_f8(q0, f0); h8_to_f8(q1, f1); h8_to_f8(q2, f2); h8_to_f8(q3, f3);
#pragma unroll
        for (int j = 0; j < 8; j++)
            acc[j] += w0 * f0[j] + w1 * f1[j] + w2 * f2[j] + w3 * f3[j];
    }
    for (; p < end; p++) {
        int r = __ldg(&src[p]);
        float wv = __ldg(&wedge[p]);
        float f0[8];
        h8_to_f8(*reinterpret_cast<const uint4*>(h + (size_t)r * HH + c), f0);
#pragma unroll
        for (int j = 0; j < 8; j++) acc[j] += wv * f0[j];
    }

    float o[8];
#pragma unroll
    for (int halfp = 0; halfp < 2; halfp++) {
        int cc = c + halfp * 4;
        float4 B  = *reinterpret_cast<const float4*>(bb + cc);
        float4 G  = *reinterpret_cast<const float4*>(gg + cc);
        float4 BE = *reinterpret_cast<const float4*>(bee + cc);
        float4 M  = *reinterpret_cast<const float4*>(mm + cc);
        float4 V  = *reinterpret_cast<const float4*>(vv + cc);
        float* op = o + halfp * 4;
        float* ap = acc + halfp * 4;
        op[0] = fmaxf((ap[0] + B.x - M.x) * rsqrtf(V.x + BN_EPS) * G.x + BE.x, 0.0f);
        op[1] = fmaxf((ap[1] + B.y - M.y) * rsqrtf(V.y + BN_EPS) * G.y + BE.y, 0.0f);
        op[2] = fmaxf((ap[2] + B.z - M.z) * rsqrtf(V.z + BN_EPS) * G.z + BE.z, 0.0f);
        op[3] = fmaxf((ap[3] + B.w - M.w) * rsqrtf(V.w + BN_EPS) * G.w + BE.w, 0.0f);
    }

    if (!W3MODE) {
        uint32_t hw[4];
#pragma unroll
        for (int j = 0; j < 4; j++) {
            __half2 hp = __floats2half2_rn(o[2 * j], o[2 * j + 1]);
            hw[j] = *reinterpret_cast<uint32_t*>(&hp);
        }
        *reinterpret_cast<uint4*>(hnext + (size_t)i * HH + c) =
            make_uint4(hw[0], hw[1], hw[2], hw[3]);
    } else {
        float p0 = 0.f, p1 = 0.f;
#pragma unroll
        for (int j = 0; j < 8; j++) {
            p0 += o[j] * __ldg(&W3[(c + j) * 2]);
            p1 += o[j] * __ldg(&W3[(c + j) * 2 + 1]);
        }
#pragma unroll
        for (int off = 16; off; off >>= 1) {
            p0 += __shfl_xor_sync(0xFFFFFFFFu, p0, off);
            p1 += __shfl_xor_sync(0xFFFFFFFFu, p1, off);
        }
        if (lane == 0) {
            h3[2 * i]     = p0;
            h3[2 * i + 1] = p1;
        }
    }
}

// -------------------- final gather (OUT=2) --------------------
__global__ void k_gather_out(const float* __restrict__ h3,
                             const int* __restrict__ rowptr, const int* __restrict__ src,
                             const float* __restrict__ wedge, const float* __restrict__ snorm,
                             const float* __restrict__ b3, float* __restrict__ out, int n) {
    int i = blockIdx.x * blockDim.x + threadIdx.x;
    if (i >= n) return;
    float s = snorm[i];
    float a0 = s * h3[2 * i]     + b3[0];
    float a1 = s * h3[2 * i + 1] + b3[1];
    int p = rowptr[i], end = rowptr[i + 1];
    for (; p + 1 < end; p += 2) {
        int   r0 = __ldg(&src[p]),   r1 = __ldg(&src[p + 1]);
        float w0 = __ldg(&wedge[p]), w1 = __ldg(&wedge[p + 1]);
        a0 += w0 * h3[2 * r0]     + w1 * h3[2 * r1];
        a1 += w0 * h3[2 * r0 + 1] + w1 * h3[2 * r1 + 1];
    }
    if (p < end) {
        int r = __ldg(&src[p]);
        float wv = __ldg(&wedge[p]);
        a0 += wv * h3[2 * r];
        a1 += wv * h3[2 * r + 1];
    }
    out[2 * i]     = a0;
    out[2 * i + 1] = a1;
}

// -------------------- launch --------------------
extern "C" void kernel_launch(void* const* d_in, const int* in_sizes, int n_in,
                              void* d_out, int out_size) {
    const float*        x   = (const float*)d_in[0];
    const unsigned int* eiw = (const unsigned int*)d_in[1];
    const float*        w   = (const float*)d_in[2];
    const float*        W1  = (const float*)d_in[3];
    const float*        b1  = (const float*)d_in[4];
    const float*        g1  = (const float*)d_in[5];
    const float*        be1 = (const float*)d_in[6];
    const float*        m1  = (const float*)d_in[7];
    const float*        v1  = (const float*)d_in[8];
    const float*        W2  = (const float*)d_in[9];
    const float*        b2  = (const float*)d_in[10];
    const float*        g2  = (const float*)d_in[11];
    const float*        be2 = (const float*)d_in[12];
    const float*        m2  = (const float*)d_in[13];
    const float*        v2  = (const float*)d_in[14];
    const float*        W3  = (const float*)d_in[15];
    const float*        b3  = (const float*)d_in[16];
    float* out = (float*)d_out;

    int *row, *col, *cnt, *incl, *blksum, *rowptr, *fill, *src;
    float *deg, *dinv, *snorm, *h3, *wedge;
    __half *h16, *hi, *Wh1, *Wh2;
    cudaGetSymbolAddress((void**)&row,    g_row);
    cudaGetSymbolAddress((void**)&col,    g_col);
    cudaGetSymbolAddress((void**)&cnt,    g_cnt);
    cudaGetSymbolAddress((void**)&incl,   g_incl);
    cudaGetSymbolAddress((void**)&blksum, g_blksum);
    cudaGetSymbolAddress((void**)&rowptr, g_rowptr);
    cudaGetSymbolAddress((void**)&fill,   g_fill);
    cudaGetSymbolAddress((void**)&src,    g_src);
    cudaGetSymbolAddress((void**)&wedge,  g_wedge);
    cudaGetSymbolAddress((void**)&deg,    g_deg);
    cudaGetSymbolAddress((void**)&dinv,   g_dinv);
    cudaGetSymbolAddress((void**)&snorm,  g_snorm);
    cudaGetSymbolAddress((void**)&h16,    g_h16);
    cudaGetSymbolAddress((void**)&h3,     g_h3);
    cudaGetSymbolAddress((void**)&hi,     g_hi);
    cudaGetSymbolAddress((void**)&Wh1,    g_Wh1);
    cudaGetSymbolAddress((void**)&Wh2,    g_Wh2);

    const int n = NN, E = EE;
    const int SMEM = 51200;    // Bs(40960) + Ah(10240)
    cudaFuncSetAttribute(mma_gemm<FIN, true>,
                         cudaFuncAttributeMaxDynamicSharedMemorySize, SMEM);
    cudaFuncSetAttribute(mma_gemm<HH, false>,
                         cudaFuncAttributeMaxDynamicSharedMemorySize, SMEM);

    dim3 t256(256);
    int nb_n  = (n + 255) / 256;
    int nb_e  = (E + 255) / 256;
    int nb_sc = (n + 511) / 512;       // 98
    int nb_g  = n / 8;                 // 6250
    int gemm_grid = (n + 63) / 64;     // 782

    // preprocessing
    k_pre<<<768 + nb_n, t256>>>(W1, Wh1, W2, Wh2, eiw, deg, cnt, fill, n);
    k_extract_deg<<<nb_e, t256>>>(eiw, w, row, col, deg, cnt, E);
    k_scan1<<<nb_sc, 512>>>(cnt, incl, blksum, n);
    k_scan23<<<nb_n, t256>>>(incl, cnt, blksum, rowptr, deg, dinv, snorm, n, E, nb_sc);
    k_norm_fill<<<nb_e, t256>>>(row, col, w, dinv, rowptr, fill, src, wedge, E);

    // ---- layer 1 (A = x fp32, rounded to fp16 in-kernel) ----
    mma_gemm<FIN, true><<<gemm_grid, t256, SMEM>>>(x, nullptr, Wh1, h16, n);
    k_gather_bn<false><<<nb_g, t256>>>(h16, rowptr, src, wedge, snorm,
                                       b1, g1, be1, m1, v1, hi, nullptr, nullptr, n);

    // ---- layer 2 (A fp16, +W3 fused) ----
    mma_gemm<HH, false><<<gemm_grid, t256, SMEM>>>(nullptr, hi, Wh2, h16, n);
    k_gather_bn<true><<<nb_g, t256>>>(h16, rowptr, src, wedge, snorm,
                                      b2, g2, be2, m2, v2, nullptr, W3, h3, n);

    // ---- layer 3 ----
    k_gather_out<<<nb_n, t256>>>(h3, rowptr, src, wedge, snorm, b3, out, n);
}

// round 13
// speedup vs baseline: 5.7143x; 1.0572x over previous
#include <cuda_runtime.h>
#include <cuda_fp16.h>
#include <stdint.h>

#define NN   50000
#define EE   800000
#define FIN  512
#define HH   256
#define OUTF 2
#define BN_EPS 1e-5f

// -------------------- scratch --------------------
__device__ int    g_is64;
__device__ int    g_row[EE];
__device__ int    g_col[EE];
__device__ float  g_deg[NN];
__device__ float  g_dinv[NN];
__device__ float  g_snorm[NN];
__device__ __half g_h16[(size_t)NN * HH];
__device__ float  g_h3[(size_t)NN * OUTF];
__device__ __half g_hi[(size_t)NN * HH];
__device__ __half g_Wh1[(size_t)HH * FIN];
__device__ __half g_Wh2[(size_t)HH * HH];
// CSR (by destination col)
__device__ int    g_cnt[NN];
__device__ int    g_incl[NN];
__device__ int    g_blksum[128];
__device__ int    g_rowptr[NN + 1];
__device__ int    g_fill[NN];
__device__ int    g_src[EE];
__device__ float  g_wedge[EE];

// -------------------- branch A: weight transpose/round --------------------
__global__ void k_preW(const float* __restrict__ W1, __half* __restrict__ Wh1,
                       const float* __restrict__ W2, __half* __restrict__ Wh2) {
    int b = blockIdx.x, tid = threadIdx.x;
    if (b < 512) {
        int u = b * 256 + tid;
        int nn = u >> 9, k = u & 511;
        Wh1[u] = __float2half_rn(W1[(size_t)k * 256 + nn]);
    } else {
        int u = (b - 512) * 256 + tid;
        int nn = u >> 8, k = u & 255;
        Wh2[u] = __float2half_rn(W2[(size_t)k * 256 + nn]);
    }
}

// -------------------- branch B: graph preprocessing --------------------
__global__ void k_preG(const unsigned int* __restrict__ wr,
                       float* __restrict__ deg, int* __restrict__ cnt,
                       int* __restrict__ fill, int n) {
    int i = blockIdx.x * blockDim.x + threadIdx.x;
    if (i < n) { deg[i] = 1.0f; cnt[i] = 0; fill[i] = 0; }
    if (blockIdx.x == 0) {
        int ok = 1;
        for (int j = threadIdx.x; j < 2048; j += 256)
            if (wr[2 * j + 1] != 0u) ok = 0;
        int all = __syncthreads_and(ok);
        if (threadIdx.x == 0) g_is64 = all;
    }
}

__global__ void k_extract_deg(const unsigned int* __restrict__ wr,
                              const float* __restrict__ w,
                              int* __restrict__ row, int* __restrict__ col,
                              float* __restrict__ deg, int* __restrict__ cnt, int E) {
    int e = blockIdx.x * blockDim.x + threadIdx.x;
    if (e >= E) return;
    int r, c;
    if (g_is64) { r = (int)wr[2 * e]; c = (int)wr[2 * (E + e)]; }
    else        { r = (int)wr[e];     c = (int)wr[E + e]; }
    row[e] = r;
    col[e] = c;
    atomicAdd(&deg[c], w[e]);
    atomicAdd(&cnt[c], 1);
}

__global__ void k_scan1(const int* __restrict__ cnt, int* __restrict__ incl,
                        int* __restrict__ blksum, int n) {
    __shared__ int sh[512];
    int t = threadIdx.x;
    int i = blockIdx.x * 512 + t;
    int v = (i < n) ? cnt[i] : 0;
    sh[t] = v;
    __syncthreads();
#pragma unroll
    for (int off = 1; off < 512; off <<= 1) {
        int x = (t >= off) ? sh[t - off] : 0;
        __syncthreads();
        sh[t] += x;
        __syncthreads();
    }
    if (i < n) incl[i] = sh[t];
    if (t == 511) blksum[blockIdx.x] = sh[511];
}

__global__ void k_scan23(const int* __restrict__ incl, const int* __restrict__ cnt,
                         const int* __restrict__ blksum, int* __restrict__ rowptr,
                         const float* __restrict__ deg, float* __restrict__ dinv,
                         float* __restrict__ snorm, int n, int E, int nb) {
    __shared__ int sh[128];
    int t = threadIdx.x;
    if (t < 128) sh[t] = (t < nb) ? blksum[t] : 0;
    __syncthreads();
#pragma unroll
    for (int off = 1; off < 128; off <<= 1) {
        int x = 0;
        if (t < 128 && t >= off) x = sh[t - off];
        __syncthreads();
        if (t < 128) sh[t] += x;
        __syncthreads();
    }
    int i = blockIdx.x * blockDim.x + t;
    if (i < n) {
        int blk = i / 512;
        int exoff = sh[blk] - blksum[blk];
        rowptr[i] = incl[i] - cnt[i] + exoff;
        float d = rsqrtf(deg[i]);
        dinv[i] = d;
        snorm[i] = d * d;
    }
    if (i == 0) rowptr[n] = E;
}

__global__ void k_norm_fill(const int* __restrict__ row, const int* __restrict__ col,
                            const float* __restrict__ w, const float* __restrict__ dinv,
                            const int* __restrict__ rowptr, int* __restrict__ fill,
                            int* __restrict__ src, float* __restrict__ wedge, int E) {
    int e = blockIdx.x * blockDim.x + threadIdx.x;
    if (e >= E) return;
    int r = row[e], c = col[e];
    float nv = dinv[r] * w[e] * dinv[c];
    int p = rowptr[c] + atomicAdd(&fill[c], 1);
    src[p] = r;
    wedge[p] = nv;
}

// -------------------- helpers --------------------
__device__ __forceinline__ uint32_t pack2h(__half a, __half b) {
    __half2 p = __halves2half2(a, b);
    return *reinterpret_cast<uint32_t*>(&p);
}
__device__ __forceinline__ void h8_to_f8(uint4 raw, float* f) {
    __half2* p = reinterpret_cast<__half2*>(&raw);
#pragma unroll
    for (int j = 0; j < 4; j++) {
        float2 t = __half22float2(p[j]);
        f[2 * j] = t.x;
        f[2 * j + 1] = t.y;
    }
}

__device__ __forceinline__ void mma16816(float* d, const uint32_t* a, const uint32_t* b) {
    asm volatile(
        "mma.sync.aligned.m16n8k16.row.col.f32.f16.f16.f32 "
        "{%0,%1,%2,%3}, {%4,%5,%6,%7}, {%8,%9}, {%0,%1,%2,%3};"
        : "+f"(d[0]), "+f"(d[1]), "+f"(d[2]), "+f"(d[3])
        : "r"(a[0]), "r"(a[1]), "r"(a[2]), "r"(a[3]), "r"(b[0]), "r"(b[1]));
}
__device__ __forceinline__ void ldmatrix_x4(uint32_t& r0, uint32_t& r1, uint32_t& r2,
                                            uint32_t& r3, uint32_t saddr) {
    asm volatile("ldmatrix.sync.aligned.m8n8.x4.shared.b16 {%0,%1,%2,%3}, [%4];"
                 : "=r"(r0), "=r"(r1), "=r"(r2), "=r"(r3) : "r"(saddr));
}
__device__ __forceinline__ void cp_async16(uint32_t saddr, const void* gaddr, int src_sz) {
    asm volatile("cp.async.cg.shared.global [%0], [%1], 16, %2;"
                 :: "r"(saddr), "l"(gaddr), "r"(src_sz));
}
__device__ __forceinline__ void cp_commit() { asm volatile("cp.async.commit_group;"); }
__device__ __forceinline__ void cp_wait1()  { asm volatile("cp.async.wait_group 1;"); }
__device__ __forceinline__ void cp_wait0()  { asm volatile("cp.async.wait_group 0;"); }

// -------------------- single-term fp16 HMMA GEMM, BM=64/BN=256, occ 2 --------------------
template <int K, bool AFP32>
__global__ __launch_bounds__(256, 2)
void mma_gemm(const float* __restrict__ Af, const __half* __restrict__ Ahalf,
              const __half* __restrict__ Bh,
              __half* __restrict__ C, int Nr) {
    constexpr int NCH = K / 32;
    extern __shared__ char smem[];
    uint32_t* Bs = reinterpret_cast<uint32_t*>(smem);
    uint32_t* Ah = reinterpret_cast<uint32_t*>(smem + 40960);

    const int tid  = threadIdx.x;
    const int lane = tid & 31;
    const int wid  = tid >> 5;
    const int warp_m = wid & 1;
    const int warp_n = wid >> 1;
    const int bm = blockIdx.x * 64;

    float acc[2][8][4];
#pragma unroll
    for (int mt = 0; mt < 2; mt++)
#pragma unroll
        for (int nt = 0; nt < 8; nt++)
#pragma unroll
            for (int q = 0; q < 4; q++) acc[mt][nt][q] = 0.0f;

    float4 fa[2];

    auto loadAf = [&](int q) {
        const int kt = q * 32;
        int r = tid >> 2, k8 = tid & 3;
        int gr = bm + r;
        if (gr < Nr) {
            const float4* p = reinterpret_cast<const float4*>(
                Af + (size_t)gr * K + kt + k8 * 8);
            fa[0] = p[0];
            fa[1] = p[1];
        } else {
            fa[0] = make_float4(0.f, 0.f, 0.f, 0.f);
            fa[1] = make_float4(0.f, 0.f, 0.f, 0.f);
        }
    };
    auto storeA = [&](int st) {
        int r = tid >> 2, k8 = tid & 3;
        uint32_t hw[4];
        hw[0] = pack2h(__float2half_rn(fa[0].x), __float2half_rn(fa[0].y));
        hw[1] = pack2h(__float2half_rn(fa[0].z), __float2half_rn(fa[0].w));
        hw[2] = pack2h(__float2half_rn(fa[1].x), __float2half_rn(fa[1].y));
        hw[3] = pack2h(__float2half_rn(fa[1].z), __float2half_rn(fa[1].w));
        int woff = st * 1280 + r * 20 + k8 * 4;
        *reinterpret_cast<uint4*>(&Ah[woff]) = make_uint4(hw[0], hw[1], hw[2], hw[3]);
    };
    auto asyncA16 = [&](int st, int q) {
        const int kt = q * 32;
        int r = tid >> 2, k8 = tid & 3;
        int gr = bm + r;
        int ok = (gr < Nr);
        size_t srcoff = (size_t)(ok ? gr : 0) * K + kt + k8 * 8;
        int woff = st * 1280 + r * 20 + k8 * 4;
        cp_async16((uint32_t)__cvta_generic_to_shared(&Ah[woff]), Ahalf + srcoff, ok ? 16 : 0);
    };
    auto asyncB = [&](int st, int q) {
        const int kt = q * 32;
#pragma unroll
        for (int i = 0; i < 4; i++) {
            int u = tid + i * 256;
            int r = u >> 2, k8 = u & 3;
            int woff = st * 5120 + r * 20 + k8 * 4;
            cp_async16((uint32_t)__cvta_generic_to_shared(&Bs[woff]),
                       Bh + (size_t)r * K + kt + k8 * 8, 16);
        }
    };

    const int aRow  = warp_m * 32 + (lane & 7) + ((lane >> 3) & 1) * 8;
    const int aWsel = (lane >> 4) * 4;
    const int bRow  = warp_n * 64 + (lane & 7) + (lane >> 4) * 8;
    const int bWsel = ((lane >> 3) & 1) * 4;

    auto compute = [&](int st) {
#pragma unroll
        for (int ks = 0; ks < 2; ks++) {
            const int kw = ks * 8;
            uint32_t a[2][4], b[8][2];
#pragma unroll
            for (int mt = 0; mt < 2; mt++) {
                uint32_t ad = (uint32_t)__cvta_generic_to_shared(
                    &Ah[st * 1280 + (aRow + mt * 16) * 20 + kw + aWsel]);
                ldmatrix_x4(a[mt][0], a[mt][1], a[mt][2], a[mt][3], ad);
            }
#pragma unroll
            for (int np = 0; np < 4; np++) {
                uint32_t bd = (uint32_t)__cvta_generic_to_shared(
                    &Bs[st * 5120 + (bRow + np * 16) * 20 + kw + bWsel]);
                ldmatrix_x4(b[2 * np][0], b[2 * np][1], b[2 * np + 1][0], b[2 * np + 1][1], bd);
            }
#pragma unroll
            for (int mt = 0; mt < 2; mt++)
#pragma unroll
                for (int nt = 0; nt < 8; nt++)
                    mma16816(acc[mt][nt], a[mt], b[nt]);
        }
    };

    if (AFP32) loadAf(0); else asyncA16(0, 0);
    asyncB(0, 0);
    cp_commit();
    if (AFP32) storeA(0);

    for (int q = 0; q < NCH; q++) {
        if (q + 1 < NCH) {
            if (AFP32) loadAf(q + 1); else asyncA16((q + 1) & 1, q + 1);
            asyncB((q + 1) & 1, q + 1);
            cp_commit();
            cp_wait1();
        } else {
            cp_wait0();
        }
        __syncthreads();
        compute(q & 1);
        if (AFP32 && q + 1 < NCH) storeA((q + 1) & 1);
        __syncthreads();
    }

    const int lr4 = lane >> 2, lk = lane & 3;
#pragma unroll
    for (int mt = 0; mt < 2; mt++) {
#pragma unroll
        for (int half = 0; half < 2; half++) {
            int r = bm + warp_m * 32 + mt * 16 + half * 8 + lr4;
            if (r >= Nr) continue;
#pragma unroll
            for (int nt = 0; nt < 8; nt++) {
                int c = warp_n * 64 + nt * 8 + lk * 2;
                *reinterpret_cast<__half2*>(C + (size_t)r * 256 + c) =
                    __floats2half2_rn(acc[mt][nt][half * 2], acc[mt][nt][half * 2 + 1]);
            }
        }
    }
}

// -------------------- fused gather + BN + ReLU (warp per node, unroll x4) --------------------
template <bool W3MODE>
__global__ __launch_bounds__(256)
void k_gather_bn(const __half* __restrict__ h,
                 const int* __restrict__ rowptr, const int* __restrict__ src,
                 const float* __restrict__ wedge, const float* __restrict__ snorm,
                 const float* __restrict__ bb, const float* __restrict__ gg,
                 const float* __restrict__ bee, const float* __restrict__ mm,
                 const float* __restrict__ vv,
                 __half* __restrict__ hnext,
                 const float* __restrict__ W3, float* __restrict__ h3, int n) {
    int i = blockIdx.x * 8 + (threadIdx.x >> 5);
    int lane = threadIdx.x & 31;
    int c = lane * 8;

    float acc[8], f[8];
    h8_to_f8(*reinterpret_cast<const uint4*>(h + (size_t)i * HH + c), f);
    float s = snorm[i];
#pragma unroll
    for (int j = 0; j < 8; j++) acc[j] = f[j] * s;

    int p   = rowptr[i];
    int end = rowptr[i + 1];
    for (; p + 3 < end; p += 4) {
        int   r0 = __ldg(&src[p]),     r1 = __ldg(&src[p + 1]);
        int   r2 = __ldg(&src[p + 2]), r3 = __ldg(&src[p + 3]);
        float w0 = __ldg(&wedge[p]),     w1 = __ldg(&wedge[p + 1]);
        float w2 = __ldg(&wedge[p + 2]), w3 = __ldg(&wedge[p + 3]);
        uint4 q0 = *reinterpret_cast<const uint4*>(h + (size_t)r0 * HH + c);
        uint4 q1 = *reinterpret_cast<const uint4*>(h + (size_t)r1 * HH + c);
        uint4 q2 = *reinterpret_cast<const uint4*>(h + (size_t)r2 * HH + c);
        uint4 q3 = *reinterpret_cast<const uint4*>(h + (size_t)r3 * HH + c);
        float f0[8], f1[8], f2[8], f3[8];
        h8_to_f8(q0, f0); h8_to_f8(q1, f1); h8_to_f8(q2, f2); h8_to_f8(q3, f3);
#pragma unroll
        for (int j = 0; j < 8; j++)
            acc[j] += w0 * f0[j] + w1 * f1[j] + w2 * f2[j] + w3 * f3[j];
    }
    for (; p < end; p++) {
        int r = __ldg(&src[p]);
        float wv = __ldg(&wedge[p]);
        float f0[8];
        h8_to_f8(*reinterpret_cast<const uint4*>(h + (size_t)r * HH + c), f0);
#pragma unroll
        for (int j = 0; j < 8; j++) acc[j] += wv * f0[j];
    }

    float o[8];
#pragma unroll
    for (int halfp = 0; halfp < 2; halfp++) {
        int cc = c + halfp * 4;
        float4 B  = *reinterpret_cast<const float4*>(bb + cc);
        float4 G  = *reinterpret_cast<const float4*>(gg + cc);
        float4 BE = *reinterpret_cast<const float4*>(bee + cc);
        float4 M  = *reinterpret_cast<const float4*>(mm + cc);
        float4 V  = *reinterpret_cast<const float4*>(vv + cc);
        float* op = o + halfp * 4;
        float* ap = acc + halfp * 4;
        op[0] = fmaxf((ap[0] + B.x - M.x) * rsqrtf(V.x + BN_EPS) * G.x + BE.x, 0.0f);
        op[1] = fmaxf((ap[1] + B.y - M.y) * rsqrtf(V.y + BN_EPS) * G.y + BE.y, 0.0f);
        op[2] = fmaxf((ap[2] + B.z - M.z) * rsqrtf(V.z + BN_EPS) * G.z + BE.z, 0.0f);
        op[3] = fmaxf((ap[3] + B.w - M.w) * rsqrtf(V.w + BN_EPS) * G.w + BE.w, 0.0f);
    }

    if (!W3MODE) {
        uint32_t hw[4];
#pragma unroll
        for (int j = 0; j < 4; j++) {
            __half2 hp = __floats2half2_rn(o[2 * j], o[2 * j + 1]);
            hw[j] = *reinterpret_cast<uint32_t*>(&hp);
        }
        *reinterpret_cast<uint4*>(hnext + (size_t)i * HH + c) =
            make_uint4(hw[0], hw[1], hw[2], hw[3]);
    } else {
        float p0 = 0.f, p1 = 0.f;
#pragma unroll
        for (int j = 0; j < 8; j++) {
            p0 += o[j] * __ldg(&W3[(c + j) * 2]);
            p1 += o[j] * __ldg(&W3[(c + j) * 2 + 1]);
        }
#pragma unroll
        for (int off = 16; off; off >>= 1) {
            p0 += __shfl_xor_sync(0xFFFFFFFFu, p0, off);
            p1 += __shfl_xor_sync(0xFFFFFFFFu, p1, off);
        }
        if (lane == 0) {
            h3[2 * i]     = p0;
            h3[2 * i + 1] = p1;
        }
    }
}

// -------------------- final gather (OUT=2) --------------------
__global__ void k_gather_out(const float* __restrict__ h3,
                             const int* __restrict__ rowptr, const int* __restrict__ src,
                             const float* __restrict__ wedge, const float* __restrict__ snorm,
                             const float* __restrict__ b3, float* __restrict__ out, int n) {
    int i = blockIdx.x * blockDim.x + threadIdx.x;
    if (i >= n) return;
    float s = snorm[i];
    float a0 = s * h3[2 * i]     + b3[0];
    float a1 = s * h3[2 * i + 1] + b3[1];
    int p = rowptr[i], end = rowptr[i + 1];
    for (; p + 1 < end; p += 2) {
        int   r0 = __ldg(&src[p]),   r1 = __ldg(&src[p + 1]);
        float w0 = __ldg(&wedge[p]), w1 = __ldg(&wedge[p + 1]);
        a0 += w0 * h3[2 * r0]     + w1 * h3[2 * r1];
        a1 += w0 * h3[2 * r0 + 1] + w1 * h3[2 * r1 + 1];
    }
    if (p < end) {
        int r = __ldg(&src[p]);
        float wv = __ldg(&wedge[p]);
        a0 += wv * h3[2 * r];
        a1 += wv * h3[2 * r + 1];
    }
    out[2 * i]     = a0;
    out[2 * i + 1] = a1;
}

// -------------------- launch --------------------
extern "C" void kernel_launch(void* const* d_in, const int* in_sizes, int n_in,
                              void* d_out, int out_size) {
    const float*        x   = (const float*)d_in[0];
    const unsigned int* eiw = (const unsigned int*)d_in[1];
    const float*        w   = (const float*)d_in[2];
    const float*        W1  = (const float*)d_in[3];
    const float*        b1  = (const float*)d_in[4];
    const float*        g1  = (const float*)d_in[5];
    const float*        be1 = (const float*)d_in[6];
    const float*        m1  = (const float*)d_in[7];
    const float*        v1  = (const float*)d_in[8];
    const float*        W2  = (const float*)d_in[9];
    const float*        b2  = (const float*)d_in[10];
    const float*        g2  = (const float*)d_in[11];
    const float*        be2 = (const float*)d_in[12];
    const float*        m2  = (const float*)d_in[13];
    const float*        v2  = (const float*)d_in[14];
    const float*        W3  = (const float*)d_in[15];
    const float*        b3  = (const float*)d_in[16];
    float* out = (float*)d_out;

    int *row, *col, *cnt, *incl, *blksum, *rowptr, *fill, *src;
    float *deg, *dinv, *snorm, *h3, *wedge;
    __half *h16, *hi, *Wh1, *Wh2;
    cudaGetSymbolAddress((void**)&row,    g_row);
    cudaGetSymbolAddress((void**)&col,    g_col);
    cudaGetSymbolAddress((void**)&cnt,    g_cnt);
    cudaGetSymbolAddress((void**)&incl,   g_incl);
    cudaGetSymbolAddress((void**)&blksum, g_blksum);
    cudaGetSymbolAddress((void**)&rowptr, g_rowptr);
    cudaGetSymbolAddress((void**)&fill,   g_fill);
    cudaGetSymbolAddress((void**)&src,    g_src);
    cudaGetSymbolAddress((void**)&wedge,  g_wedge);
    cudaGetSymbolAddress((void**)&deg,    g_deg);
    cudaGetSymbolAddress((void**)&dinv,   g_dinv);
    cudaGetSymbolAddress((void**)&snorm,  g_snorm);
    cudaGetSymbolAddress((void**)&h16,    g_h16);
    cudaGetSymbolAddress((void**)&h3,     g_h3);
    cudaGetSymbolAddress((void**)&hi,     g_hi);
    cudaGetSymbolAddress((void**)&Wh1,    g_Wh1);
    cudaGetSymbolAddress((void**)&Wh2,    g_Wh2);

    // second stream + fork/join events, created once (outside any capture;
    // the captured call reuses them — record/wait are capture-legal)
    static cudaStream_t sB = nullptr;
    static cudaEvent_t  evF = nullptr, evJ = nullptr;
    if (sB == nullptr) {
        cudaStreamCreateWithFlags(&sB, cudaStreamNonBlocking);
        cudaEventCreateWithFlags(&evF, cudaEventDisableTiming);
        cudaEventCreateWithFlags(&evJ, cudaEventDisableTiming);
    }

    const int n = NN, E = EE;
    const int SMEM = 51200;
    cudaFuncSetAttribute(mma_gemm<FIN, true>,
                         cudaFuncAttributeMaxDynamicSharedMemorySize, SMEM);
    cudaFuncSetAttribute(mma_gemm<HH, false>,
                         cudaFuncAttributeMaxDynamicSharedMemorySize, SMEM);

    dim3 t256(256);
    int nb_n  = (n + 255) / 256;
    int nb_e  = (E + 255) / 256;
    int nb_sc = (n + 511) / 512;       // 98
    int nb_g  = n / 8;                 // 6250
    int gemm_grid = (n + 63) / 64;     // 782

    // ---- fork: branch B (graph preproc) on sB ----
    cudaEventRecord(evF, 0);
    cudaStreamWaitEvent(sB, evF, 0);
    k_preG<<<nb_n, t256, 0, sB>>>(eiw, deg, cnt, fill, n);
    k_extract_deg<<<nb_e, t256, 0, sB>>>(eiw, w, row, col, deg, cnt, E);
    k_scan1<<<nb_sc, 512, 0, sB>>>(cnt, incl, blksum, n);
    k_scan23<<<nb_n, t256, 0, sB>>>(incl, cnt, blksum, rowptr, deg, dinv, snorm, n, E, nb_sc);
    k_norm_fill<<<nb_e, t256, 0, sB>>>(row, col, w, dinv, rowptr, fill, src, wedge, E);
    cudaEventRecord(evJ, sB);

    // ---- branch A (weights + GEMM1) on default stream ----
    k_preW<<<768, t256>>>(W1, Wh1, W2, Wh2);
    mma_gemm<FIN, true><<<gemm_grid, t256, SMEM>>>(x, nullptr, Wh1, h16, n);

    // ---- join ----
    cudaStreamWaitEvent(0, evJ, 0);

    // ---- layer 1 gather ----
    k_gather_bn<false><<<nb_g, t256>>>(h16, rowptr, src, wedge, snorm,
                                       b1, g1, be1, m1, v1, hi, nullptr, nullptr, n);

    // ---- layer 2 (A fp16, +W3 fused) ----
    mma_gemm<HH, false><<<gemm_grid, t256, SMEM>>>(nullptr, hi, Wh2, h16, n);
    k_gather_bn<true><<<nb_g, t256>>>(h16, rowptr, src, wedge, snorm,
                                      b2, g2, be2, m2, v2, nullptr, W3, h3, n);

    // ---- layer 3 ----
    k_gather_out<<<nb_n, t256>>>(h3, rowptr, src, wedge, snorm, b3, out, n);
}